// round 3
// baseline (speedup 1.0000x reference)
#include <cuda_runtime.h>
#include <math.h>

// Problem constants (fixed by the dataset)
#define BB    4096
#define NINP  1024
#define C0    2000
#define C1    10000
#define NH    2002      // head columns: 2000 tokens + 2 cluster logits
#define N0T   8000      // tail cluster 0 tokens
#define N1T   22000     // tail cluster 1 tokens
#define H0D   256
#define H1D   64

// Tiling
#define TM 128
#define TN 128
#define KC 32
#define TMP (TM + 4)    // padded row for transposed A tile (keeps float4 alignment)

// Column-group counts for partial LSE (occupancy)
#define GH 8
#define G0 32
#define G1 16

// ---------------- device scratch (no allocations allowed) ----------------
__device__ int   g_n0, g_n1;
__device__ int   g_idx0[BB], g_idx1[BB];
__device__ int   g_cid[BB], g_gind[BB], g_t0[BB], g_t1[BB];
__device__ float g_H0[BB * H0D];
__device__ float g_H1[BB * H1D];
__device__ float g_zh[BB], g_z0[BB], g_z1[BB];
__device__ float g_pmH[BB * GH], g_psH[BB * GH];
__device__ float g_pm0[BB * G0], g_ps0[BB * G0];
__device__ float g_pm1[BB * G1], g_ps1[BB * G1];
__device__ float g_blocksum[16];

// ---------------- small kernels ----------------
__global__ void init_kernel() { g_n0 = 0; g_n1 = 0; }

__global__ void prep_kernel(const int* __restrict__ target) {
    int i = blockIdx.x * blockDim.x + threadIdx.x;
    if (i >= BB) return;
    int t = target[i];
    int cid = (t >= C0) + (t >= C1);
    g_cid[i]  = cid;
    g_gind[i] = (cid == 0) ? t : (C0 + cid - 1);
    int a = t - C0; a = a < 0 ? 0 : a; a = a > N0T - 1 ? N0T - 1 : a; g_t0[i] = a;
    int b = t - C1; b = b < 0 ? 0 : b; b = b > N1T - 1 ? N1T - 1 : b; g_t1[i] = b;
    if (cid == 1)      g_idx0[atomicAdd(&g_n0, 1)] = i;
    else if (cid == 2) g_idx1[atomicAdd(&g_n1, 1)] = i;
}

// ---------------- dense GEMM for hidden projections (C = A @ W) ----------------
// A: [BB x K] row-major, W: [K x N] row-major (N multiple of 64), C: [BB x N]
__global__ __launch_bounds__(256, 2)
void gemm_kernel(const float* __restrict__ A, int K,
                 const float* __restrict__ W, int N,
                 int outSel) {
    float* C = (outSel == 0) ? g_H0 : g_H1;
    int rbase = blockIdx.x * TM;
    int j0 = blockIdx.y * 64;

    __shared__ __align__(16) float As[TM][KC + 1];
    __shared__ __align__(16) float Ws[KC][64];

    int tid = threadIdx.x;
    int tx = tid & 15, ty = tid >> 4;

    float acc[8][4];
#pragma unroll
    for (int r = 0; r < 8; r++)
#pragma unroll
        for (int c = 0; c < 4; c++) acc[r][c] = 0.f;

    for (int k0 = 0; k0 < K; k0 += KC) {
#pragma unroll
        for (int e = 0; e < 4; e++) {
            int f = e * 256 + tid;
            int row = f >> 3;
            int kq = (f & 7) << 2;
            float4 v = *reinterpret_cast<const float4*>(&A[(size_t)(rbase + row) * K + k0 + kq]);
            As[row][kq] = v.x; As[row][kq + 1] = v.y; As[row][kq + 2] = v.z; As[row][kq + 3] = v.w;
        }
#pragma unroll
        for (int e = 0; e < 2; e++) {
            int f = e * 256 + tid;
            int kk = f >> 4;
            int cq = (f & 15) << 2;
            float4 v = *reinterpret_cast<const float4*>(&W[(size_t)(k0 + kk) * N + j0 + cq]);
            Ws[kk][cq] = v.x; Ws[kk][cq + 1] = v.y; Ws[kk][cq + 2] = v.z; Ws[kk][cq + 3] = v.w;
        }
        __syncthreads();
#pragma unroll
        for (int kk = 0; kk < KC; kk++) {
            float4 b = *reinterpret_cast<float4*>(&Ws[kk][tx * 4]);
#pragma unroll
            for (int r = 0; r < 8; r++) {
                float a = As[ty * 8 + r][kk];
                acc[r][0] += a * b.x; acc[r][1] += a * b.y;
                acc[r][2] += a * b.z; acc[r][3] += a * b.w;
            }
        }
        __syncthreads();
    }
#pragma unroll
    for (int r = 0; r < 8; r++) {
        float4 v = make_float4(acc[r][0], acc[r][1], acc[r][2], acc[r][3]);
        *reinterpret_cast<float4*>(&C[(size_t)(rbase + ty * 8 + r) * N + j0 + tx * 4]) = v;
    }
}

// ---------------- gathered logit: out[i] = dot(A[i,:], W[:, colidx[i]]) ----------------
__global__ void gatherdot_kernel(const float* __restrict__ X,
                                 const float* __restrict__ W,
                                 int K, int N, int sel) {
    const float* A = (sel == 0) ? X : (sel == 1) ? g_H0 : g_H1;
    const int* colidx = (sel == 0) ? g_gind : (sel == 1) ? g_t0 : g_t1;
    float* out = (sel == 0) ? g_zh : (sel == 1) ? g_z0 : g_z1;

    int w = (blockIdx.x * blockDim.x + threadIdx.x) >> 5;
    int lane = threadIdx.x & 31;
    if (w >= BB) return;
    int c = colidx[w];
    float s = 0.f;
    for (int k = lane; k < K; k += 32)
        s += A[(size_t)w * K + k] * W[(size_t)k * N + c];
#pragma unroll
    for (int o = 16; o > 0; o >>= 1) s += __shfl_xor_sync(0xffffffffu, s, o);
    if (lane == 0) out[w] = s;
}

// ---------------- streaming LSE-GEMM ----------------
// Per-row partial (max, sumexp) over a group of column tiles of A@W; logits
// never hit memory. sel: 0=head (all rows), 1=tail0, 2=tail1 (compacted rows).
// A tile stored TRANSPOSED in smem (As[kk][row]) so the 8 A-operands per
// (thread, kk) are two float4 LDS instead of 8 scalar LDS.
__global__ __launch_bounds__(256, 2)
void lse_kernel(const float* __restrict__ X,
                const float* __restrict__ W,
                int K, int N, int sel, int tpg) {
    const float* A;
    const int* rowlist;
    int cnt, G;
    float *pM, *pS;
    if (sel == 0) { A = X;    rowlist = nullptr; cnt = BB;   G = GH; pM = g_pmH; pS = g_psH; }
    else if (sel == 1) { A = g_H0; rowlist = g_idx0; cnt = g_n0; G = G0; pM = g_pm0; pS = g_ps0; }
    else { A = g_H1; rowlist = g_idx1; cnt = g_n1; G = G1; pM = g_pm1; pS = g_ps1; }

    int rbase = blockIdx.x * TM;
    if (rbase >= cnt) return;
    int by = blockIdx.y;

    __shared__ __align__(16) float As[KC][TMP];   // transposed: [k][row]
    __shared__ __align__(16) float Ws[KC][TN];

    int tid = threadIdx.x;
    int tx = tid & 15, ty = tid >> 4;
    bool nvec = ((N & 3) == 0);

    float rm[8], rs[8];
#pragma unroll
    for (int r = 0; r < 8; r++) { rm[r] = -INFINITY; rs[r] = 0.f; }

    for (int t = 0; t < tpg; t++) {
        int j0 = (by * tpg + t) * TN;
        if (j0 >= N) break;

        float acc[8][8];
#pragma unroll
        for (int r = 0; r < 8; r++)
#pragma unroll
            for (int c = 0; c < 8; c++) acc[r][c] = 0.f;

        for (int k0 = 0; k0 < K; k0 += KC) {
            // A tile (rows via compacted list when sel != 0), stored transposed
#pragma unroll
            for (int e = 0; e < 4; e++) {
                int f = e * 256 + tid;
                int row = f >> 3;
                int kq = (f & 7) << 2;
                int grow = rbase + row;
                int lrow = (grow < cnt) ? grow : (cnt - 1);   // clamp: dup last valid row
                int arow = rowlist ? rowlist[lrow] : grow;
                float4 v = *reinterpret_cast<const float4*>(&A[(size_t)arow * K + k0 + kq]);
                As[kq + 0][row] = v.x; As[kq + 1][row] = v.y;
                As[kq + 2][row] = v.z; As[kq + 3][row] = v.w;
            }
            // W tile with N-edge masking (scalar path when N not float4-aligned, e.g. NH=2002)
#pragma unroll
            for (int e = 0; e < 4; e++) {
                int f = e * 256 + tid;
                int kk = f >> 5;
                int cq = (f & 31) << 2;
                int col = j0 + cq;
                float4 v;
                const float* wrow = &W[(size_t)(k0 + kk) * N];
                if (nvec && col < N) {
                    v = *reinterpret_cast<const float4*>(&wrow[col]);
                } else {
                    v.x = (col + 0 < N) ? wrow[col + 0] : 0.f;
                    v.y = (col + 1 < N) ? wrow[col + 1] : 0.f;
                    v.z = (col + 2 < N) ? wrow[col + 2] : 0.f;
                    v.w = (col + 3 < N) ? wrow[col + 3] : 0.f;
                }
                Ws[kk][cq] = v.x; Ws[kk][cq + 1] = v.y; Ws[kk][cq + 2] = v.z; Ws[kk][cq + 3] = v.w;
            }
            __syncthreads();
#pragma unroll
            for (int kk = 0; kk < KC; kk++) {
                float4 b0 = *reinterpret_cast<float4*>(&Ws[kk][tx * 8]);
                float4 b1 = *reinterpret_cast<float4*>(&Ws[kk][tx * 8 + 4]);
                float4 a0 = *reinterpret_cast<float4*>(&As[kk][ty * 8]);
                float4 a1 = *reinterpret_cast<float4*>(&As[kk][ty * 8 + 4]);
                float bb[8] = {b0.x, b0.y, b0.z, b0.w, b1.x, b1.y, b1.z, b1.w};
                float aa[8] = {a0.x, a0.y, a0.z, a0.w, a1.x, a1.y, a1.z, a1.w};
#pragma unroll
                for (int r = 0; r < 8; r++)
#pragma unroll
                    for (int c = 0; c < 8; c++) acc[r][c] += aa[r] * bb[c];
            }
            __syncthreads();
        }

        // online LSE update for this 128x128 tile
        int cb = j0 + tx * 8;
#pragma unroll
        for (int r = 0; r < 8; r++) {
            float m = -INFINITY;
#pragma unroll
            for (int c = 0; c < 8; c++)
                if (cb + c < N) m = fmaxf(m, acc[r][c]);
#pragma unroll
            for (int o = 8; o > 0; o >>= 1) m = fmaxf(m, __shfl_xor_sync(0xffffffffu, m, o, 16));
            float s = 0.f;
            if (m != -INFINITY) {
#pragma unroll
                for (int c = 0; c < 8; c++)
                    if (cb + c < N) s += __expf(acc[r][c] - m);
            }
#pragma unroll
            for (int o = 8; o > 0; o >>= 1) s += __shfl_xor_sync(0xffffffffu, s, o, 16);
            if (m != -INFINITY) {
                if (m > rm[r]) { rs[r] = rs[r] * __expf(rm[r] - m) + s; rm[r] = m; }
                else           { rs[r] += s * __expf(m - rm[r]); }
            }
        }
    }

    if (tx == 0) {
#pragma unroll
        for (int r = 0; r < 8; r++) {
            int grow = rbase + ty * 8 + r;
            if (grow < cnt) {
                int orow = rowlist ? rowlist[grow] : grow;
                pM[(size_t)orow * G + by] = rm[r];
                pS[(size_t)orow * G + by] = rs[r];
            }
        }
    }
}

// ---------------- combine + deterministic loss reduction ----------------
__device__ __forceinline__ void merge_lse(float& m, float& s, float pm, float ps) {
    if (pm != -INFINITY) {
        if (pm > m) { s = s * __expf(m - pm) + ps; m = pm; }
        else        { s += ps * __expf(pm - m); }
    }
}

__global__ void combine_kernel(float* __restrict__ out) {
    __shared__ float red[256];
    int i = blockIdx.x * 256 + threadIdx.x;

    float m = -INFINITY, s = 0.f;
#pragma unroll
    for (int g = 0; g < GH; g++) merge_lse(m, s, g_pmH[(size_t)i * GH + g], g_psH[(size_t)i * GH + g]);
    float o = g_zh[i] - (m + logf(s));

    int cid = g_cid[i];
    if (cid == 1) {
        float m2 = -INFINITY, s2 = 0.f;
#pragma unroll
        for (int g = 0; g < G0; g++) merge_lse(m2, s2, g_pm0[(size_t)i * G0 + g], g_ps0[(size_t)i * G0 + g]);
        o += g_z0[i] - (m2 + logf(s2));
    } else if (cid == 2) {
        float m2 = -INFINITY, s2 = 0.f;
#pragma unroll
        for (int g = 0; g < G1; g++) merge_lse(m2, s2, g_pm1[(size_t)i * G1 + g], g_ps1[(size_t)i * G1 + g]);
        o += g_z1[i] - (m2 + logf(s2));
    }
    out[i] = o;

    red[threadIdx.x] = o;
    __syncthreads();
    for (int st = 128; st > 0; st >>= 1) {
        if (threadIdx.x < st) red[threadIdx.x] += red[threadIdx.x + st];
        __syncthreads();
    }
    if (threadIdx.x == 0) g_blocksum[blockIdx.x] = red[0];
}

__global__ void finalize_kernel(float* __restrict__ out, int out_size) {
    float s = 0.f;
    for (int i = 0; i < 16; i++) s += g_blocksum[i];
    if (out_size > BB) out[BB] = -s / (float)BB;
}

// ---------------- launch ----------------
extern "C" void kernel_launch(void* const* d_in, const int* in_sizes, int n_in,
                              void* d_out, int out_size) {
    const float* X    = (const float*)d_in[0];
    const int*   tgt  = (const int*)d_in[1];
    const float* Wh   = (const float*)d_in[2];
    const float* W1_0 = (const float*)d_in[3];
    const float* W2_0 = (const float*)d_in[4];
    const float* W1_1 = (const float*)d_in[5];
    const float* W2_1 = (const float*)d_in[6];
    float* out = (float*)d_out;

    init_kernel<<<1, 1>>>();
    prep_kernel<<<BB / 256, 256>>>(tgt);

    // hidden projections H0 = X@W1_0 [4096x256], H1 = X@W1_1 [4096x64]
    gemm_kernel<<<dim3(BB / TM, H0D / 64), 256>>>(X, NINP, W1_0, H0D, 0);
    gemm_kernel<<<dim3(BB / TM, H1D / 64), 256>>>(X, NINP, W1_1, H1D, 1);

    // gathered logits (per-row dot with one weight column)
    gatherdot_kernel<<<BB * 32 / 256, 256>>>(X, Wh,   NINP, NH,  0);
    gatherdot_kernel<<<BB * 32 / 256, 256>>>(X, W2_0, H0D,  N0T, 1);
    gatherdot_kernel<<<BB * 32 / 256, 256>>>(X, W2_1, H1D,  N1T, 2);

    // streaming logsumexp GEMMs
    lse_kernel<<<dim3(BB / TM, GH), 256>>>(X, Wh,   NINP, NH,  0, 2);   // 8*2*128  = 2048  >= 2002
    lse_kernel<<<dim3(BB / TM, G0), 256>>>(X, W2_0, H0D,  N0T, 1, 2);   // 32*2*128 = 8192  >= 8000
    lse_kernel<<<dim3(BB / TM, G1), 256>>>(X, W2_1, H1D,  N1T, 2, 11);  // 16*11*128= 22528 >= 22000

    combine_kernel<<<BB / 256, 256>>>(out);
    finalize_kernel<<<1, 1>>>(out, out_size);
}

// round 6
// speedup vs baseline: 1.8383x; 1.8383x over previous
#include <cuda_runtime.h>
#include <cuda_bf16.h>
#include <math.h>
#include <stdint.h>

// ---------------- problem constants ----------------
#define BB    4096
#define NINP  1024
#define C0    2000
#define C1    10000
#define NH    2002
#define N0T   8000
#define N1T   22000
#define H0D   256
#define H1D   64

// padded column counts (multiples of 128)
#define NHP   2048
#define N0P   8064
#define N1P   22016
#define GH    (NHP/128)    // 16
#define G0    (N0P/128)    // 63
#define G1    (N1P/128)    // 172

// smem tile: [128 rows][64 k] bf16, row stride 72 (pad) -> 18432 B per matrix
#define RS    72
#define TILE_B (128*RS*2)
#define OFF_AH 0
#define OFF_AL TILE_B
#define OFF_BH (2*TILE_B)
#define OFF_BL (3*TILE_B)
#define SMEM_DYN (4*TILE_B)   // 73728

// ---------------- device scratch ----------------
__device__ int   g_n0, g_n1;
__device__ int   g_idx0[BB], g_idx1[BB];
__device__ int   g_cid[BB], g_gind[BB], g_t0[BB], g_t1[BB];
__device__ __nv_bfloat16 g_Xhi[BB*NINP],  g_Xlo[BB*NINP];
__device__ __nv_bfloat16 g_Whh[NHP*NINP], g_Whl[NHP*NINP];
__device__ __nv_bfloat16 g_W10h[H0D*NINP], g_W10l[H0D*NINP];
__device__ __nv_bfloat16 g_W11h[128*NINP], g_W11l[128*NINP];
__device__ __nv_bfloat16 g_W20h[N0P*H0D], g_W20l[N0P*H0D];
__device__ __nv_bfloat16 g_W21h[N1P*H1D], g_W21l[N1P*H1D];
__device__ float g_H0[BB*H0D]; __device__ __nv_bfloat16 g_H0h[BB*H0D], g_H0l[BB*H0D];
__device__ float g_H1[BB*H1D]; __device__ __nv_bfloat16 g_H1h[BB*H1D], g_H1l[BB*H1D];
__device__ float g_zh[BB], g_z0[BB], g_z1[BB];
__device__ float g_pmH[BB*GH], g_psH[BB*GH];
__device__ float g_pm0[(size_t)BB*G0], g_ps0[(size_t)BB*G0];
__device__ float g_pm1[(size_t)BB*G1], g_ps1[(size_t)BB*G1];
__device__ float g_blocksum[16];

// ---------------- helpers ----------------
__device__ __forceinline__ uint32_t smem_u32(const void* p) {
    uint32_t a;
    asm("{ .reg .u64 t; cvta.to.shared.u64 t, %1; cvt.u32.u64 %0, t; }" : "=r"(a) : "l"(p));
    return a;
}
__device__ __forceinline__ void ldmx4(uint32_t* r, uint32_t addr) {
    asm volatile("ldmatrix.sync.aligned.m8n8.x4.shared.b16 {%0,%1,%2,%3}, [%4];"
        : "=r"(r[0]), "=r"(r[1]), "=r"(r[2]), "=r"(r[3]) : "r"(addr));
}
__device__ __forceinline__ void ldmx2(uint32_t* r, uint32_t addr) {
    asm volatile("ldmatrix.sync.aligned.m8n8.x2.shared.b16 {%0,%1}, [%2];"
        : "=r"(r[0]), "=r"(r[1]) : "r"(addr));
}
__device__ __forceinline__ void mma16816(float* c, const uint32_t* a, const uint32_t* b) {
    asm volatile("mma.sync.aligned.m16n8k16.row.col.f32.bf16.bf16.f32 "
        "{%0,%1,%2,%3}, {%4,%5,%6,%7}, {%8,%9}, {%0,%1,%2,%3};"
        : "+f"(c[0]), "+f"(c[1]), "+f"(c[2]), "+f"(c[3])
        : "r"(a[0]), "r"(a[1]), "r"(a[2]), "r"(a[3]), "r"(b[0]), "r"(b[1]));
}

// ---------------- small kernels ----------------
__global__ void init_kernel() { g_n0 = 0; g_n1 = 0; }

__global__ void prep_kernel(const int* __restrict__ target) {
    int i = blockIdx.x * blockDim.x + threadIdx.x;
    if (i >= BB) return;
    int t = target[i];
    int cid = (t >= C0) + (t >= C1);
    g_cid[i]  = cid;
    g_gind[i] = (cid == 0) ? t : (C0 + cid - 1);
    int a = t - C0; a = a < 0 ? 0 : a; a = a > N0T-1 ? N0T-1 : a; g_t0[i] = a;
    int b = t - C1; b = b < 0 ? 0 : b; b = b > N1T-1 ? N1T-1 : b; g_t1[i] = b;
    if (cid == 1)      g_idx0[atomicAdd(&g_n0, 1)] = i;
    else if (cid == 2) g_idx1[atomicAdd(&g_n1, 1)] = i;
}

__global__ void splitx_kernel(const float* __restrict__ X) {
    int i = blockIdx.x * 256 + threadIdx.x;
    float v = X[i];
    __nv_bfloat16 h = __float2bfloat16(v);
    g_Xhi[i] = h;
    g_Xlo[i] = __float2bfloat16(v - __bfloat162float(h));
}

// transpose + split: src [R][C] row-major -> dst [Cpad][R] bf16 hi/lo (zero-pad)
__global__ void tsplit_kernel(const float* __restrict__ src, int R, int C, int Cpad, int sel) {
    __nv_bfloat16 *dhi, *dlo;
    switch (sel) {
        case 0: dhi = g_Whh;  dlo = g_Whl;  break;
        case 1: dhi = g_W10h; dlo = g_W10l; break;
        case 2: dhi = g_W11h; dlo = g_W11l; break;
        case 3: dhi = g_W20h; dlo = g_W20l; break;
        default: dhi = g_W21h; dlo = g_W21l; break;
    }
    __shared__ float t[32][33];
    int cb = blockIdx.x * 32, rb = blockIdx.y * 32;
#pragma unroll
    for (int e = 0; e < 4; e++) {
        int rr = rb + threadIdx.y + e*8, cc = cb + threadIdx.x;
        t[threadIdx.y + e*8][threadIdx.x] = (rr < R && cc < C) ? src[(size_t)rr*C + cc] : 0.f;
    }
    __syncthreads();
#pragma unroll
    for (int e = 0; e < 4; e++) {
        int n = cb + threadIdx.y + e*8, k = rb + threadIdx.x;
        if (n < Cpad && k < R) {
            float v = t[threadIdx.x][threadIdx.y + e*8];
            __nv_bfloat16 h = __float2bfloat16(v);
            dhi[(size_t)n*R + k] = h;
            dlo[(size_t)n*R + k] = __float2bfloat16(v - __bfloat162float(h));
        }
    }
}

// ---------------- gathered logit (fp32, exact) ----------------
__global__ void gatherdot_kernel(const float* __restrict__ X,
                                 const float* __restrict__ W,
                                 int K, int N, int sel) {
    const float* A = (sel == 0) ? X : (sel == 1) ? g_H0 : g_H1;
    const int* colidx = (sel == 0) ? g_gind : (sel == 1) ? g_t0 : g_t1;
    float* out = (sel == 0) ? g_zh : (sel == 1) ? g_z0 : g_z1;
    int w = (blockIdx.x * blockDim.x + threadIdx.x) >> 5;
    int lane = threadIdx.x & 31;
    if (w >= BB) return;
    int c = colidx[w];
    float s = 0.f;
    for (int k = lane; k < K; k += 32)
        s += A[(size_t)w*K + k] * W[(size_t)k*N + c];
#pragma unroll
    for (int o = 16; o > 0; o >>= 1) s += __shfl_xor_sync(0xffffffffu, s, o);
    if (lane == 0) out[w] = s;
}

// ---------------- mma.sync split-bf16 GEMM / LSE kernel ----------------
// sel: 0=head LSE, 1=tail0 LSE, 2=tail1 LSE, 3=hidden0 GEMM, 4=hidden1 GEMM
// CTA tile 128x128; 8 warps = 2(m) x 4(n), each warp m64 x n32.
// D = Ahi@Bhi + Ahi@Blo + Alo@Bhi accumulated in fp32 registers.
__global__ __launch_bounds__(256, 2)
void mma_kernel(int sel) {
    const __nv_bfloat16 *Ahi, *Alo, *Bhi, *Blo;
    int K, Nvalid, G = 0;
    const int* rowlist = nullptr;
    int cnt = BB, mode;  // 1 = LSE, 0 = GEMM
    float *pM = nullptr, *pS = nullptr, *Hout = nullptr;
    __nv_bfloat16 *Hh = nullptr, *Hl = nullptr;
    int ldH = 0;
    switch (sel) {
        case 0: Ahi=g_Xhi;  Alo=g_Xlo;  K=NINP; Bhi=g_Whh;  Blo=g_Whl;  Nvalid=NH;  G=GH; pM=g_pmH; pS=g_psH; mode=1; break;
        case 1: Ahi=g_H0h;  Alo=g_H0l;  K=H0D;  Bhi=g_W20h; Blo=g_W20l; Nvalid=N0T; G=G0; pM=g_pm0; pS=g_ps0; rowlist=g_idx0; cnt=g_n0; mode=1; break;
        case 2: Ahi=g_H1h;  Alo=g_H1l;  K=H1D;  Bhi=g_W21h; Blo=g_W21l; Nvalid=N1T; G=G1; pM=g_pm1; pS=g_ps1; rowlist=g_idx1; cnt=g_n1; mode=1; break;
        case 3: Ahi=g_Xhi;  Alo=g_Xlo;  K=NINP; Bhi=g_W10h; Blo=g_W10l; Nvalid=H0D; Hout=g_H0; Hh=g_H0h; Hl=g_H0l; ldH=H0D; mode=0; break;
        default:Ahi=g_Xhi;  Alo=g_Xlo;  K=NINP; Bhi=g_W11h; Blo=g_W11l; Nvalid=H1D; Hout=g_H1; Hh=g_H1h; Hl=g_H1l; ldH=H1D; mode=0; break;
    }

    int rbase = blockIdx.x * 128;
    if (rbase >= cnt) return;
    int by = blockIdx.y;

    extern __shared__ __align__(16) char sm[];
    uint32_t sbase = smem_u32(sm);

    int tid = threadIdx.x, wid = tid >> 5, lane = tid & 31;
    int wm = wid >> 2, wn = wid & 3;   // warp covers rows [wm*64, +64), cols [wn*32, +32)

    float acc[4][4][4];
#pragma unroll
    for (int mt = 0; mt < 4; mt++)
#pragma unroll
        for (int nt = 0; nt < 4; nt++)
#pragma unroll
            for (int c = 0; c < 4; c++) acc[mt][nt][c] = 0.f;

    // ldmatrix lane base addresses (bytes)
    uint32_t aoff = (uint32_t)(((wm*64 + (lane & 15)) * RS + (lane >> 4) * 8) * 2);
    uint32_t boff = (uint32_t)(((wn*32 + (lane & 7)) * RS + ((lane >> 3) & 1) * 8) * 2);
    uint32_t aAH = sbase + OFF_AH + aoff, aAL = sbase + OFF_AL + aoff;
    uint32_t aBH = sbase + OFF_BH + boff, aBL = sbase + OFF_BL + boff;

    int nchunks = K >> 6;
    for (int ch = 0; ch < nchunks; ch++) {
        int k0 = ch << 6;
        // fill smem: A 128x64 hi/lo, B 128x64 hi/lo; 4 x 16B per thread per matrix
#pragma unroll
        for (int e = 0; e < 4; e++) {
            int f = e*256 + tid, row = f >> 3, u = f & 7;
            int grow = rbase + row; if (grow >= cnt) grow = cnt - 1;
            int arow = rowlist ? rowlist[grow] : grow;
            size_t go = (size_t)arow * K + k0 + u*8;
            uint32_t so = (uint32_t)((row*RS + u*8) * 2);
            *(uint4*)(sm + OFF_AH + so) = *(const uint4*)(Ahi + go);
            *(uint4*)(sm + OFF_AL + so) = *(const uint4*)(Alo + go);
            size_t gb = (size_t)(by*128 + row) * K + k0 + u*8;
            *(uint4*)(sm + OFF_BH + so) = *(const uint4*)(Bhi + gb);
            *(uint4*)(sm + OFF_BL + so) = *(const uint4*)(Blo + gb);
        }
        __syncthreads();
#pragma unroll
        for (int ks = 0; ks < 4; ks++) {
            uint32_t ah[4][4], al[4][4];
#pragma unroll
            for (int mt = 0; mt < 4; mt++) {
                uint32_t d = (uint32_t)(mt*16*RS*2 + ks*32);
                ldmx4(ah[mt], aAH + d);
                ldmx4(al[mt], aAL + d);
            }
#pragma unroll
            for (int nt = 0; nt < 4; nt++) {
                uint32_t d = (uint32_t)(nt*8*RS*2 + ks*32);
                uint32_t bh[2], bl[2];
                ldmx2(bh, aBH + d);
                ldmx2(bl, aBL + d);
#pragma unroll
                for (int mt = 0; mt < 4; mt++) {
                    mma16816(acc[mt][nt], ah[mt], bh);
                    mma16816(acc[mt][nt], ah[mt], bl);
                    mma16816(acc[mt][nt], al[mt], bh);
                }
            }
        }
        __syncthreads();
    }

    int q = lane >> 2, r4 = lane & 3;
    if (mode == 1) {
        // per-row LSE over this CTA's 128 cols: quad-reduce -> smem partials -> merge
        float* spm = (float*)sm;            // [128][4]
        float* sps = (float*)(sm + 2048);   // [128][4]
#pragma unroll
        for (int mt = 0; mt < 4; mt++) {
#pragma unroll
            for (int h = 0; h < 2; h++) {
                float m = -INFINITY;
#pragma unroll
                for (int nt = 0; nt < 4; nt++)
#pragma unroll
                    for (int c = 0; c < 2; c++) {
                        int col = by*128 + wn*32 + nt*8 + r4*2 + c;
                        if (col < Nvalid) m = fmaxf(m, acc[mt][nt][h*2 + c]);
                    }
                m = fmaxf(m, __shfl_xor_sync(0xffffffffu, m, 1));
                m = fmaxf(m, __shfl_xor_sync(0xffffffffu, m, 2));
                float s = 0.f;
                if (m != -INFINITY) {
#pragma unroll
                    for (int nt = 0; nt < 4; nt++)
#pragma unroll
                        for (int c = 0; c < 2; c++) {
                            int col = by*128 + wn*32 + nt*8 + r4*2 + c;
                            if (col < Nvalid) s += __expf(acc[mt][nt][h*2 + c] - m);
                        }
                }
                s += __shfl_xor_sync(0xffffffffu, s, 1);
                s += __shfl_xor_sync(0xffffffffu, s, 2);
                if (r4 == 0) {
                    int row = wm*64 + mt*16 + q + h*8;
                    spm[row*4 + wn] = m;
                    sps[row*4 + wn] = s;
                }
            }
        }
        __syncthreads();
        if (tid < 128) {
            float m = -INFINITY, s = 0.f;
#pragma unroll
            for (int w = 0; w < 4; w++) {
                float pm = spm[tid*4 + w], ps = sps[tid*4 + w];
                if (pm != -INFINITY) {
                    if (pm > m) { s = s * __expf(m - pm) + ps; m = pm; }
                    else        { s += ps * __expf(pm - m); }
                }
            }
            int grow = rbase + tid;
            if (grow < cnt) {
                int orow = rowlist ? rowlist[grow] : grow;
                pM[(size_t)orow*G + by] = m;
                pS[(size_t)orow*G + by] = s;
            }
        }
    } else {
        // GEMM mode: write fp32 H + bf16 hi/lo split
#pragma unroll
        for (int mt = 0; mt < 4; mt++)
#pragma unroll
            for (int nt = 0; nt < 4; nt++)
#pragma unroll
                for (int c = 0; c < 4; c++) {
                    int row = rbase + wm*64 + mt*16 + q + (c >> 1)*8;
                    int col = by*128 + wn*32 + nt*8 + r4*2 + (c & 1);
                    if (col < Nvalid) {
                        float v = acc[mt][nt][c];
                        Hout[(size_t)row*ldH + col] = v;
                        __nv_bfloat16 hh = __float2bfloat16(v);
                        Hh[(size_t)row*ldH + col] = hh;
                        Hl[(size_t)row*ldH + col] = __float2bfloat16(v - __bfloat162float(hh));
                    }
                }
    }
}

// ---------------- combine + deterministic loss reduction ----------------
__device__ __forceinline__ void merge_lse(float& m, float& s, float pm, float ps) {
    if (pm != -INFINITY) {
        if (pm > m) { s = s * __expf(m - pm) + ps; m = pm; }
        else        { s += ps * __expf(pm - m); }
    }
}

__global__ void combine_kernel(float* __restrict__ out) {
    __shared__ float red[256];
    int i = blockIdx.x * 256 + threadIdx.x;

    float m = -INFINITY, s = 0.f;
    for (int g = 0; g < GH; g++) merge_lse(m, s, g_pmH[(size_t)i*GH + g], g_psH[(size_t)i*GH + g]);
    float o = g_zh[i] - (m + logf(s));

    int cid = g_cid[i];
    if (cid == 1) {
        float m2 = -INFINITY, s2 = 0.f;
        for (int g = 0; g < G0; g++) merge_lse(m2, s2, g_pm0[(size_t)i*G0 + g], g_ps0[(size_t)i*G0 + g]);
        o += g_z0[i] - (m2 + logf(s2));
    } else if (cid == 2) {
        float m2 = -INFINITY, s2 = 0.f;
        for (int g = 0; g < G1; g++) merge_lse(m2, s2, g_pm1[(size_t)i*G1 + g], g_ps1[(size_t)i*G1 + g]);
        o += g_z1[i] - (m2 + logf(s2));
    }
    out[i] = o;

    red[threadIdx.x] = o;
    __syncthreads();
    for (int st = 128; st > 0; st >>= 1) {
        if (threadIdx.x < st) red[threadIdx.x] += red[threadIdx.x + st];
        __syncthreads();
    }
    if (threadIdx.x == 0) g_blocksum[blockIdx.x] = red[0];
}

__global__ void finalize_kernel(float* __restrict__ out, int out_size) {
    float s = 0.f;
    for (int i = 0; i < 16; i++) s += g_blocksum[i];
    if (out_size > BB) out[BB] = -s / (float)BB;
}

// ---------------- launch ----------------
extern "C" void kernel_launch(void* const* d_in, const int* in_sizes, int n_in,
                              void* d_out, int out_size) {
    const float* X    = (const float*)d_in[0];
    const int*   tgt  = (const int*)d_in[1];
    const float* Wh   = (const float*)d_in[2];
    const float* W1_0 = (const float*)d_in[3];
    const float* W2_0 = (const float*)d_in[4];
    const float* W1_1 = (const float*)d_in[5];
    const float* W2_1 = (const float*)d_in[6];
    float* out = (float*)d_out;

    cudaFuncSetAttribute(mma_kernel, cudaFuncAttributeMaxDynamicSharedMemorySize, SMEM_DYN);

    init_kernel<<<1, 1>>>();
    prep_kernel<<<BB/256, 256>>>(tgt);
    splitx_kernel<<<BB*NINP/256, 256>>>(X);

    tsplit_kernel<<<dim3(NHP/32, NINP/32), dim3(32,8)>>>(Wh,   NINP, NH,  NHP, 0);
    tsplit_kernel<<<dim3(H0D/32, NINP/32), dim3(32,8)>>>(W1_0, NINP, H0D, H0D, 1);
    tsplit_kernel<<<dim3(128/32, NINP/32), dim3(32,8)>>>(W1_1, NINP, H1D, 128, 2);
    tsplit_kernel<<<dim3(N0P/32, H0D/32),  dim3(32,8)>>>(W2_0, H0D,  N0T, N0P, 3);
    tsplit_kernel<<<dim3(N1P/32, H1D/32),  dim3(32,8)>>>(W2_1, H1D,  N1T, N1P, 4);

    // hidden projections (tensor cores; also emits bf16 splits of H)
    mma_kernel<<<dim3(BB/128, H0D/128), 256, SMEM_DYN>>>(3);
    mma_kernel<<<dim3(BB/128, 1),       256, SMEM_DYN>>>(4);

    // gathered logits (fp32 exact)
    gatherdot_kernel<<<BB*32/256, 256>>>(X, Wh,   NINP, NH,  0);
    gatherdot_kernel<<<BB*32/256, 256>>>(X, W2_0, H0D,  N0T, 1);
    gatherdot_kernel<<<BB*32/256, 256>>>(X, W2_1, H1D,  N1T, 2);

    // streaming logsumexp (tensor cores)
    mma_kernel<<<dim3(BB/128, GH), 256, SMEM_DYN>>>(0);
    mma_kernel<<<dim3(BB/128, G0), 256, SMEM_DYN>>>(1);
    mma_kernel<<<dim3(BB/128, G1), 256, SMEM_DYN>>>(2);

    combine_kernel<<<BB/256, 256>>>(out);
    finalize_kernel<<<1, 1>>>(out, out_size);
}

// round 7
// speedup vs baseline: 2.2120x; 1.2033x over previous
#include <cuda_runtime.h>
#include <cuda_bf16.h>
#include <math.h>
#include <stdint.h>

// ---------------- problem constants ----------------
#define BB    4096
#define NINP  1024
#define C0    2000
#define C1    10000
#define NH    2002
#define N0T   8000
#define N1T   22000
#define H0D   256
#define H1D   64

// padded column counts (multiples of 128); padding confined to last 128-tile
#define NHP   2048
#define N0P   8064
#define N1P   22016
#define GH    (NHP/128)    // 16
#define G0    (N0P/128)    // 63
#define G1    (N1P/128)    // 172

#define LOG2E 1.4426950408889634f
#define LN2   0.6931471805599453f

// smem tile: [128 rows][64 k] bf16, row stride 72 (pad) -> 18432 B per matrix
#define RS    72
#define TILE_B (128*RS*2)
#define OFF_AH 0
#define OFF_AL TILE_B
#define OFF_BH (2*TILE_B)
#define OFF_BL (3*TILE_B)
#define SMEM_DYN (4*TILE_B)   // 73728

// ---------------- device scratch ----------------
__device__ int   g_n0, g_n1;
__device__ int   g_idx0[BB], g_idx1[BB];
__device__ int   g_cid[BB], g_gind[BB], g_t0[BB], g_t1[BB];
__device__ __nv_bfloat16 g_Xhi[BB*NINP],  g_Xlo[BB*NINP];
__device__ __nv_bfloat16 g_Whh[NHP*NINP], g_Whl[NHP*NINP];
__device__ __nv_bfloat16 g_W10h[H0D*NINP], g_W10l[H0D*NINP];
__device__ __nv_bfloat16 g_W11h[128*NINP], g_W11l[128*NINP];
__device__ __nv_bfloat16 g_W20h[N0P*H0D], g_W20l[N0P*H0D];
__device__ __nv_bfloat16 g_W21h[N1P*H1D], g_W21l[N1P*H1D];
__device__ float g_H0[BB*H0D]; __device__ __nv_bfloat16 g_H0h[BB*H0D], g_H0l[BB*H0D];
__device__ float g_H1[BB*H1D]; __device__ __nv_bfloat16 g_H1h[BB*H1D], g_H1l[BB*H1D];
__device__ float g_zh[BB], g_z0[BB], g_z1[BB];
__device__ float g_psH[BB*GH];
__device__ float g_ps0[(size_t)BB*G0];
__device__ float g_ps1[(size_t)BB*G1];
__device__ float g_blocksum[16];

// ---------------- helpers ----------------
__device__ __forceinline__ uint32_t smem_u32(const void* p) {
    uint32_t a;
    asm("{ .reg .u64 t; cvta.to.shared.u64 t, %1; cvt.u32.u64 %0, t; }" : "=r"(a) : "l"(p));
    return a;
}
__device__ __forceinline__ void ldmx4(uint32_t* r, uint32_t addr) {
    asm volatile("ldmatrix.sync.aligned.m8n8.x4.shared.b16 {%0,%1,%2,%3}, [%4];"
        : "=r"(r[0]), "=r"(r[1]), "=r"(r[2]), "=r"(r[3]) : "r"(addr));
}
__device__ __forceinline__ void ldmx2(uint32_t* r, uint32_t addr) {
    asm volatile("ldmatrix.sync.aligned.m8n8.x2.shared.b16 {%0,%1}, [%2];"
        : "=r"(r[0]), "=r"(r[1]) : "r"(addr));
}
__device__ __forceinline__ void mma16816(float* c, const uint32_t* a, const uint32_t* b) {
    asm volatile("mma.sync.aligned.m16n8k16.row.col.f32.bf16.bf16.f32 "
        "{%0,%1,%2,%3}, {%4,%5,%6,%7}, {%8,%9}, {%0,%1,%2,%3};"
        : "+f"(c[0]), "+f"(c[1]), "+f"(c[2]), "+f"(c[3])
        : "r"(a[0]), "r"(a[1]), "r"(a[2]), "r"(a[3]), "r"(b[0]), "r"(b[1]));
}
// pack 2 f32 -> f16x2, dual-exp2, return half2 of 2^a, 2^b
__device__ __forceinline__ uint32_t ex2_pair(float a, float b) {
    uint32_t p;
    asm("cvt.rn.f16x2.f32 %0, %1, %2;" : "=r"(p) : "f"(b), "f"(a));
    asm("ex2.approx.f16x2 %0, %0;" : "+r"(p));
    return p;
}
__device__ __forceinline__ uint32_t hadd2u(uint32_t a, uint32_t b) {
    uint32_t d;
    asm("add.f16x2 %0, %1, %2;" : "=r"(d) : "r"(a), "r"(b));
    return d;
}

// ---------------- small kernels ----------------
__global__ void init_kernel() { g_n0 = 0; g_n1 = 0; }

__global__ void prep_kernel(const int* __restrict__ target) {
    int i = blockIdx.x * blockDim.x + threadIdx.x;
    if (i >= BB) return;
    int t = target[i];
    int cid = (t >= C0) + (t >= C1);
    g_cid[i]  = cid;
    g_gind[i] = (cid == 0) ? t : (C0 + cid - 1);
    int a = t - C0; a = a < 0 ? 0 : a; a = a > N0T-1 ? N0T-1 : a; g_t0[i] = a;
    int b = t - C1; b = b < 0 ? 0 : b; b = b > N1T-1 ? N1T-1 : b; g_t1[i] = b;
    if (cid == 1)      g_idx0[atomicAdd(&g_n0, 1)] = i;
    else if (cid == 2) g_idx1[atomicAdd(&g_n1, 1)] = i;
}

__global__ void splitx_kernel(const float* __restrict__ X) {
    int i = blockIdx.x * 256 + threadIdx.x;
    float v = X[i];
    __nv_bfloat16 h = __float2bfloat16(v);
    g_Xhi[i] = h;
    g_Xlo[i] = __float2bfloat16(v - __bfloat162float(h));
}

// transpose + split + scale: src [R][C] row-major -> dst [Cpad][R] bf16 hi/lo
// scale = LOG2E for LSE weight matrices (folds base-2 conversion into the GEMM)
__global__ void tsplit_kernel(const float* __restrict__ src, int R, int C, int Cpad,
                              int sel, float scale) {
    __nv_bfloat16 *dhi, *dlo;
    switch (sel) {
        case 0: dhi = g_Whh;  dlo = g_Whl;  break;
        case 1: dhi = g_W10h; dlo = g_W10l; break;
        case 2: dhi = g_W11h; dlo = g_W11l; break;
        case 3: dhi = g_W20h; dlo = g_W20l; break;
        default: dhi = g_W21h; dlo = g_W21l; break;
    }
    __shared__ float t[32][33];
    int cb = blockIdx.x * 32, rb = blockIdx.y * 32;
#pragma unroll
    for (int e = 0; e < 4; e++) {
        int rr = rb + threadIdx.y + e*8, cc = cb + threadIdx.x;
        t[threadIdx.y + e*8][threadIdx.x] = (rr < R && cc < C) ? src[(size_t)rr*C + cc] : 0.f;
    }
    __syncthreads();
#pragma unroll
    for (int e = 0; e < 4; e++) {
        int n = cb + threadIdx.y + e*8, k = rb + threadIdx.x;
        if (n < Cpad && k < R) {
            float v = t[threadIdx.x][threadIdx.y + e*8] * scale;
            __nv_bfloat16 h = __float2bfloat16(v);
            dhi[(size_t)n*R + k] = h;
            dlo[(size_t)n*R + k] = __float2bfloat16(v - __bfloat162float(h));
        }
    }
}

// ---------------- gathered logit (fp32, exact) ----------------
__global__ void gatherdot_kernel(const float* __restrict__ X,
                                 const float* __restrict__ W,
                                 int K, int N, int sel) {
    const float* A = (sel == 0) ? X : (sel == 1) ? g_H0 : g_H1;
    const int* colidx = (sel == 0) ? g_gind : (sel == 1) ? g_t0 : g_t1;
    float* out = (sel == 0) ? g_zh : (sel == 1) ? g_z0 : g_z1;
    int w = (blockIdx.x * blockDim.x + threadIdx.x) >> 5;
    int lane = threadIdx.x & 31;
    if (w >= BB) return;
    int c = colidx[w];
    float s = 0.f;
    for (int k = lane; k < K; k += 32)
        s += A[(size_t)w*K + k] * W[(size_t)k*N + c];
#pragma unroll
    for (int o = 16; o > 0; o >>= 1) s += __shfl_xor_sync(0xffffffffu, s, o);
    if (lane == 0) out[w] = s;
}

// ---------------- mma.sync split-bf16 GEMM / sumexp2 kernel ----------------
// sel: 0=head, 1=tail0, 2=tail1 (sum of 2^t per row), 3=hidden0 GEMM, 4=hidden1 GEMM
// LSE matrices have log2(e) folded into B, so accumulators ARE base-2 logits.
__global__ __launch_bounds__(256, 2)
void mma_kernel(int sel) {
    const __nv_bfloat16 *Ahi, *Alo, *Bhi, *Blo;
    int K, Nvalid, G = 0;
    const int* rowlist = nullptr;
    int cnt = BB, mode;  // 1 = sumexp2, 0 = GEMM
    float *pS = nullptr, *Hout = nullptr;
    __nv_bfloat16 *Hh = nullptr, *Hl = nullptr;
    int ldH = 0;
    switch (sel) {
        case 0: Ahi=g_Xhi;  Alo=g_Xlo;  K=NINP; Bhi=g_Whh;  Blo=g_Whl;  Nvalid=NH;  G=GH; pS=g_psH; mode=1; break;
        case 1: Ahi=g_H0h;  Alo=g_H0l;  K=H0D;  Bhi=g_W20h; Blo=g_W20l; Nvalid=N0T; G=G0; pS=g_ps0; rowlist=g_idx0; cnt=g_n0; mode=1; break;
        case 2: Ahi=g_H1h;  Alo=g_H1l;  K=H1D;  Bhi=g_W21h; Blo=g_W21l; Nvalid=N1T; G=G1; pS=g_ps1; rowlist=g_idx1; cnt=g_n1; mode=1; break;
        case 3: Ahi=g_Xhi;  Alo=g_Xlo;  K=NINP; Bhi=g_W10h; Blo=g_W10l; Nvalid=H0D; Hout=g_H0; Hh=g_H0h; Hl=g_H0l; ldH=H0D; mode=0; break;
        default:Ahi=g_Xhi;  Alo=g_Xlo;  K=NINP; Bhi=g_W11h; Blo=g_W11l; Nvalid=H1D; Hout=g_H1; Hh=g_H1h; Hl=g_H1l; ldH=H1D; mode=0; break;
    }

    int rbase = blockIdx.x * 128;
    if (rbase >= cnt) return;
    int by = blockIdx.y;

    extern __shared__ __align__(16) char sm[];
    uint32_t sbase = smem_u32(sm);

    int tid = threadIdx.x, wid = tid >> 5, lane = tid & 31;
    int wm = wid >> 2, wn = wid & 3;

    float acc[4][4][4];
#pragma unroll
    for (int mt = 0; mt < 4; mt++)
#pragma unroll
        for (int nt = 0; nt < 4; nt++)
#pragma unroll
            for (int c = 0; c < 4; c++) acc[mt][nt][c] = 0.f;

    uint32_t aoff = (uint32_t)(((wm*64 + (lane & 15)) * RS + (lane >> 4) * 8) * 2);
    uint32_t boff = (uint32_t)(((wn*32 + (lane & 7)) * RS + ((lane >> 3) & 1) * 8) * 2);
    uint32_t aAH = sbase + OFF_AH + aoff, aAL = sbase + OFF_AL + aoff;
    uint32_t aBH = sbase + OFF_BH + boff, aBL = sbase + OFF_BL + boff;

    int nchunks = K >> 6;
    for (int ch = 0; ch < nchunks; ch++) {
        int k0 = ch << 6;
#pragma unroll
        for (int e = 0; e < 4; e++) {
            int f = e*256 + tid, row = f >> 3, u = f & 7;
            int grow = rbase + row; if (grow >= cnt) grow = cnt - 1;
            int arow = rowlist ? rowlist[grow] : grow;
            size_t go = (size_t)arow * K + k0 + u*8;
            uint32_t so = (uint32_t)((row*RS + u*8) * 2);
            *(uint4*)(sm + OFF_AH + so) = *(const uint4*)(Ahi + go);
            *(uint4*)(sm + OFF_AL + so) = *(const uint4*)(Alo + go);
            size_t gb = (size_t)(by*128 + row) * K + k0 + u*8;
            *(uint4*)(sm + OFF_BH + so) = *(const uint4*)(Bhi + gb);
            *(uint4*)(sm + OFF_BL + so) = *(const uint4*)(Blo + gb);
        }
        __syncthreads();
#pragma unroll
        for (int ks = 0; ks < 4; ks++) {
            uint32_t ah[4][4], al[4][4];
#pragma unroll
            for (int mt = 0; mt < 4; mt++) {
                uint32_t d = (uint32_t)(mt*16*RS*2 + ks*32);
                ldmx4(ah[mt], aAH + d);
                ldmx4(al[mt], aAL + d);
            }
#pragma unroll
            for (int nt = 0; nt < 4; nt++) {
                uint32_t d = (uint32_t)(nt*8*RS*2 + ks*32);
                uint32_t bh[2], bl[2];
                ldmx2(bh, aBH + d);
                ldmx2(bl, aBL + d);
#pragma unroll
                for (int mt = 0; mt < 4; mt++) {
                    mma16816(acc[mt][nt], ah[mt], bh);
                    mma16816(acc[mt][nt], ah[mt], bl);
                    mma16816(acc[mt][nt], al[mt], bh);
                }
            }
        }
        __syncthreads();
    }

    int q = lane >> 2, r4 = lane & 3;
    if (mode == 1) {
        // sum of 2^t over this CTA's 128 cols per row, via dual-half ex2.
        // Padding/edge handling only needed in the last column group.
        float* sps = (float*)sm;            // [128][4]
        bool edge = (by == G - 1);
#pragma unroll
        for (int mt = 0; mt < 4; mt++) {
#pragma unroll
            for (int h = 0; h < 2; h++) {
                float v[8];
#pragma unroll
                for (int nt = 0; nt < 4; nt++)
#pragma unroll
                    for (int c = 0; c < 2; c++) {
                        float t = acc[mt][nt][h*2 + c];
                        if (edge) {
                            int col = by*128 + wn*32 + nt*8 + r4*2 + c;
                            if (col >= Nvalid) t = -100.f;
                        }
                        v[nt*2 + c] = t;
                    }
                uint32_t e0 = ex2_pair(v[0], v[1]);
                uint32_t e1 = ex2_pair(v[2], v[3]);
                uint32_t e2 = ex2_pair(v[4], v[5]);
                uint32_t e3 = ex2_pair(v[6], v[7]);
                uint32_t t3 = hadd2u(hadd2u(e0, e1), hadd2u(e2, e3));
                __half2 hh = *(__half2*)&t3;
                float s8 = __low2float(hh) + __high2float(hh);
                s8 += __shfl_xor_sync(0xffffffffu, s8, 1);
                s8 += __shfl_xor_sync(0xffffffffu, s8, 2);
                if (r4 == 0) sps[(wm*64 + mt*16 + q + h*8)*4 + wn] = s8;
            }
        }
        __syncthreads();
        if (tid < 128) {
            float s = sps[tid*4 + 0] + sps[tid*4 + 1] + sps[tid*4 + 2] + sps[tid*4 + 3];
            int grow = rbase + tid;
            if (grow < cnt) {
                int orow = rowlist ? rowlist[grow] : grow;
                pS[(size_t)orow*G + by] = s;
            }
        }
    } else {
        // GEMM mode: write fp32 H + bf16 hi/lo split
#pragma unroll
        for (int mt = 0; mt < 4; mt++)
#pragma unroll
            for (int nt = 0; nt < 4; nt++)
#pragma unroll
                for (int c = 0; c < 4; c++) {
                    int row = rbase + wm*64 + mt*16 + q + (c >> 1)*8;
                    int col = by*128 + wn*32 + nt*8 + r4*2 + (c & 1);
                    if (col < Nvalid) {
                        float v = acc[mt][nt][c];
                        Hout[(size_t)row*ldH + col] = v;
                        __nv_bfloat16 hh = __float2bfloat16(v);
                        Hh[(size_t)row*ldH + col] = hh;
                        Hl[(size_t)row*ldH + col] = __float2bfloat16(v - __bfloat162float(hh));
                    }
                }
    }
}

// ---------------- combine + deterministic loss reduction ----------------
__global__ void combine_kernel(float* __restrict__ out) {
    __shared__ float red[256];
    int i = blockIdx.x * 256 + threadIdx.x;

    float s = 0.f;
    for (int g = 0; g < GH; g++) s += g_psH[(size_t)i*GH + g];
    float o = g_zh[i] - LN2 * log2f(s);

    int cid = g_cid[i];
    if (cid == 1) {
        float s2 = 0.f;
        for (int g = 0; g < G0; g++) s2 += g_ps0[(size_t)i*G0 + g];
        o += g_z0[i] - LN2 * log2f(s2);
    } else if (cid == 2) {
        float s2 = 0.f;
        for (int g = 0; g < G1; g++) s2 += g_ps1[(size_t)i*G1 + g];
        o += g_z1[i] - LN2 * log2f(s2);
    }
    out[i] = o;

    red[threadIdx.x] = o;
    __syncthreads();
    for (int st = 128; st > 0; st >>= 1) {
        if (threadIdx.x < st) red[threadIdx.x] += red[threadIdx.x + st];
        __syncthreads();
    }
    if (threadIdx.x == 0) g_blocksum[blockIdx.x] = red[0];
}

__global__ void finalize_kernel(float* __restrict__ out, int out_size) {
    float s = 0.f;
    for (int i = 0; i < 16; i++) s += g_blocksum[i];
    if (out_size > BB) out[BB] = -s / (float)BB;
}

// ---------------- launch ----------------
extern "C" void kernel_launch(void* const* d_in, const int* in_sizes, int n_in,
                              void* d_out, int out_size) {
    const float* X    = (const float*)d_in[0];
    const int*   tgt  = (const int*)d_in[1];
    const float* Wh   = (const float*)d_in[2];
    const float* W1_0 = (const float*)d_in[3];
    const float* W2_0 = (const float*)d_in[4];
    const float* W1_1 = (const float*)d_in[5];
    const float* W2_1 = (const float*)d_in[6];
    float* out = (float*)d_out;

    cudaFuncSetAttribute(mma_kernel, cudaFuncAttributeMaxDynamicSharedMemorySize, SMEM_DYN);

    init_kernel<<<1, 1>>>();
    prep_kernel<<<BB/256, 256>>>(tgt);
    splitx_kernel<<<BB*NINP/256, 256>>>(X);

    // LSE matrices carry the log2(e) factor; hidden projections do not.
    tsplit_kernel<<<dim3(NHP/32, NINP/32), dim3(32,8)>>>(Wh,   NINP, NH,  NHP, 0, LOG2E);
    tsplit_kernel<<<dim3(H0D/32, NINP/32), dim3(32,8)>>>(W1_0, NINP, H0D, H0D, 1, 1.0f);
    tsplit_kernel<<<dim3(128/32, NINP/32), dim3(32,8)>>>(W1_1, NINP, H1D, 128, 2, 1.0f);
    tsplit_kernel<<<dim3(N0P/32, H0D/32),  dim3(32,8)>>>(W2_0, H0D,  N0T, N0P, 3, LOG2E);
    tsplit_kernel<<<dim3(N1P/32, H1D/32),  dim3(32,8)>>>(W2_1, H1D,  N1T, N1P, 4, LOG2E);

    // hidden projections (tensor cores; also emits bf16 splits of H)
    mma_kernel<<<dim3(BB/128, H0D/128), 256, SMEM_DYN>>>(3);
    mma_kernel<<<dim3(BB/128, 1),       256, SMEM_DYN>>>(4);

    // gathered logits (fp32 exact)
    gatherdot_kernel<<<BB*32/256, 256>>>(X, Wh,   NINP, NH,  0);
    gatherdot_kernel<<<BB*32/256, 256>>>(X, W2_0, H0D,  N0T, 1);
    gatherdot_kernel<<<BB*32/256, 256>>>(X, W2_1, H1D,  N1T, 2);

    // streaming sum-of-exp2 (tensor cores + dual-half ex2)
    mma_kernel<<<dim3(BB/128, GH), 256, SMEM_DYN>>>(0);
    mma_kernel<<<dim3(BB/128, G0), 256, SMEM_DYN>>>(1);
    mma_kernel<<<dim3(BB/128, G1), 256, SMEM_DYN>>>(2);

    combine_kernel<<<BB/256, 256>>>(out);
    finalize_kernel<<<1, 1>>>(out, out_size);
}

// round 8
// speedup vs baseline: 2.6381x; 1.1926x over previous
#include <cuda_runtime.h>
#include <cuda_bf16.h>
#include <math.h>
#include <stdint.h>

// ---------------- problem constants ----------------
#define BB    4096
#define NINP  1024
#define C0    2000
#define C1    10000
#define NH    2002
#define N0T   8000
#define N1T   22000
#define H0D   256
#define H1D   64

// padded column counts (multiples of 128); padding confined to last 128-tile
#define NHP   2048
#define N0P   8064
#define N1P   22016
#define GH    (NHP/128)    // 16
#define G0    (N0P/128)    // 63
#define G1    (N1P/128)    // 172

#define LOG2E 1.4426950408889634f
#define LN2   0.6931471805599453f

// smem tile: [128 rows][64 k] bf16, row stride 72 (pad) -> 18432 B per matrix
#define RS    72
#define TILE_B (128*RS*2)
// hidden-proj kernel (3 products): AH, AL, BH, BL
#define OFF_AH 0
#define OFF_AL TILE_B
#define OFF_BH (2*TILE_B)
#define OFF_BL (3*TILE_B)
#define SMEM_HID (4*TILE_B)   // 73728
// fused LSE kernel (2 products): AH, BH, BL
#define LOFF_AH 0
#define LOFF_BH TILE_B
#define LOFF_BL (2*TILE_B)
#define SMEM_LSE (3*TILE_B)   // 55296

// ---------------- device scratch ----------------
__device__ int   g_n0, g_n1;
__device__ int   g_idx0[BB], g_idx1[BB];
__device__ int   g_cid[BB], g_gind[BB], g_t0[BB], g_t1[BB];
__device__ __nv_bfloat16 g_Xhi[BB*NINP],  g_Xlo[BB*NINP];
__device__ __nv_bfloat16 g_Whh[NHP*NINP], g_Whl[NHP*NINP];
__device__ __nv_bfloat16 g_W10h[H0D*NINP], g_W10l[H0D*NINP];
__device__ __nv_bfloat16 g_W11h[128*NINP], g_W11l[128*NINP];
__device__ __nv_bfloat16 g_W20h[N0P*H0D], g_W20l[N0P*H0D];
__device__ __nv_bfloat16 g_W21h[N1P*H1D], g_W21l[N1P*H1D];
__device__ float g_H0[BB*H0D]; __device__ __nv_bfloat16 g_H0h[BB*H0D], g_H0l[BB*H0D];
__device__ float g_H1[BB*H1D]; __device__ __nv_bfloat16 g_H1h[BB*H1D], g_H1l[BB*H1D];
__device__ float g_zh[BB], g_z0[BB], g_z1[BB];
__device__ float g_psH[BB*GH];
__device__ float g_ps0[(size_t)BB*G0];
__device__ float g_ps1[(size_t)BB*G1];
__device__ float g_blocksum[16];

// ---------------- helpers ----------------
__device__ __forceinline__ uint32_t smem_u32(const void* p) {
    uint32_t a;
    asm("{ .reg .u64 t; cvta.to.shared.u64 t, %1; cvt.u32.u64 %0, t; }" : "=r"(a) : "l"(p));
    return a;
}
__device__ __forceinline__ void ldmx4(uint32_t* r, uint32_t addr) {
    asm volatile("ldmatrix.sync.aligned.m8n8.x4.shared.b16 {%0,%1,%2,%3}, [%4];"
        : "=r"(r[0]), "=r"(r[1]), "=r"(r[2]), "=r"(r[3]) : "r"(addr));
}
__device__ __forceinline__ void ldmx2(uint32_t* r, uint32_t addr) {
    asm volatile("ldmatrix.sync.aligned.m8n8.x2.shared.b16 {%0,%1}, [%2];"
        : "=r"(r[0]), "=r"(r[1]) : "r"(addr));
}
__device__ __forceinline__ void mma16816(float* c, const uint32_t* a, const uint32_t* b) {
    asm volatile("mma.sync.aligned.m16n8k16.row.col.f32.bf16.bf16.f32 "
        "{%0,%1,%2,%3}, {%4,%5,%6,%7}, {%8,%9}, {%0,%1,%2,%3};"
        : "+f"(c[0]), "+f"(c[1]), "+f"(c[2]), "+f"(c[3])
        : "r"(a[0]), "r"(a[1]), "r"(a[2]), "r"(a[3]), "r"(b[0]), "r"(b[1]));
}
__device__ __forceinline__ uint32_t ex2_pair(float a, float b) {
    uint32_t p;
    asm("cvt.rn.f16x2.f32 %0, %1, %2;" : "=r"(p) : "f"(b), "f"(a));
    asm("ex2.approx.f16x2 %0, %0;" : "+r"(p));
    return p;
}
__device__ __forceinline__ uint32_t hadd2u(uint32_t a, uint32_t b) {
    uint32_t d;
    asm("add.f16x2 %0, %1, %2;" : "=r"(d) : "r"(a), "r"(b));
    return d;
}

// ---------------- small kernels ----------------
__global__ void init_kernel() { g_n0 = 0; g_n1 = 0; }

__global__ void prep_kernel(const int* __restrict__ target) {
    int i = blockIdx.x * blockDim.x + threadIdx.x;
    if (i >= BB) return;
    int t = target[i];
    int cid = (t >= C0) + (t >= C1);
    g_cid[i]  = cid;
    g_gind[i] = (cid == 0) ? t : (C0 + cid - 1);
    int a = t - C0; a = a < 0 ? 0 : a; a = a > N0T-1 ? N0T-1 : a; g_t0[i] = a;
    int b = t - C1; b = b < 0 ? 0 : b; b = b > N1T-1 ? N1T-1 : b; g_t1[i] = b;
    if (cid == 1)      g_idx0[atomicAdd(&g_n0, 1)] = i;
    else if (cid == 2) g_idx1[atomicAdd(&g_n1, 1)] = i;
}

__global__ void splitx_kernel(const float* __restrict__ X) {
    int i = blockIdx.x * 256 + threadIdx.x;
    float v = X[i];
    __nv_bfloat16 h = __float2bfloat16(v);
    g_Xhi[i] = h;
    g_Xlo[i] = __float2bfloat16(v - __bfloat162float(h));
}

// transpose + split + scale (LOG2E folded into LSE matrices)
__global__ void tsplit_kernel(const float* __restrict__ src, int R, int C, int Cpad,
                              int sel, float scale) {
    __nv_bfloat16 *dhi, *dlo;
    switch (sel) {
        case 0: dhi = g_Whh;  dlo = g_Whl;  break;
        case 1: dhi = g_W10h; dlo = g_W10l; break;
        case 2: dhi = g_W11h; dlo = g_W11l; break;
        case 3: dhi = g_W20h; dlo = g_W20l; break;
        default: dhi = g_W21h; dlo = g_W21l; break;
    }
    __shared__ float t[32][33];
    int cb = blockIdx.x * 32, rb = blockIdx.y * 32;
#pragma unroll
    for (int e = 0; e < 4; e++) {
        int rr = rb + threadIdx.y + e*8, cc = cb + threadIdx.x;
        t[threadIdx.y + e*8][threadIdx.x] = (rr < R && cc < C) ? src[(size_t)rr*C + cc] : 0.f;
    }
    __syncthreads();
#pragma unroll
    for (int e = 0; e < 4; e++) {
        int n = cb + threadIdx.y + e*8, k = rb + threadIdx.x;
        if (n < Cpad && k < R) {
            float v = t[threadIdx.x][threadIdx.y + e*8] * scale;
            __nv_bfloat16 h = __float2bfloat16(v);
            dhi[(size_t)n*R + k] = h;
            dlo[(size_t)n*R + k] = __float2bfloat16(v - __bfloat162float(h));
        }
    }
}

// ---------------- gathered logits, all three in one launch ----------------
__global__ void gatherdot_kernel(const float* __restrict__ X,
                                 const float* __restrict__ Wh,
                                 const float* __restrict__ W20,
                                 const float* __restrict__ W21) {
    int sel = blockIdx.y;
    const float* A; const float* W; const int* colidx; float* out; int K, N;
    if (sel == 0)      { A = X;    W = Wh;  colidx = g_gind; out = g_zh; K = NINP; N = NH; }
    else if (sel == 1) { A = g_H0; W = W20; colidx = g_t0;   out = g_z0; K = H0D;  N = N0T; }
    else               { A = g_H1; W = W21; colidx = g_t1;   out = g_z1; K = H1D;  N = N1T; }
    int w = (blockIdx.x * blockDim.x + threadIdx.x) >> 5;
    int lane = threadIdx.x & 31;
    if (w >= BB) return;
    int c = colidx[w];
    float s = 0.f;
    for (int k = lane; k < K; k += 32)
        s += A[(size_t)w*K + k] * W[(size_t)k*N + c];
#pragma unroll
    for (int o = 16; o > 0; o >>= 1) s += __shfl_xor_sync(0xffffffffu, s, o);
    if (lane == 0) out[w] = s;
}

// ---------------- hidden projections: 3-product split-bf16 mma ----------------
// sel: 0 = H0 (N=256), 1 = H1 (N=64)
__global__ __launch_bounds__(256, 2)
void hidden_kernel(int sel) {
    const __nv_bfloat16 *Ahi = g_Xhi, *Alo = g_Xlo, *Bhi, *Blo;
    int Nvalid, ldH; float* Hout; __nv_bfloat16 *Hh, *Hl;
    if (sel == 0) { Bhi=g_W10h; Blo=g_W10l; Nvalid=H0D; Hout=g_H0; Hh=g_H0h; Hl=g_H0l; ldH=H0D; }
    else          { Bhi=g_W11h; Blo=g_W11l; Nvalid=H1D; Hout=g_H1; Hh=g_H1h; Hl=g_H1l; ldH=H1D; }
    const int K = NINP;
    int rbase = blockIdx.x * 128, by = blockIdx.y;

    extern __shared__ __align__(16) char sm[];
    uint32_t sbase = smem_u32(sm);
    int tid = threadIdx.x, wid = tid >> 5, lane = tid & 31;
    int wm = wid >> 2, wn = wid & 3;

    float acc[4][4][4];
#pragma unroll
    for (int mt = 0; mt < 4; mt++)
#pragma unroll
        for (int nt = 0; nt < 4; nt++)
#pragma unroll
            for (int c = 0; c < 4; c++) acc[mt][nt][c] = 0.f;

    uint32_t aoff = (uint32_t)(((wm*64 + (lane & 15)) * RS + (lane >> 4) * 8) * 2);
    uint32_t boff = (uint32_t)(((wn*32 + (lane & 7)) * RS + ((lane >> 3) & 1) * 8) * 2);
    uint32_t aAH = sbase + OFF_AH + aoff, aAL = sbase + OFF_AL + aoff;
    uint32_t aBH = sbase + OFF_BH + boff, aBL = sbase + OFF_BL + boff;

    for (int ch = 0; ch < K/64; ch++) {
        int k0 = ch << 6;
#pragma unroll
        for (int e = 0; e < 4; e++) {
            int f = e*256 + tid, row = f >> 3, u = f & 7;
            size_t go = (size_t)(rbase + row) * K + k0 + u*8;
            uint32_t so = (uint32_t)((row*RS + u*8) * 2);
            *(uint4*)(sm + OFF_AH + so) = *(const uint4*)(Ahi + go);
            *(uint4*)(sm + OFF_AL + so) = *(const uint4*)(Alo + go);
            size_t gb = (size_t)(by*128 + row) * K + k0 + u*8;
            *(uint4*)(sm + OFF_BH + so) = *(const uint4*)(Bhi + gb);
            *(uint4*)(sm + OFF_BL + so) = *(const uint4*)(Blo + gb);
        }
        __syncthreads();
#pragma unroll
        for (int ks = 0; ks < 4; ks++) {
            uint32_t ah[4][4], al[4][4];
#pragma unroll
            for (int mt = 0; mt < 4; mt++) {
                uint32_t d = (uint32_t)(mt*16*RS*2 + ks*32);
                ldmx4(ah[mt], aAH + d);
                ldmx4(al[mt], aAL + d);
            }
#pragma unroll
            for (int nt = 0; nt < 4; nt++) {
                uint32_t d = (uint32_t)(nt*8*RS*2 + ks*32);
                uint32_t bh[2], bl[2];
                ldmx2(bh, aBH + d);
                ldmx2(bl, aBL + d);
#pragma unroll
                for (int mt = 0; mt < 4; mt++) {
                    mma16816(acc[mt][nt], ah[mt], bh);
                    mma16816(acc[mt][nt], ah[mt], bl);
                    mma16816(acc[mt][nt], al[mt], bh);
                }
            }
        }
        __syncthreads();
    }

    int q = lane >> 2, r4 = lane & 3;
#pragma unroll
    for (int mt = 0; mt < 4; mt++)
#pragma unroll
        for (int nt = 0; nt < 4; nt++)
#pragma unroll
            for (int c = 0; c < 4; c++) {
                int row = rbase + wm*64 + mt*16 + q + (c >> 1)*8;
                int col = by*128 + wn*32 + nt*8 + r4*2 + (c & 1);
                if (col < Nvalid) {
                    float v = acc[mt][nt][c];
                    Hout[(size_t)row*ldH + col] = v;
                    __nv_bfloat16 hh = __float2bfloat16(v);
                    Hh[(size_t)row*ldH + col] = hh;
                    Hl[(size_t)row*ldH + col] = __float2bfloat16(v - __bfloat162float(hh));
                }
            }
}

// ---------------- fused LSE kernel: all three clusters, interleaved ----------------
// 8192 CTAs, period-16 decode: slot 0 -> head, slots 1-4 -> tail0, slots 5-15 -> tail1.
// 2-product MMA: D = Ahi@Bhi + Ahi@Blo (Alo term dropped; ~6e-4 abs in base-2 logits).
__global__ __launch_bounds__(256, 2)
void lse_fused_kernel() {
    int z = blockIdx.x;
    int p = z >> 4, s = z & 15;
    int sel, bx, by;
    if (s == 0) {
        sel = 0; bx = p & 31; by = p >> 5;              // 512 head tiles
    } else if (s <= 4) {
        int idx = p*4 + (s-1);
        if (idx >= 32*G0) return;
        sel = 1; bx = idx & 31; by = idx >> 5;          // 2016 tail0 tiles
    } else {
        int idx = p*11 + (s-5);
        if (idx >= 32*G1) return;
        sel = 2; bx = idx & 31; by = idx >> 5;          // 5504 tail1 tiles
    }

    const __nv_bfloat16 *Ahi, *Bhi, *Blo;
    int K, Nvalid, G, cnt;
    const int* rowlist;
    float* pS;
    if (sel == 0)      { Ahi=g_Xhi;  K=NINP; Bhi=g_Whh;  Blo=g_Whl;  Nvalid=NH;  G=GH; pS=g_psH; rowlist=nullptr; cnt=BB; }
    else if (sel == 1) { Ahi=g_H0h;  K=H0D;  Bhi=g_W20h; Blo=g_W20l; Nvalid=N0T; G=G0; pS=g_ps0; rowlist=g_idx0; cnt=g_n0; }
    else               { Ahi=g_H1h;  K=H1D;  Bhi=g_W21h; Blo=g_W21l; Nvalid=N1T; G=G1; pS=g_ps1; rowlist=g_idx1; cnt=g_n1; }

    int rbase = bx * 128;
    if (rbase >= cnt) return;

    extern __shared__ __align__(16) char sm[];
    uint32_t sbase = smem_u32(sm);
    int tid = threadIdx.x, wid = tid >> 5, lane = tid & 31;
    int wm = wid >> 2, wn = wid & 3;

    float acc[4][4][4];
#pragma unroll
    for (int mt = 0; mt < 4; mt++)
#pragma unroll
        for (int nt = 0; nt < 4; nt++)
#pragma unroll
            for (int c = 0; c < 4; c++) acc[mt][nt][c] = 0.f;

    uint32_t aoff = (uint32_t)(((wm*64 + (lane & 15)) * RS + (lane >> 4) * 8) * 2);
    uint32_t boff = (uint32_t)(((wn*32 + (lane & 7)) * RS + ((lane >> 3) & 1) * 8) * 2);
    uint32_t aAH = sbase + LOFF_AH + aoff;
    uint32_t aBH = sbase + LOFF_BH + boff, aBL = sbase + LOFF_BL + boff;

    int nchunks = K >> 6;
    for (int ch = 0; ch < nchunks; ch++) {
        int k0 = ch << 6;
#pragma unroll
        for (int e = 0; e < 4; e++) {
            int f = e*256 + tid, row = f >> 3, u = f & 7;
            int grow = rbase + row; if (grow >= cnt) grow = cnt - 1;
            int arow = rowlist ? rowlist[grow] : grow;
            size_t go = (size_t)arow * K + k0 + u*8;
            uint32_t so = (uint32_t)((row*RS + u*8) * 2);
            *(uint4*)(sm + LOFF_AH + so) = *(const uint4*)(Ahi + go);
            size_t gb = (size_t)(by*128 + row) * K + k0 + u*8;
            *(uint4*)(sm + LOFF_BH + so) = *(const uint4*)(Bhi + gb);
            *(uint4*)(sm + LOFF_BL + so) = *(const uint4*)(Blo + gb);
        }
        __syncthreads();
#pragma unroll
        for (int ks = 0; ks < 4; ks++) {
            uint32_t ah[4][4];
#pragma unroll
            for (int mt = 0; mt < 4; mt++)
                ldmx4(ah[mt], aAH + (uint32_t)(mt*16*RS*2 + ks*32));
#pragma unroll
            for (int nt = 0; nt < 4; nt++) {
                uint32_t d = (uint32_t)(nt*8*RS*2 + ks*32);
                uint32_t bh[2], bl[2];
                ldmx2(bh, aBH + d);
                ldmx2(bl, aBL + d);
#pragma unroll
                for (int mt = 0; mt < 4; mt++) {
                    mma16816(acc[mt][nt], ah[mt], bh);
                    mma16816(acc[mt][nt], ah[mt], bl);
                }
            }
        }
        __syncthreads();
    }

    // sum of 2^t over this CTA's 128 cols per row (dual-half ex2)
    int q = lane >> 2, r4 = lane & 3;
    float* sps = (float*)sm;            // [128][4]
    bool edge = (by == G - 1);
#pragma unroll
    for (int mt = 0; mt < 4; mt++) {
#pragma unroll
        for (int h = 0; h < 2; h++) {
            float v[8];
#pragma unroll
            for (int nt = 0; nt < 4; nt++)
#pragma unroll
                for (int c = 0; c < 2; c++) {
                    float t = acc[mt][nt][h*2 + c];
                    if (edge) {
                        int col = by*128 + wn*32 + nt*8 + r4*2 + c;
                        if (col >= Nvalid) t = -100.f;
                    }
                    v[nt*2 + c] = t;
                }
            uint32_t e0 = ex2_pair(v[0], v[1]);
            uint32_t e1 = ex2_pair(v[2], v[3]);
            uint32_t e2 = ex2_pair(v[4], v[5]);
            uint32_t e3 = ex2_pair(v[6], v[7]);
            uint32_t t3 = hadd2u(hadd2u(e0, e1), hadd2u(e2, e3));
            __half2 hh = *(__half2*)&t3;
            float s8 = __low2float(hh) + __high2float(hh);
            s8 += __shfl_xor_sync(0xffffffffu, s8, 1);
            s8 += __shfl_xor_sync(0xffffffffu, s8, 2);
            if (r4 == 0) sps[(wm*64 + mt*16 + q + h*8)*4 + wn] = s8;
        }
    }
    __syncthreads();
    if (tid < 128) {
        float ssum = sps[tid*4 + 0] + sps[tid*4 + 1] + sps[tid*4 + 2] + sps[tid*4 + 3];
        int grow = rbase + tid;
        if (grow < cnt) {
            int orow = rowlist ? rowlist[grow] : grow;
            pS[(size_t)orow*G + by] = ssum;
        }
    }
}

// ---------------- combine + deterministic loss reduction ----------------
__global__ void combine_kernel(float* __restrict__ out) {
    __shared__ float red[256];
    int i = blockIdx.x * 256 + threadIdx.x;

    float s = 0.f;
    for (int g = 0; g < GH; g++) s += g_psH[(size_t)i*GH + g];
    float o = g_zh[i] - LN2 * log2f(s);

    int cid = g_cid[i];
    if (cid == 1) {
        float s2 = 0.f;
        for (int g = 0; g < G0; g++) s2 += g_ps0[(size_t)i*G0 + g];
        o += g_z0[i] - LN2 * log2f(s2);
    } else if (cid == 2) {
        float s2 = 0.f;
        for (int g = 0; g < G1; g++) s2 += g_ps1[(size_t)i*G1 + g];
        o += g_z1[i] - LN2 * log2f(s2);
    }
    out[i] = o;

    red[threadIdx.x] = o;
    __syncthreads();
    for (int st = 128; st > 0; st >>= 1) {
        if (threadIdx.x < st) red[threadIdx.x] += red[threadIdx.x + st];
        __syncthreads();
    }
    if (threadIdx.x == 0) g_blocksum[blockIdx.x] = red[0];
}

__global__ void finalize_kernel(float* __restrict__ out, int out_size) {
    float s = 0.f;
    for (int i = 0; i < 16; i++) s += g_blocksum[i];
    if (out_size > BB) out[BB] = -s / (float)BB;
}

// ---------------- launch ----------------
extern "C" void kernel_launch(void* const* d_in, const int* in_sizes, int n_in,
                              void* d_out, int out_size) {
    const float* X    = (const float*)d_in[0];
    const int*   tgt  = (const int*)d_in[1];
    const float* Wh   = (const float*)d_in[2];
    const float* W1_0 = (const float*)d_in[3];
    const float* W2_0 = (const float*)d_in[4];
    const float* W1_1 = (const float*)d_in[5];
    const float* W2_1 = (const float*)d_in[6];
    float* out = (float*)d_out;

    cudaFuncSetAttribute(hidden_kernel,    cudaFuncAttributeMaxDynamicSharedMemorySize, SMEM_HID);
    cudaFuncSetAttribute(lse_fused_kernel, cudaFuncAttributeMaxDynamicSharedMemorySize, SMEM_LSE);

    init_kernel<<<1, 1>>>();
    prep_kernel<<<BB/256, 256>>>(tgt);
    splitx_kernel<<<BB*NINP/256, 256>>>(X);

    // LSE matrices carry the log2(e) factor; hidden projections do not.
    tsplit_kernel<<<dim3(NHP/32, NINP/32), dim3(32,8)>>>(Wh,   NINP, NH,  NHP, 0, LOG2E);
    tsplit_kernel<<<dim3(H0D/32, NINP/32), dim3(32,8)>>>(W1_0, NINP, H0D, H0D, 1, 1.0f);
    tsplit_kernel<<<dim3(128/32, NINP/32), dim3(32,8)>>>(W1_1, NINP, H1D, 128, 2, 1.0f);
    tsplit_kernel<<<dim3(N0P/32, H0D/32),  dim3(32,8)>>>(W2_0, H0D,  N0T, N0P, 3, LOG2E);
    tsplit_kernel<<<dim3(N1P/32, H1D/32),  dim3(32,8)>>>(W2_1, H1D,  N1T, N1P, 4, LOG2E);

    // hidden projections (3-product; emits fp32 H + bf16 splits)
    hidden_kernel<<<dim3(BB/128, H0D/128), 256, SMEM_HID>>>(0);
    hidden_kernel<<<dim3(BB/128, 1),       256, SMEM_HID>>>(1);

    // gathered logits (fp32 exact), all three in one launch
    gatherdot_kernel<<<dim3(BB*32/256, 3), 256>>>(X, Wh, W2_0, W2_1);

    // fused, interleaved sum-of-exp2 over all three clusters
    lse_fused_kernel<<<8192, 256, SMEM_LSE>>>();

    combine_kernel<<<BB/256, 256>>>(out);
    finalize_kernel<<<1, 1>>>(out, out_size);
}

// round 9
// speedup vs baseline: 2.7207x; 1.0313x over previous
#include <cuda_runtime.h>
#include <cuda_bf16.h>
#include <math.h>
#include <stdint.h>

// ---------------- problem constants ----------------
#define BB    4096
#define NINP  1024
#define C0    2000
#define C1    10000
#define NH    2002
#define N0T   8000
#define N1T   22000
#define H0D   256
#define H1D   64

#define NHP   2048
#define N0P   8064
#define N1P   22016
#define GH    (NHP/128)    // 16
#define G0    (N0P/128)    // 63
#define G1    (N1P/128)    // 172

#define LOG2E 1.4426950408889634f
#define LN2   0.6931471805599453f
// mean of (1+f)/2^f over f~U[0,1): 1.04068203 ; its reciprocal:
#define SCHR_CORR 0.96090830f

#define RS    72
#define TILE_B (128*RS*2)
#define OFF_AH 0
#define OFF_AL TILE_B
#define OFF_BH (2*TILE_B)
#define OFF_BL (3*TILE_B)
#define SMEM_HID (4*TILE_B)   // 73728
#define LOFF_AH 0
#define LOFF_BH TILE_B
#define LOFF_BL (2*TILE_B)
#define SMEM_LSE (3*TILE_B)   // 55296

// ---------------- device scratch ----------------
__device__ int   g_n0, g_n1;
__device__ int   g_idx0[BB], g_idx1[BB];
__device__ int   g_cid[BB], g_gind[BB], g_t0[BB], g_t1[BB];
__device__ __nv_bfloat16 g_Xhi[BB*NINP],  g_Xlo[BB*NINP];
__device__ __nv_bfloat16 g_Whh[NHP*NINP], g_Whl[NHP*NINP];
__device__ __nv_bfloat16 g_W10h[H0D*NINP], g_W10l[H0D*NINP];
__device__ __nv_bfloat16 g_W11h[128*NINP], g_W11l[128*NINP];
__device__ __nv_bfloat16 g_W20h[N0P*H0D], g_W20l[N0P*H0D];
__device__ __nv_bfloat16 g_W21h[N1P*H1D], g_W21l[N1P*H1D];
__device__ float g_H0[BB*H0D]; __device__ __nv_bfloat16 g_H0h[BB*H0D], g_H0l[BB*H0D];
__device__ float g_H1[BB*H1D]; __device__ __nv_bfloat16 g_H1h[BB*H1D], g_H1l[BB*H1D];
__device__ float g_zh[BB], g_z0[BB], g_z1[BB];   // base-2 units (log2e folded in)
__device__ float g_psH[BB*GH];
__device__ float g_ps0[(size_t)BB*G0];
__device__ float g_ps1[(size_t)BB*G1];
__device__ float g_blocksum[16];

// ---------------- helpers ----------------
__device__ __forceinline__ uint32_t smem_u32(const void* p) {
    uint32_t a;
    asm("{ .reg .u64 t; cvta.to.shared.u64 t, %1; cvt.u32.u64 %0, t; }" : "=r"(a) : "l"(p));
    return a;
}
__device__ __forceinline__ void ldmx4(uint32_t* r, uint32_t addr) {
    asm volatile("ldmatrix.sync.aligned.m8n8.x4.shared.b16 {%0,%1,%2,%3}, [%4];"
        : "=r"(r[0]), "=r"(r[1]), "=r"(r[2]), "=r"(r[3]) : "r"(addr));
}
__device__ __forceinline__ void ldmx2(uint32_t* r, uint32_t addr) {
    asm volatile("ldmatrix.sync.aligned.m8n8.x2.shared.b16 {%0,%1}, [%2];"
        : "=r"(r[0]), "=r"(r[1]) : "r"(addr));
}
__device__ __forceinline__ void mma16816(float* c, const uint32_t* a, const uint32_t* b) {
    asm volatile("mma.sync.aligned.m16n8k16.row.col.f32.bf16.bf16.f32 "
        "{%0,%1,%2,%3}, {%4,%5,%6,%7}, {%8,%9}, {%0,%1,%2,%3};"
        : "+f"(c[0]), "+f"(c[1]), "+f"(c[2]), "+f"(c[3])
        : "r"(a[0]), "r"(a[1]), "r"(a[2]), "r"(a[3]), "r"(b[0]), "r"(b[1]));
}
__device__ __forceinline__ uint32_t ex2_pair(float a, float b) {
    uint32_t p;
    asm("cvt.rn.f16x2.f32 %0, %1, %2;" : "=r"(p) : "f"(b), "f"(a));
    asm("ex2.approx.f16x2 %0, %0;" : "+r"(p));
    return p;
}
__device__ __forceinline__ uint32_t hadd2u(uint32_t a, uint32_t b) {
    uint32_t d;
    asm("add.f16x2 %0, %1, %2;" : "=r"(d) : "r"(a), "r"(b));
    return d;
}
// Schraudolph exp2: bits-linear 2^t (overestimates by mean 1.040682; corrected at merge)
__device__ __forceinline__ float schr_exp2(float t) {
    float vv = fmaf(t, 32768.0f, 12582912.0f);           // mantissa := round(t*2^15)
    return __uint_as_float((__float_as_uint(vv) << 8) + 0xFF800000u);
}

// ---------------- small kernels ----------------
__global__ void init_kernel() { g_n0 = 0; g_n1 = 0; }

__global__ void prep_kernel(const int* __restrict__ target) {
    int i = blockIdx.x * blockDim.x + threadIdx.x;
    if (i >= BB) return;
    int t = target[i];
    int cid = (t >= C0) + (t >= C1);
    g_cid[i]  = cid;
    g_gind[i] = (cid == 0) ? t : (C0 + cid - 1);
    int a = t - C0; a = a < 0 ? 0 : a; a = a > N0T-1 ? N0T-1 : a; g_t0[i] = a;
    int b = t - C1; b = b < 0 ? 0 : b; b = b > N1T-1 ? N1T-1 : b; g_t1[i] = b;
    if (cid == 1)      g_idx0[atomicAdd(&g_n0, 1)] = i;
    else if (cid == 2) g_idx1[atomicAdd(&g_n1, 1)] = i;
}

__global__ void splitx_kernel(const float* __restrict__ X) {
    int i = blockIdx.x * 256 + threadIdx.x;
    float v = X[i];
    __nv_bfloat16 h = __float2bfloat16(v);
    g_Xhi[i] = h;
    g_Xlo[i] = __float2bfloat16(v - __bfloat162float(h));
}

// transpose + split + scale (LOG2E folded into LSE matrices)
__global__ void tsplit_kernel(const float* __restrict__ src, int R, int C, int Cpad,
                              int sel, float scale) {
    __nv_bfloat16 *dhi, *dlo;
    switch (sel) {
        case 0: dhi = g_Whh;  dlo = g_Whl;  break;
        case 1: dhi = g_W10h; dlo = g_W10l; break;
        case 2: dhi = g_W11h; dlo = g_W11l; break;
        case 3: dhi = g_W20h; dlo = g_W20l; break;
        default: dhi = g_W21h; dlo = g_W21l; break;
    }
    __shared__ float t[32][33];
    int cb = blockIdx.x * 32, rb = blockIdx.y * 32;
#pragma unroll
    for (int e = 0; e < 4; e++) {
        int rr = rb + threadIdx.y + e*8, cc = cb + threadIdx.x;
        t[threadIdx.y + e*8][threadIdx.x] = (rr < R && cc < C) ? src[(size_t)rr*C + cc] : 0.f;
    }
    __syncthreads();
#pragma unroll
    for (int e = 0; e < 4; e++) {
        int n = cb + threadIdx.y + e*8, k = rb + threadIdx.x;
        if (n < Cpad && k < R) {
            float v = t[threadIdx.x][threadIdx.y + e*8] * scale;
            __nv_bfloat16 h = __float2bfloat16(v);
            dhi[(size_t)n*R + k] = h;
            dlo[(size_t)n*R + k] = __float2bfloat16(v - __bfloat162float(h));
        }
    }
}

// ---------------- gathered logits: coalesced via transposed bf16 hi/lo ----------
// Produces z in base-2 units (weights carry log2e).
__global__ void gatherdot_kernel(const float* __restrict__ X) {
    int sel = blockIdx.y;
    const float* A; const __nv_bfloat16 *Whi, *Wlo; const int* colidx; float* out; int K;
    if (sel == 0)      { A = X;    Whi = g_Whh;  Wlo = g_Whl;  colidx = g_gind; out = g_zh; K = NINP; }
    else if (sel == 1) { A = g_H0; Whi = g_W20h; Wlo = g_W20l; colidx = g_t0;   out = g_z0; K = H0D; }
    else               { A = g_H1; Whi = g_W21h; Wlo = g_W21l; colidx = g_t1;   out = g_z1; K = H1D; }
    int w = (blockIdx.x * blockDim.x + threadIdx.x) >> 5;
    int lane = threadIdx.x & 31;
    if (w >= BB) return;
    int c = colidx[w];
    float s = 0.f;
    for (int k = lane*2; k < K; k += 64) {
        float2 a = *(const float2*)&A[(size_t)w*K + k];
        __nv_bfloat162 h = *(const __nv_bfloat162*)&Whi[(size_t)c*K + k];
        __nv_bfloat162 l = *(const __nv_bfloat162*)&Wlo[(size_t)c*K + k];
        s += a.x * (__bfloat162float(h.x) + __bfloat162float(l.x));
        s += a.y * (__bfloat162float(h.y) + __bfloat162float(l.y));
    }
#pragma unroll
    for (int o = 16; o > 0; o >>= 1) s += __shfl_xor_sync(0xffffffffu, s, o);
    if (lane == 0) out[w] = s;
}

// ---------------- hidden projections: 3-product split-bf16 mma ----------------
__global__ __launch_bounds__(256, 2)
void hidden_kernel(int sel) {
    const __nv_bfloat16 *Ahi = g_Xhi, *Alo = g_Xlo, *Bhi, *Blo;
    int Nvalid, ldH; float* Hout; __nv_bfloat16 *Hh, *Hl;
    if (sel == 0) { Bhi=g_W10h; Blo=g_W10l; Nvalid=H0D; Hout=g_H0; Hh=g_H0h; Hl=g_H0l; ldH=H0D; }
    else          { Bhi=g_W11h; Blo=g_W11l; Nvalid=H1D; Hout=g_H1; Hh=g_H1h; Hl=g_H1l; ldH=H1D; }
    const int K = NINP;
    int rbase = blockIdx.x * 128, by = blockIdx.y;

    extern __shared__ __align__(16) char sm[];
    uint32_t sbase = smem_u32(sm);
    int tid = threadIdx.x, wid = tid >> 5, lane = tid & 31;
    int wm = wid >> 2, wn = wid & 3;

    float acc[4][4][4];
#pragma unroll
    for (int mt = 0; mt < 4; mt++)
#pragma unroll
        for (int nt = 0; nt < 4; nt++)
#pragma unroll
            for (int c = 0; c < 4; c++) acc[mt][nt][c] = 0.f;

    uint32_t aoff = (uint32_t)(((wm*64 + (lane & 15)) * RS + (lane >> 4) * 8) * 2);
    uint32_t boff = (uint32_t)(((wn*32 + (lane & 7)) * RS + ((lane >> 3) & 1) * 8) * 2);
    uint32_t aAH = sbase + OFF_AH + aoff, aAL = sbase + OFF_AL + aoff;
    uint32_t aBH = sbase + OFF_BH + boff, aBL = sbase + OFF_BL + boff;

    for (int ch = 0; ch < K/64; ch++) {
        int k0 = ch << 6;
#pragma unroll
        for (int e = 0; e < 4; e++) {
            int f = e*256 + tid, row = f >> 3, u = f & 7;
            size_t go = (size_t)(rbase + row) * K + k0 + u*8;
            uint32_t so = (uint32_t)((row*RS + u*8) * 2);
            *(uint4*)(sm + OFF_AH + so) = *(const uint4*)(Ahi + go);
            *(uint4*)(sm + OFF_AL + so) = *(const uint4*)(Alo + go);
            size_t gb = (size_t)(by*128 + row) * K + k0 + u*8;
            *(uint4*)(sm + OFF_BH + so) = *(const uint4*)(Bhi + gb);
            *(uint4*)(sm + OFF_BL + so) = *(const uint4*)(Blo + gb);
        }
        __syncthreads();
#pragma unroll
        for (int ks = 0; ks < 4; ks++) {
            uint32_t ah[4][4], al[4][4];
#pragma unroll
            for (int mt = 0; mt < 4; mt++) {
                uint32_t d = (uint32_t)(mt*16*RS*2 + ks*32);
                ldmx4(ah[mt], aAH + d);
                ldmx4(al[mt], aAL + d);
            }
#pragma unroll
            for (int nt = 0; nt < 4; nt++) {
                uint32_t d = (uint32_t)(nt*8*RS*2 + ks*32);
                uint32_t bh[2], bl[2];
                ldmx2(bh, aBH + d);
                ldmx2(bl, aBL + d);
#pragma unroll
                for (int mt = 0; mt < 4; mt++) {
                    mma16816(acc[mt][nt], ah[mt], bh);
                    mma16816(acc[mt][nt], ah[mt], bl);
                    mma16816(acc[mt][nt], al[mt], bh);
                }
            }
        }
        __syncthreads();
    }

    int q = lane >> 2, r4 = lane & 3;
#pragma unroll
    for (int mt = 0; mt < 4; mt++)
#pragma unroll
        for (int nt = 0; nt < 4; nt++)
#pragma unroll
            for (int c = 0; c < 4; c++) {
                int row = rbase + wm*64 + mt*16 + q + (c >> 1)*8;
                int col = by*128 + wn*32 + nt*8 + r4*2 + (c & 1);
                if (col < Nvalid) {
                    float v = acc[mt][nt][c];
                    Hout[(size_t)row*ldH + col] = v;
                    __nv_bfloat16 hh = __float2bfloat16(v);
                    Hh[(size_t)row*ldH + col] = hh;
                    Hl[(size_t)row*ldH + col] = __float2bfloat16(v - __bfloat162float(hh));
                }
            }
}

// ---------------- fused LSE kernel: interleaved clusters, hybrid dual-pipe exp ----
__global__ __launch_bounds__(256, 2)
void lse_fused_kernel() {
    int z = blockIdx.x;
    int p = z >> 4, s = z & 15;
    int sel, bx, by;
    if (s == 0) {
        sel = 0; bx = p & 31; by = p >> 5;
    } else if (s <= 4) {
        int idx = p*4 + (s-1);
        if (idx >= 32*G0) return;
        sel = 1; bx = idx & 31; by = idx >> 5;
    } else {
        int idx = p*11 + (s-5);
        if (idx >= 32*G1) return;
        sel = 2; bx = idx & 31; by = idx >> 5;
    }

    const __nv_bfloat16 *Ahi, *Bhi, *Blo;
    int K, Nvalid, G, cnt;
    const int* rowlist;
    float* pS;
    if (sel == 0)      { Ahi=g_Xhi;  K=NINP; Bhi=g_Whh;  Blo=g_Whl;  Nvalid=NH;  G=GH; pS=g_psH; rowlist=nullptr; cnt=BB; }
    else if (sel == 1) { Ahi=g_H0h;  K=H0D;  Bhi=g_W20h; Blo=g_W20l; Nvalid=N0T; G=G0; pS=g_ps0; rowlist=g_idx0; cnt=g_n0; }
    else               { Ahi=g_H1h;  K=H1D;  Bhi=g_W21h; Blo=g_W21l; Nvalid=N1T; G=G1; pS=g_ps1; rowlist=g_idx1; cnt=g_n1; }

    int rbase = bx * 128;
    if (rbase >= cnt) return;

    extern __shared__ __align__(16) char sm[];
    uint32_t sbase = smem_u32(sm);
    int tid = threadIdx.x, wid = tid >> 5, lane = tid & 31;
    int wm = wid >> 2, wn = wid & 3;

    float acc[4][4][4];
#pragma unroll
    for (int mt = 0; mt < 4; mt++)
#pragma unroll
        for (int nt = 0; nt < 4; nt++)
#pragma unroll
            for (int c = 0; c < 4; c++) acc[mt][nt][c] = 0.f;

    uint32_t aoff = (uint32_t)(((wm*64 + (lane & 15)) * RS + (lane >> 4) * 8) * 2);
    uint32_t boff = (uint32_t)(((wn*32 + (lane & 7)) * RS + ((lane >> 3) & 1) * 8) * 2);
    uint32_t aAH = sbase + LOFF_AH + aoff;
    uint32_t aBH = sbase + LOFF_BH + boff, aBL = sbase + LOFF_BL + boff;

    int nchunks = K >> 6;
    for (int ch = 0; ch < nchunks; ch++) {
        int k0 = ch << 6;
#pragma unroll
        for (int e = 0; e < 4; e++) {
            int f = e*256 + tid, row = f >> 3, u = f & 7;
            int grow = rbase + row; if (grow >= cnt) grow = cnt - 1;
            int arow = rowlist ? rowlist[grow] : grow;
            size_t go = (size_t)arow * K + k0 + u*8;
            uint32_t so = (uint32_t)((row*RS + u*8) * 2);
            *(uint4*)(sm + LOFF_AH + so) = *(const uint4*)(Ahi + go);
            size_t gb = (size_t)(by*128 + row) * K + k0 + u*8;
            *(uint4*)(sm + LOFF_BH + so) = *(const uint4*)(Bhi + gb);
            *(uint4*)(sm + LOFF_BL + so) = *(const uint4*)(Blo + gb);
        }
        __syncthreads();
#pragma unroll
        for (int ks = 0; ks < 4; ks++) {
            uint32_t ah[4][4];
#pragma unroll
            for (int mt = 0; mt < 4; mt++)
                ldmx4(ah[mt], aAH + (uint32_t)(mt*16*RS*2 + ks*32));
#pragma unroll
            for (int nt = 0; nt < 4; nt++) {
                uint32_t d = (uint32_t)(nt*8*RS*2 + ks*32);
                uint32_t bh[2], bl[2];
                ldmx2(bh, aBH + d);
                ldmx2(bl, aBL + d);
#pragma unroll
                for (int mt = 0; mt < 4; mt++) {
                    mma16816(acc[mt][nt], ah[mt], bh);
                    mma16816(acc[mt][nt], ah[mt], bl);
                }
            }
        }
        __syncthreads();
    }

    // hybrid epilogue: 4 values via MUFU f16x2, 4 via Schraudolph (fma/alu pipes)
    int q = lane >> 2, r4 = lane & 3;
    float* sps = (float*)sm;            // [128][4]
    bool edge = (by == G - 1);
#pragma unroll
    for (int mt = 0; mt < 4; mt++) {
#pragma unroll
        for (int h = 0; h < 2; h++) {
            float v[8];
#pragma unroll
            for (int nt = 0; nt < 4; nt++)
#pragma unroll
                for (int c = 0; c < 2; c++) {
                    float t = acc[mt][nt][h*2 + c];
                    if (edge) {
                        int col = by*128 + wn*32 + nt*8 + r4*2 + c;
                        if (col >= Nvalid) t = -100.f;
                    }
                    v[nt*2 + c] = t;
                }
            // MUFU half
            uint32_t e0 = ex2_pair(v[0], v[1]);
            uint32_t e1 = ex2_pair(v[2], v[3]);
            uint32_t t2 = hadd2u(e0, e1);
            __half2 hh = *(__half2*)&t2;
            float sm_ = __low2float(hh) + __high2float(hh);
            // Schraudolph half (zero-mean after SCHR_CORR)
            float y4 = schr_exp2(v[4]);
            float y5 = schr_exp2(v[5]);
            float y6 = schr_exp2(v[6]);
            float y7 = schr_exp2(v[7]);
            float s8 = fmaf(SCHR_CORR, (y4 + y5) + (y6 + y7), sm_);
            s8 += __shfl_xor_sync(0xffffffffu, s8, 1);
            s8 += __shfl_xor_sync(0xffffffffu, s8, 2);
            if (r4 == 0) sps[(wm*64 + mt*16 + q + h*8)*4 + wn] = s8;
        }
    }
    __syncthreads();
    if (tid < 128) {
        float ssum = sps[tid*4 + 0] + sps[tid*4 + 1] + sps[tid*4 + 2] + sps[tid*4 + 3];
        int grow = rbase + tid;
        if (grow < cnt) {
            int orow = rowlist ? rowlist[grow] : grow;
            pS[(size_t)orow*G + by] = ssum;
        }
    }
}

// ---------------- combine + deterministic loss reduction ----------------
__global__ void combine_kernel(float* __restrict__ out) {
    __shared__ float red[256];
    int i = blockIdx.x * 256 + threadIdx.x;

    float s = 0.f;
    for (int g = 0; g < GH; g++) s += g_psH[(size_t)i*GH + g];
    float o = g_zh[i] - log2f(s);

    int cid = g_cid[i];
    if (cid == 1) {
        float s2 = 0.f;
        for (int g = 0; g < G0; g++) s2 += g_ps0[(size_t)i*G0 + g];
        o += g_z0[i] - log2f(s2);
    } else if (cid == 2) {
        float s2 = 0.f;
        for (int g = 0; g < G1; g++) s2 += g_ps1[(size_t)i*G1 + g];
        o += g_z1[i] - log2f(s2);
    }
    o *= LN2;
    out[i] = o;

    red[threadIdx.x] = o;
    __syncthreads();
    for (int st = 128; st > 0; st >>= 1) {
        if (threadIdx.x < st) red[threadIdx.x] += red[threadIdx.x + st];
        __syncthreads();
    }
    if (threadIdx.x == 0) g_blocksum[blockIdx.x] = red[0];
}

__global__ void finalize_kernel(float* __restrict__ out, int out_size) {
    float s = 0.f;
    for (int i = 0; i < 16; i++) s += g_blocksum[i];
    if (out_size > BB) out[BB] = -s / (float)BB;
}

// ---------------- launch ----------------
extern "C" void kernel_launch(void* const* d_in, const int* in_sizes, int n_in,
                              void* d_out, int out_size) {
    const float* X    = (const float*)d_in[0];
    const int*   tgt  = (const int*)d_in[1];
    const float* Wh   = (const float*)d_in[2];
    const float* W1_0 = (const float*)d_in[3];
    const float* W2_0 = (const float*)d_in[4];
    const float* W1_1 = (const float*)d_in[5];
    const float* W2_1 = (const float*)d_in[6];
    float* out = (float*)d_out;

    cudaFuncSetAttribute(hidden_kernel,    cudaFuncAttributeMaxDynamicSharedMemorySize, SMEM_HID);
    cudaFuncSetAttribute(lse_fused_kernel, cudaFuncAttributeMaxDynamicSharedMemorySize, SMEM_LSE);

    init_kernel<<<1, 1>>>();
    prep_kernel<<<BB/256, 256>>>(tgt);
    splitx_kernel<<<BB*NINP/256, 256>>>(X);

    tsplit_kernel<<<dim3(NHP/32, NINP/32), dim3(32,8)>>>(Wh,   NINP, NH,  NHP, 0, LOG2E);
    tsplit_kernel<<<dim3(H0D/32, NINP/32), dim3(32,8)>>>(W1_0, NINP, H0D, H0D, 1, 1.0f);
    tsplit_kernel<<<dim3(128/32, NINP/32), dim3(32,8)>>>(W1_1, NINP, H1D, 128, 2, 1.0f);
    tsplit_kernel<<<dim3(N0P/32, H0D/32),  dim3(32,8)>>>(W2_0, H0D,  N0T, N0P, 3, LOG2E);
    tsplit_kernel<<<dim3(N1P/32, H1D/32),  dim3(32,8)>>>(W2_1, H1D,  N1T, N1P, 4, LOG2E);

    hidden_kernel<<<dim3(BB/128, H0D/128), 256, SMEM_HID>>>(0);
    hidden_kernel<<<dim3(BB/128, 1),       256, SMEM_HID>>>(1);

    // gathered logits (coalesced bf16 hi/lo reads; z in base-2 units)
    gatherdot_kernel<<<dim3(BB*32/256, 3), 256>>>(X);

    // fused, interleaved sum-of-exp2 with hybrid MUFU+Schraudolph exp
    lse_fused_kernel<<<8192, 256, SMEM_LSE>>>();

    combine_kernel<<<BB/256, 256>>>(out);
    finalize_kernel<<<1, 1>>>(out, out_size);
}

// round 10
// speedup vs baseline: 3.4874x; 1.2818x over previous
#include <cuda_runtime.h>
#include <cuda_bf16.h>
#include <math.h>
#include <stdint.h>

// ---------------- problem constants ----------------
#define BB    4096
#define NINP  1024
#define C0    2000
#define C1    10000
#define NH    2002
#define N0T   8000
#define N1T   22000
#define H0D   256
#define H1D   64

#define NHP   2048
#define N0P   8064
#define N1P   22016
#define GH    (NHP/128)    // 16
#define G0    (N0P/128)    // 63
#define G1    (N1P/128)    // 172

#define LOG2E 1.4426950408889634f
#define LN2   0.6931471805599453f
#define SCHR_CORR 0.96090830f

#define RS    72
#define TILE_B (128*RS*2)      // 18432
// hidden kernel (3 products): AH AL BH BL
#define OFF_AH 0
#define OFF_AL TILE_B
#define OFF_BH (2*TILE_B)
#define OFF_BL (3*TILE_B)
#define SMEM_HID (4*TILE_B)    // 73728
// fused LSE: double-buffered single product: 2 stages x (A + B)
#define STAGE_B (2*TILE_B)     // 36864
#define SMEM_LSE (2*STAGE_B)   // 73728

// ---------------- device scratch ----------------
__device__ int   g_n0, g_n1;
__device__ int   g_idx0[BB], g_idx1[BB];
__device__ int   g_cid[BB], g_gind[BB], g_t0[BB], g_t1[BB];
__device__ __nv_bfloat16 g_Xhi[BB*NINP],  g_Xlo[BB*NINP];
__device__ __nv_bfloat16 g_Whh[NHP*NINP], g_Whl[NHP*NINP];
__device__ __nv_bfloat16 g_W10h[H0D*NINP], g_W10l[H0D*NINP];
__device__ __nv_bfloat16 g_W11h[128*NINP], g_W11l[128*NINP];
__device__ __nv_bfloat16 g_W20h[N0P*H0D], g_W20l[N0P*H0D];
__device__ __nv_bfloat16 g_W21h[N1P*H1D], g_W21l[N1P*H1D];
__device__ float g_H0[BB*H0D]; __device__ __nv_bfloat16 g_H0h[BB*H0D], g_H0l[BB*H0D];
__device__ float g_H1[BB*H1D]; __device__ __nv_bfloat16 g_H1h[BB*H1D], g_H1l[BB*H1D];
__device__ float g_zh[BB], g_z0[BB], g_z1[BB];   // base-2 units
__device__ float g_psH[BB*GH];
__device__ float g_ps0[(size_t)BB*G0];
__device__ float g_ps1[(size_t)BB*G1];
__device__ float g_blocksum[16];

// ---------------- helpers ----------------
__device__ __forceinline__ uint32_t smem_u32(const void* p) {
    uint32_t a;
    asm("{ .reg .u64 t; cvta.to.shared.u64 t, %1; cvt.u32.u64 %0, t; }" : "=r"(a) : "l"(p));
    return a;
}
__device__ __forceinline__ void ldmx4(uint32_t* r, uint32_t addr) {
    asm volatile("ldmatrix.sync.aligned.m8n8.x4.shared.b16 {%0,%1,%2,%3}, [%4];"
        : "=r"(r[0]), "=r"(r[1]), "=r"(r[2]), "=r"(r[3]) : "r"(addr));
}
__device__ __forceinline__ void ldmx2(uint32_t* r, uint32_t addr) {
    asm volatile("ldmatrix.sync.aligned.m8n8.x2.shared.b16 {%0,%1}, [%2];"
        : "=r"(r[0]), "=r"(r[1]) : "r"(addr));
}
__device__ __forceinline__ void mma16816(float* c, const uint32_t* a, const uint32_t* b) {
    asm volatile("mma.sync.aligned.m16n8k16.row.col.f32.bf16.bf16.f32 "
        "{%0,%1,%2,%3}, {%4,%5,%6,%7}, {%8,%9}, {%0,%1,%2,%3};"
        : "+f"(c[0]), "+f"(c[1]), "+f"(c[2]), "+f"(c[3])
        : "r"(a[0]), "r"(a[1]), "r"(a[2]), "r"(a[3]), "r"(b[0]), "r"(b[1]));
}
__device__ __forceinline__ uint32_t ex2_pair(float a, float b) {
    uint32_t p;
    asm("cvt.rn.f16x2.f32 %0, %1, %2;" : "=r"(p) : "f"(b), "f"(a));
    asm("ex2.approx.f16x2 %0, %0;" : "+r"(p));
    return p;
}
__device__ __forceinline__ uint32_t hadd2u(uint32_t a, uint32_t b) {
    uint32_t d;
    asm("add.f16x2 %0, %1, %2;" : "=r"(d) : "r"(a), "r"(b));
    return d;
}
__device__ __forceinline__ float schr_exp2(float t) {
    float vv = fmaf(t, 32768.0f, 12582912.0f);
    return __uint_as_float((__float_as_uint(vv) << 8) + 0xFF800000u);
}
#define CP_ASYNC16(dst, src) \
    asm volatile("cp.async.cg.shared.global [%0], [%1], 16;" :: "r"(dst), "l"(src) : "memory")
#define CP_COMMIT() asm volatile("cp.async.commit_group;" ::: "memory")

// ---------------- small kernels ----------------
__global__ void init_kernel() { g_n0 = 0; g_n1 = 0; }

__global__ void prep_kernel(const int* __restrict__ target) {
    int i = blockIdx.x * blockDim.x + threadIdx.x;
    if (i >= BB) return;
    int t = target[i];
    int cid = (t >= C0) + (t >= C1);
    g_cid[i]  = cid;
    g_gind[i] = (cid == 0) ? t : (C0 + cid - 1);
    int a = t - C0; a = a < 0 ? 0 : a; a = a > N0T-1 ? N0T-1 : a; g_t0[i] = a;
    int b = t - C1; b = b < 0 ? 0 : b; b = b > N1T-1 ? N1T-1 : b; g_t1[i] = b;
    if (cid == 1)      g_idx0[atomicAdd(&g_n0, 1)] = i;
    else if (cid == 2) g_idx1[atomicAdd(&g_n1, 1)] = i;
}

__global__ void splitx_kernel(const float* __restrict__ X) {
    int i = blockIdx.x * 256 + threadIdx.x;
    float v = X[i];
    __nv_bfloat16 h = __float2bfloat16(v);
    g_Xhi[i] = h;
    g_Xlo[i] = __float2bfloat16(v - __bfloat162float(h));
}

__global__ void tsplit_kernel(const float* __restrict__ src, int R, int C, int Cpad,
                              int sel, float scale) {
    __nv_bfloat16 *dhi, *dlo;
    switch (sel) {
        case 0: dhi = g_Whh;  dlo = g_Whl;  break;
        case 1: dhi = g_W10h; dlo = g_W10l; break;
        case 2: dhi = g_W11h; dlo = g_W11l; break;
        case 3: dhi = g_W20h; dlo = g_W20l; break;
        default: dhi = g_W21h; dlo = g_W21l; break;
    }
    __shared__ float t[32][33];
    int cb = blockIdx.x * 32, rb = blockIdx.y * 32;
#pragma unroll
    for (int e = 0; e < 4; e++) {
        int rr = rb + threadIdx.y + e*8, cc = cb + threadIdx.x;
        t[threadIdx.y + e*8][threadIdx.x] = (rr < R && cc < C) ? src[(size_t)rr*C + cc] : 0.f;
    }
    __syncthreads();
#pragma unroll
    for (int e = 0; e < 4; e++) {
        int n = cb + threadIdx.y + e*8, k = rb + threadIdx.x;
        if (n < Cpad && k < R) {
            float v = t[threadIdx.x][threadIdx.y + e*8] * scale;
            __nv_bfloat16 h = __float2bfloat16(v);
            dhi[(size_t)n*R + k] = h;
            dlo[(size_t)n*R + k] = __float2bfloat16(v - __bfloat162float(h));
        }
    }
}

// ---------------- gathered logits (exact hi+lo, base-2 units) ----------------
__global__ void gatherdot_kernel(const float* __restrict__ X) {
    int sel = blockIdx.y;
    const float* A; const __nv_bfloat16 *Whi, *Wlo; const int* colidx; float* out; int K;
    if (sel == 0)      { A = X;    Whi = g_Whh;  Wlo = g_Whl;  colidx = g_gind; out = g_zh; K = NINP; }
    else if (sel == 1) { A = g_H0; Whi = g_W20h; Wlo = g_W20l; colidx = g_t0;   out = g_z0; K = H0D; }
    else               { A = g_H1; Whi = g_W21h; Wlo = g_W21l; colidx = g_t1;   out = g_z1; K = H1D; }
    int w = (blockIdx.x * blockDim.x + threadIdx.x) >> 5;
    int lane = threadIdx.x & 31;
    if (w >= BB) return;
    int c = colidx[w];
    float s = 0.f;
    for (int k = lane*2; k < K; k += 64) {
        float2 a = *(const float2*)&A[(size_t)w*K + k];
        __nv_bfloat162 h = *(const __nv_bfloat162*)&Whi[(size_t)c*K + k];
        __nv_bfloat162 l = *(const __nv_bfloat162*)&Wlo[(size_t)c*K + k];
        s += a.x * (__bfloat162float(h.x) + __bfloat162float(l.x));
        s += a.y * (__bfloat162float(h.y) + __bfloat162float(l.y));
    }
#pragma unroll
    for (int o = 16; o > 0; o >>= 1) s += __shfl_xor_sync(0xffffffffu, s, o);
    if (lane == 0) out[w] = s;
}

// ---------------- hidden projections: 3-product split-bf16 mma ----------------
__global__ __launch_bounds__(256, 2)
void hidden_kernel(int sel) {
    const __nv_bfloat16 *Ahi = g_Xhi, *Alo = g_Xlo, *Bhi, *Blo;
    int Nvalid, ldH; float* Hout; __nv_bfloat16 *Hh, *Hl;
    if (sel == 0) { Bhi=g_W10h; Blo=g_W10l; Nvalid=H0D; Hout=g_H0; Hh=g_H0h; Hl=g_H0l; ldH=H0D; }
    else          { Bhi=g_W11h; Blo=g_W11l; Nvalid=H1D; Hout=g_H1; Hh=g_H1h; Hl=g_H1l; ldH=H1D; }
    const int K = NINP;
    int rbase = blockIdx.x * 128, by = blockIdx.y;

    extern __shared__ __align__(16) char sm[];
    uint32_t sbase = smem_u32(sm);
    int tid = threadIdx.x, wid = tid >> 5, lane = tid & 31;
    int wm = wid >> 2, wn = wid & 3;

    float acc[4][4][4];
#pragma unroll
    for (int mt = 0; mt < 4; mt++)
#pragma unroll
        for (int nt = 0; nt < 4; nt++)
#pragma unroll
            for (int c = 0; c < 4; c++) acc[mt][nt][c] = 0.f;

    uint32_t aoff = (uint32_t)(((wm*64 + (lane & 15)) * RS + (lane >> 4) * 8) * 2);
    uint32_t boff = (uint32_t)(((wn*32 + (lane & 7)) * RS + ((lane >> 3) & 1) * 8) * 2);
    uint32_t aAH = sbase + OFF_AH + aoff, aAL = sbase + OFF_AL + aoff;
    uint32_t aBH = sbase + OFF_BH + boff, aBL = sbase + OFF_BL + boff;

    for (int ch = 0; ch < K/64; ch++) {
        int k0 = ch << 6;
#pragma unroll
        for (int e = 0; e < 4; e++) {
            int f = e*256 + tid, row = f >> 3, u = f & 7;
            size_t go = (size_t)(rbase + row) * K + k0 + u*8;
            uint32_t so = (uint32_t)((row*RS + u*8) * 2);
            *(uint4*)(sm + OFF_AH + so) = *(const uint4*)(Ahi + go);
            *(uint4*)(sm + OFF_AL + so) = *(const uint4*)(Alo + go);
            size_t gb = (size_t)(by*128 + row) * K + k0 + u*8;
            *(uint4*)(sm + OFF_BH + so) = *(const uint4*)(Bhi + gb);
            *(uint4*)(sm + OFF_BL + so) = *(const uint4*)(Blo + gb);
        }
        __syncthreads();
#pragma unroll
        for (int ks = 0; ks < 4; ks++) {
            uint32_t ah[4][4], al[4][4];
#pragma unroll
            for (int mt = 0; mt < 4; mt++) {
                uint32_t d = (uint32_t)(mt*16*RS*2 + ks*32);
                ldmx4(ah[mt], aAH + d);
                ldmx4(al[mt], aAL + d);
            }
#pragma unroll
            for (int nt = 0; nt < 4; nt++) {
                uint32_t d = (uint32_t)(nt*8*RS*2 + ks*32);
                uint32_t bh[2], bl[2];
                ldmx2(bh, aBH + d);
                ldmx2(bl, aBL + d);
#pragma unroll
                for (int mt = 0; mt < 4; mt++) {
                    mma16816(acc[mt][nt], ah[mt], bh);
                    mma16816(acc[mt][nt], ah[mt], bl);
                    mma16816(acc[mt][nt], al[mt], bh);
                }
            }
        }
        __syncthreads();
    }

    int q = lane >> 2, r4 = lane & 3;
#pragma unroll
    for (int mt = 0; mt < 4; mt++)
#pragma unroll
        for (int nt = 0; nt < 4; nt++)
#pragma unroll
            for (int c = 0; c < 4; c++) {
                int row = rbase + wm*64 + mt*16 + q + (c >> 1)*8;
                int col = by*128 + wn*32 + nt*8 + r4*2 + (c & 1);
                if (col < Nvalid) {
                    float v = acc[mt][nt][c];
                    Hout[(size_t)row*ldH + col] = v;
                    __nv_bfloat16 hh = __float2bfloat16(v);
                    Hh[(size_t)row*ldH + col] = hh;
                    Hl[(size_t)row*ldH + col] = __float2bfloat16(v - __bfloat162float(hh));
                }
            }
}

// ---------------- fused LSE: single-product, cp.async double-buffered ----------
__global__ __launch_bounds__(256, 2)
void lse_fused_kernel() {
    int z = blockIdx.x;
    int p = z >> 4, s = z & 15;
    int sel, bx, by;
    if (s == 0) {
        sel = 0; bx = p & 31; by = p >> 5;
    } else if (s <= 4) {
        int idx = p*4 + (s-1);
        if (idx >= 32*G0) return;
        sel = 1; bx = idx & 31; by = idx >> 5;
    } else {
        int idx = p*11 + (s-5);
        if (idx >= 32*G1) return;
        sel = 2; bx = idx & 31; by = idx >> 5;
    }

    const __nv_bfloat16 *Ahi, *Bhi;
    int K, Nvalid, G, cnt;
    const int* rowlist;
    float* pS;
    if (sel == 0)      { Ahi=g_Xhi;  K=NINP; Bhi=g_Whh;  Nvalid=NH;  G=GH; pS=g_psH; rowlist=nullptr; cnt=BB; }
    else if (sel == 1) { Ahi=g_H0h;  K=H0D;  Bhi=g_W20h; Nvalid=N0T; G=G0; pS=g_ps0; rowlist=g_idx0; cnt=g_n0; }
    else               { Ahi=g_H1h;  K=H1D;  Bhi=g_W21h; Nvalid=N1T; G=G1; pS=g_ps1; rowlist=g_idx1; cnt=g_n1; }

    int rbase = bx * 128;
    if (rbase >= cnt) return;

    extern __shared__ __align__(16) char sm[];
    uint32_t sbase = smem_u32(sm);
    int tid = threadIdx.x, wid = tid >> 5, lane = tid & 31;
    int wm = wid >> 2, wn = wid & 3;

    float acc[4][4][4];
#pragma unroll
    for (int mt = 0; mt < 4; mt++)
#pragma unroll
        for (int nt = 0; nt < 4; nt++)
#pragma unroll
            for (int c = 0; c < 4; c++) acc[mt][nt][c] = 0.f;

    // per-thread load slots (4 x 16B per matrix per chunk)
    int lrow[4]; uint32_t lso[4]; int lu[4];
#pragma unroll
    for (int e = 0; e < 4; e++) {
        int f = e*256 + tid, row = f >> 3, u = f & 7;
        int grow = rbase + row; if (grow >= cnt) grow = cnt - 1;
        lrow[e] = rowlist ? rowlist[grow] : grow;
        lso[e] = (uint32_t)((row*RS + u*8) * 2);
        lu[e] = (by*128 + row);
    }
    int nchunks = K >> 6;

    // stage 0 loads
    {
        int k0 = 0;
#pragma unroll
        for (int e = 0; e < 4; e++) {
            int u8 = (lso[e]/2) % RS;           // u*8 recovered
            CP_ASYNC16(sbase + lso[e],           Ahi + (size_t)lrow[e]*K + k0 + u8);
            CP_ASYNC16(sbase + TILE_B + lso[e],  Bhi + (size_t)lu[e]*K + k0 + u8);
        }
        CP_COMMIT();
    }

    uint32_t aoff = (uint32_t)(((wm*64 + (lane & 15)) * RS + (lane >> 4) * 8) * 2);
    uint32_t boff = (uint32_t)(((wn*32 + (lane & 7)) * RS + ((lane >> 3) & 1) * 8) * 2);

    for (int ch = 0; ch < nchunks; ch++) {
        if (ch + 1 < nchunks) {
            int k0 = (ch + 1) << 6;
            uint32_t st = ((ch + 1) & 1) * STAGE_B;
#pragma unroll
            for (int e = 0; e < 4; e++) {
                int u8 = (lso[e]/2) % RS;
                CP_ASYNC16(sbase + st + lso[e],          Ahi + (size_t)lrow[e]*K + k0 + u8);
                CP_ASYNC16(sbase + st + TILE_B + lso[e], Bhi + (size_t)lu[e]*K + k0 + u8);
            }
            CP_COMMIT();
            asm volatile("cp.async.wait_group 1;" ::: "memory");
        } else {
            asm volatile("cp.async.wait_group 0;" ::: "memory");
        }
        __syncthreads();
        uint32_t sb = sbase + (ch & 1) * STAGE_B;
        uint32_t aA = sb + aoff, aB = sb + TILE_B + boff;
#pragma unroll
        for (int ks = 0; ks < 4; ks++) {
            uint32_t ah[4][4];
#pragma unroll
            for (int mt = 0; mt < 4; mt++)
                ldmx4(ah[mt], aA + (uint32_t)(mt*16*RS*2 + ks*32));
#pragma unroll
            for (int nt = 0; nt < 4; nt++) {
                uint32_t bh[2];
                ldmx2(bh, aB + (uint32_t)(nt*8*RS*2 + ks*32));
#pragma unroll
                for (int mt = 0; mt < 4; mt++)
                    mma16816(acc[mt][nt], ah[mt], bh);
            }
        }
        __syncthreads();
    }

    // epilogue: sum of 2^t (hybrid MUFU f16x2 + Schraudolph)
    int q = lane >> 2, r4 = lane & 3;
    float* sps = (float*)sm;            // [128][4]
    bool edge = (by == G - 1);
#pragma unroll
    for (int mt = 0; mt < 4; mt++) {
#pragma unroll
        for (int h = 0; h < 2; h++) {
            float v[8];
#pragma unroll
            for (int nt = 0; nt < 4; nt++)
#pragma unroll
                for (int c = 0; c < 2; c++) {
                    float t = acc[mt][nt][h*2 + c];
                    if (edge) {
                        int col = by*128 + wn*32 + nt*8 + r4*2 + c;
                        if (col >= Nvalid) t = -100.f;
                    }
                    v[nt*2 + c] = t;
                }
            uint32_t e0 = ex2_pair(v[0], v[1]);
            uint32_t e1 = ex2_pair(v[2], v[3]);
            uint32_t t2 = hadd2u(e0, e1);
            __half2 hh = *(__half2*)&t2;
            float sm_ = __low2float(hh) + __high2float(hh);
            float y4 = schr_exp2(v[4]);
            float y5 = schr_exp2(v[5]);
            float y6 = schr_exp2(v[6]);
            float y7 = schr_exp2(v[7]);
            float s8 = fmaf(SCHR_CORR, (y4 + y5) + (y6 + y7), sm_);
            s8 += __shfl_xor_sync(0xffffffffu, s8, 1);
            s8 += __shfl_xor_sync(0xffffffffu, s8, 2);
            if (r4 == 0) sps[(wm*64 + mt*16 + q + h*8)*4 + wn] = s8;
        }
    }
    __syncthreads();
    if (tid < 128) {
        float ssum = sps[tid*4 + 0] + sps[tid*4 + 1] + sps[tid*4 + 2] + sps[tid*4 + 3];
        int grow = rbase + tid;
        if (grow < cnt) {
            int orow = rowlist ? rowlist[grow] : grow;
            pS[(size_t)orow*G + by] = ssum;
        }
    }
}

// ---------------- combine + deterministic loss reduction ----------------
__global__ void combine_kernel(float* __restrict__ out) {
    __shared__ float red[256];
    int i = blockIdx.x * 256 + threadIdx.x;

    float s = 0.f;
    for (int g = 0; g < GH; g++) s += g_psH[(size_t)i*GH + g];
    float o = g_zh[i] - log2f(s);

    int cid = g_cid[i];
    if (cid == 1) {
        float s2 = 0.f;
        for (int g = 0; g < G0; g++) s2 += g_ps0[(size_t)i*G0 + g];
        o += g_z0[i] - log2f(s2);
    } else if (cid == 2) {
        float s2 = 0.f;
        for (int g = 0; g < G1; g++) s2 += g_ps1[(size_t)i*G1 + g];
        o += g_z1[i] - log2f(s2);
    }
    o *= LN2;
    out[i] = o;

    red[threadIdx.x] = o;
    __syncthreads();
    for (int st = 128; st > 0; st >>= 1) {
        if (threadIdx.x < st) red[threadIdx.x] += red[threadIdx.x + st];
        __syncthreads();
    }
    if (threadIdx.x == 0) g_blocksum[blockIdx.x] = red[0];
}

__global__ void finalize_kernel(float* __restrict__ out, int out_size) {
    float s = 0.f;
    for (int i = 0; i < 16; i++) s += g_blocksum[i];
    if (out_size > BB) out[BB] = -s / (float)BB;
}

// ---------------- launch ----------------
extern "C" void kernel_launch(void* const* d_in, const int* in_sizes, int n_in,
                              void* d_out, int out_size) {
    const float* X    = (const float*)d_in[0];
    const int*   tgt  = (const int*)d_in[1];
    const float* Wh   = (const float*)d_in[2];
    const float* W1_0 = (const float*)d_in[3];
    const float* W2_0 = (const float*)d_in[4];
    const float* W1_1 = (const float*)d_in[5];
    const float* W2_1 = (const float*)d_in[6];
    float* out = (float*)d_out;

    cudaFuncSetAttribute(hidden_kernel,    cudaFuncAttributeMaxDynamicSharedMemorySize, SMEM_HID);
    cudaFuncSetAttribute(lse_fused_kernel, cudaFuncAttributeMaxDynamicSharedMemorySize, SMEM_LSE);

    init_kernel<<<1, 1>>>();
    prep_kernel<<<BB/256, 256>>>(tgt);
    splitx_kernel<<<BB*NINP/256, 256>>>(X);

    tsplit_kernel<<<dim3(NHP/32, NINP/32), dim3(32,8)>>>(Wh,   NINP, NH,  NHP, 0, LOG2E);
    tsplit_kernel<<<dim3(H0D/32, NINP/32), dim3(32,8)>>>(W1_0, NINP, H0D, H0D, 1, 1.0f);
    tsplit_kernel<<<dim3(128/32, NINP/32), dim3(32,8)>>>(W1_1, NINP, H1D, 128, 2, 1.0f);
    tsplit_kernel<<<dim3(N0P/32, H0D/32),  dim3(32,8)>>>(W2_0, H0D,  N0T, N0P, 3, LOG2E);
    tsplit_kernel<<<dim3(N1P/32, H1D/32),  dim3(32,8)>>>(W2_1, H1D,  N1T, N1P, 4, LOG2E);

    hidden_kernel<<<dim3(BB/128, H0D/128), 256, SMEM_HID>>>(0);
    hidden_kernel<<<dim3(BB/128, 1),       256, SMEM_HID>>>(1);

    gatherdot_kernel<<<dim3(BB*32/256, 3), 256>>>(X);

    lse_fused_kernel<<<8192, 256, SMEM_LSE>>>();

    combine_kernel<<<BB/256, 256>>>(out);
    finalize_kernel<<<1, 1>>>(out, out_size);
}

// round 11
// speedup vs baseline: 4.4814x; 1.2850x over previous
#include <cuda_runtime.h>
#include <cuda_bf16.h>
#include <math.h>
#include <stdint.h>

// ---------------- problem constants ----------------
#define BB    4096
#define NINP  1024
#define C0    2000
#define C1    10000
#define NH    2002
#define N0T   8000
#define N1T   22000
#define H0D   256
#define H1D   64

#define NHP   2048
#define N0P   8064
#define N1P   22016
#define GH    (NHP/128)    // 16
#define G0    (N0P/128)    // 63
#define G1    (N1P/128)    // 172

#define LOG2E 1.4426950408889634f
#define LN2   0.6931471805599453f
#define SCHR_CORR 0.96090830f

#define RS    72
#define TILE_B (128*RS*2)      // 18432
#define OFF_AH 0
#define OFF_AL TILE_B
#define OFF_BH (2*TILE_B)
#define OFF_BL (3*TILE_B)
#define SMEM_HID (4*TILE_B)    // 73728
#define STAGE_B (2*TILE_B)     // 36864
#define SMEM_LSE (2*STAGE_B)   // 73728

// grid decode for lse launch: gatherdot occupies the first GD_BLKS blocks
#define GD_BLKS 1536           // 512 x 3

// ---------------- device scratch ----------------
__device__ int   g_n0, g_n1;
__device__ int   g_idx0[BB], g_idx1[BB];
__device__ int   g_cid[BB], g_gind[BB], g_t0[BB], g_t1[BB];
__device__ __nv_bfloat16 g_Xhi[BB*NINP],  g_Xlo[BB*NINP];
__device__ __nv_bfloat16 g_Whh[NHP*NINP], g_Whl[NHP*NINP];
__device__ __nv_bfloat16 g_W10h[H0D*NINP], g_W10l[H0D*NINP];
__device__ __nv_bfloat16 g_W11h[128*NINP], g_W11l[128*NINP];
__device__ __nv_bfloat16 g_W20h[N0P*H0D], g_W20l[N0P*H0D];
__device__ __nv_bfloat16 g_W21h[N1P*H1D], g_W21l[N1P*H1D];
__device__ float g_H0[BB*H0D]; __device__ __nv_bfloat16 g_H0h[BB*H0D], g_H0l[BB*H0D];
__device__ float g_H1[BB*H1D]; __device__ __nv_bfloat16 g_H1h[BB*H1D], g_H1l[BB*H1D];
__device__ float g_zh[BB], g_z0[BB], g_z1[BB];   // base-2 units
__device__ float g_psH[BB*GH];
__device__ float g_ps0[(size_t)BB*G0];
__device__ float g_ps1[(size_t)BB*G1];
__device__ float g_blocksum[16];

// ---------------- helpers ----------------
__device__ __forceinline__ uint32_t smem_u32(const void* p) {
    uint32_t a;
    asm("{ .reg .u64 t; cvta.to.shared.u64 t, %1; cvt.u32.u64 %0, t; }" : "=r"(a) : "l"(p));
    return a;
}
__device__ __forceinline__ void ldmx4(uint32_t* r, uint32_t addr) {
    asm volatile("ldmatrix.sync.aligned.m8n8.x4.shared.b16 {%0,%1,%2,%3}, [%4];"
        : "=r"(r[0]), "=r"(r[1]), "=r"(r[2]), "=r"(r[3]) : "r"(addr));
}
__device__ __forceinline__ void ldmx2(uint32_t* r, uint32_t addr) {
    asm volatile("ldmatrix.sync.aligned.m8n8.x2.shared.b16 {%0,%1}, [%2];"
        : "=r"(r[0]), "=r"(r[1]) : "r"(addr));
}
__device__ __forceinline__ void mma16816(float* c, const uint32_t* a, const uint32_t* b) {
    asm volatile("mma.sync.aligned.m16n8k16.row.col.f32.bf16.bf16.f32 "
        "{%0,%1,%2,%3}, {%4,%5,%6,%7}, {%8,%9}, {%0,%1,%2,%3};"
        : "+f"(c[0]), "+f"(c[1]), "+f"(c[2]), "+f"(c[3])
        : "r"(a[0]), "r"(a[1]), "r"(a[2]), "r"(a[3]), "r"(b[0]), "r"(b[1]));
}
__device__ __forceinline__ uint32_t ex2_pair(float a, float b) {
    uint32_t p;
    asm("cvt.rn.f16x2.f32 %0, %1, %2;" : "=r"(p) : "f"(b), "f"(a));
    asm("ex2.approx.f16x2 %0, %0;" : "+r"(p));
    return p;
}
__device__ __forceinline__ uint32_t hadd2u(uint32_t a, uint32_t b) {
    uint32_t d;
    asm("add.f16x2 %0, %1, %2;" : "=r"(d) : "r"(a), "r"(b));
    return d;
}
__device__ __forceinline__ float schr_exp2(float t) {
    float vv = fmaf(t, 32768.0f, 12582912.0f);
    return __uint_as_float((__float_as_uint(vv) << 8) + 0xFF800000u);
}
#define CP_ASYNC16(dst, src) \
    asm volatile("cp.async.cg.shared.global [%0], [%1], 16;" :: "r"(dst), "l"(src) : "memory")
#define CP_COMMIT() asm volatile("cp.async.commit_group;" ::: "memory")

// ---------------- init ----------------
__global__ void init_kernel() { g_n0 = 0; g_n1 = 0; }

// ---------------- fused prologue: prep + splitx + all tsplits ----------------
// block dim (32,8). grid decode:
//  [0,16)                prep
//  [16,16400)            splitx
//  [16400, ...)          tsplit segments (Wh, W1_0, W1_1, W2_0, W2_1)
__global__ void fusedprep_kernel(const float* __restrict__ X,
                                 const int* __restrict__ target,
                                 const float* __restrict__ Wh,
                                 const float* __restrict__ W10,
                                 const float* __restrict__ W20,
                                 const float* __restrict__ W11,
                                 const float* __restrict__ W21) {
    __shared__ float t[32][33];
    int tid = threadIdx.y * 32 + threadIdx.x;
    int z = blockIdx.x;

    if (z < 16) {                         // prep
        int i = z * 256 + tid;
        int tg = target[i];
        int cid = (tg >= C0) + (tg >= C1);
        g_cid[i]  = cid;
        g_gind[i] = (cid == 0) ? tg : (C0 + cid - 1);
        int a = tg - C0; a = a < 0 ? 0 : a; a = a > N0T-1 ? N0T-1 : a; g_t0[i] = a;
        int b = tg - C1; b = b < 0 ? 0 : b; b = b > N1T-1 ? N1T-1 : b; g_t1[i] = b;
        if (cid == 1)      g_idx0[atomicAdd(&g_n0, 1)] = i;
        else if (cid == 2) g_idx1[atomicAdd(&g_n1, 1)] = i;
        return;
    }
    z -= 16;
    if (z < BB*NINP/256) {                // splitx
        int i = z * 256 + tid;
        float v = X[i];
        __nv_bfloat16 h = __float2bfloat16(v);
        g_Xhi[i] = h;
        g_Xlo[i] = __float2bfloat16(v - __bfloat162float(h));
        return;
    }
    z -= BB*NINP/256;

    // tsplit segments
    const float* src; int R, C, Cpad, Cb; __nv_bfloat16 *dhi, *dlo; float scale;
    if (z < 2048)        { src=Wh;  R=NINP; C=NH;  Cpad=NHP; dhi=g_Whh;  dlo=g_Whl;  scale=LOG2E; Cb=64; }
    else if (z < 2304)   { z-=2048; src=W10; R=NINP; C=H0D; Cpad=H0D; dhi=g_W10h; dlo=g_W10l; scale=1.0f; Cb=8; }
    else if (z < 2432)   { z-=2304; src=W11; R=NINP; C=H1D; Cpad=128; dhi=g_W11h; dlo=g_W11l; scale=1.0f; Cb=4; }
    else if (z < 4448)   { z-=2432; src=W20; R=H0D;  C=N0T; Cpad=N0P; dhi=g_W20h; dlo=g_W20l; scale=LOG2E; Cb=252; }
    else                 { z-=4448; src=W21; R=H1D;  C=N1T; Cpad=N1P; dhi=g_W21h; dlo=g_W21l; scale=LOG2E; Cb=688; }
    int cb = (z % Cb) * 32, rb = (z / Cb) * 32;
#pragma unroll
    for (int e = 0; e < 4; e++) {
        int rr = rb + threadIdx.y + e*8, cc = cb + threadIdx.x;
        t[threadIdx.y + e*8][threadIdx.x] = (rr < R && cc < C) ? src[(size_t)rr*C + cc] : 0.f;
    }
    __syncthreads();
#pragma unroll
    for (int e = 0; e < 4; e++) {
        int n = cb + threadIdx.y + e*8, k = rb + threadIdx.x;
        if (n < Cpad && k < R) {
            float v = t[threadIdx.x][threadIdx.y + e*8] * scale;
            __nv_bfloat16 h = __float2bfloat16(v);
            dhi[(size_t)n*R + k] = h;
            dlo[(size_t)n*R + k] = __float2bfloat16(v - __bfloat162float(h));
        }
    }
}
#define FUSEDPREP_BLKS (16 + BB*NINP/256 + 2048 + 256 + 128 + 2016 + 1376)

// ---------------- hidden projections (both in one launch): 3-product mma ------
__global__ __launch_bounds__(256, 2)
void hidden_kernel() {
    int sel = (blockIdx.y == 2) ? 1 : 0;
    int by  = (blockIdx.y == 2) ? 0 : blockIdx.y;
    const __nv_bfloat16 *Ahi = g_Xhi, *Alo = g_Xlo, *Bhi, *Blo;
    int Nvalid, ldH; float* Hout; __nv_bfloat16 *Hh, *Hl;
    if (sel == 0) { Bhi=g_W10h; Blo=g_W10l; Nvalid=H0D; Hout=g_H0; Hh=g_H0h; Hl=g_H0l; ldH=H0D; }
    else          { Bhi=g_W11h; Blo=g_W11l; Nvalid=H1D; Hout=g_H1; Hh=g_H1h; Hl=g_H1l; ldH=H1D; }
    const int K = NINP;
    int rbase = blockIdx.x * 128;

    extern __shared__ __align__(16) char sm[];
    uint32_t sbase = smem_u32(sm);
    int tid = threadIdx.x, wid = tid >> 5, lane = tid & 31;
    int wm = wid >> 2, wn = wid & 3;

    float acc[4][4][4];
#pragma unroll
    for (int mt = 0; mt < 4; mt++)
#pragma unroll
        for (int nt = 0; nt < 4; nt++)
#pragma unroll
            for (int c = 0; c < 4; c++) acc[mt][nt][c] = 0.f;

    uint32_t aoff = (uint32_t)(((wm*64 + (lane & 15)) * RS + (lane >> 4) * 8) * 2);
    uint32_t boff = (uint32_t)(((wn*32 + (lane & 7)) * RS + ((lane >> 3) & 1) * 8) * 2);
    uint32_t aAH = sbase + OFF_AH + aoff, aAL = sbase + OFF_AL + aoff;
    uint32_t aBH = sbase + OFF_BH + boff, aBL = sbase + OFF_BL + boff;

    for (int ch = 0; ch < K/64; ch++) {
        int k0 = ch << 6;
#pragma unroll
        for (int e = 0; e < 4; e++) {
            int f = e*256 + tid, row = f >> 3, u = f & 7;
            size_t go = (size_t)(rbase + row) * K + k0 + u*8;
            uint32_t so = (uint32_t)((row*RS + u*8) * 2);
            *(uint4*)(sm + OFF_AH + so) = *(const uint4*)(Ahi + go);
            *(uint4*)(sm + OFF_AL + so) = *(const uint4*)(Alo + go);
            size_t gb = (size_t)(by*128 + row) * K + k0 + u*8;
            *(uint4*)(sm + OFF_BH + so) = *(const uint4*)(Bhi + gb);
            *(uint4*)(sm + OFF_BL + so) = *(const uint4*)(Blo + gb);
        }
        __syncthreads();
#pragma unroll
        for (int ks = 0; ks < 4; ks++) {
            uint32_t ah[4][4], al[4][4];
#pragma unroll
            for (int mt = 0; mt < 4; mt++) {
                uint32_t d = (uint32_t)(mt*16*RS*2 + ks*32);
                ldmx4(ah[mt], aAH + d);
                ldmx4(al[mt], aAL + d);
            }
#pragma unroll
            for (int nt = 0; nt < 4; nt++) {
                uint32_t d = (uint32_t)(nt*8*RS*2 + ks*32);
                uint32_t bh[2], bl[2];
                ldmx2(bh, aBH + d);
                ldmx2(bl, aBL + d);
#pragma unroll
                for (int mt = 0; mt < 4; mt++) {
                    mma16816(acc[mt][nt], ah[mt], bh);
                    mma16816(acc[mt][nt], ah[mt], bl);
                    mma16816(acc[mt][nt], al[mt], bh);
                }
            }
        }
        __syncthreads();
    }

    int q = lane >> 2, r4 = lane & 3;
#pragma unroll
    for (int mt = 0; mt < 4; mt++)
#pragma unroll
        for (int nt = 0; nt < 4; nt++)
#pragma unroll
            for (int c = 0; c < 4; c++) {
                int row = rbase + wm*64 + mt*16 + q + (c >> 1)*8;
                int col = by*128 + wn*32 + nt*8 + r4*2 + (c & 1);
                if (col < Nvalid) {
                    float v = acc[mt][nt][c];
                    Hout[(size_t)row*ldH + col] = v;
                    __nv_bfloat16 hh = __float2bfloat16(v);
                    Hh[(size_t)row*ldH + col] = hh;
                    Hl[(size_t)row*ldH + col] = __float2bfloat16(v - __bfloat162float(hh));
                }
            }
}

// ---------------- fused LSE + gatherdot launch -------------------------------
// blocks [0, GD_BLKS): gathered logits; blocks [GD_BLKS, +8192): interleaved LSE.
__global__ __launch_bounds__(256, 2)
void lse_fused_kernel(const float* __restrict__ X) {
    int zb = blockIdx.x;
    int tid = threadIdx.x, wid = tid >> 5, lane = tid & 31;

    if (zb < GD_BLKS) {
        // -------- gatherdot (exact hi+lo, base-2 units) --------
        int sel = zb / 512, bx = zb % 512;
        const float* A; const __nv_bfloat16 *Whi, *Wlo; const int* colidx; float* out; int K;
        if (sel == 0)      { A = X;    Whi = g_Whh;  Wlo = g_Whl;  colidx = g_gind; out = g_zh; K = NINP; }
        else if (sel == 1) { A = g_H0; Whi = g_W20h; Wlo = g_W20l; colidx = g_t0;   out = g_z0; K = H0D; }
        else               { A = g_H1; Whi = g_W21h; Wlo = g_W21l; colidx = g_t1;   out = g_z1; K = H1D; }
        int w = (bx * 256 + tid) >> 5;
        if (w >= BB) return;
        int c = colidx[w];
        float s = 0.f;
        for (int k = lane*2; k < K; k += 64) {
            float2 a = *(const float2*)&A[(size_t)w*K + k];
            __nv_bfloat162 h = *(const __nv_bfloat162*)&Whi[(size_t)c*K + k];
            __nv_bfloat162 l = *(const __nv_bfloat162*)&Wlo[(size_t)c*K + k];
            s += a.x * (__bfloat162float(h.x) + __bfloat162float(l.x));
            s += a.y * (__bfloat162float(h.y) + __bfloat162float(l.y));
        }
#pragma unroll
        for (int o = 16; o > 0; o >>= 1) s += __shfl_xor_sync(0xffffffffu, s, o);
        if (lane == 0) out[w] = s;
        return;
    }

    // -------- interleaved LSE --------
    int z = zb - GD_BLKS;
    int p = z >> 4, s = z & 15;
    int sel, bx, by;
    if (s == 0) {
        sel = 0; bx = p & 31; by = p >> 5;
    } else if (s <= 4) {
        int idx = p*4 + (s-1);
        if (idx >= 32*G0) return;
        sel = 1; bx = idx & 31; by = idx >> 5;
    } else {
        int idx = p*11 + (s-5);
        if (idx >= 32*G1) return;
        sel = 2; bx = idx & 31; by = idx >> 5;
    }

    const __nv_bfloat16 *Ahi, *Bhi;
    int K, Nvalid, G, cnt;
    const int* rowlist;
    float* pS;
    if (sel == 0)      { Ahi=g_Xhi;  K=NINP; Bhi=g_Whh;  Nvalid=NH;  G=GH; pS=g_psH; rowlist=nullptr; cnt=BB; }
    else if (sel == 1) { Ahi=g_H0h;  K=H0D;  Bhi=g_W20h; Nvalid=N0T; G=G0; pS=g_ps0; rowlist=g_idx0; cnt=g_n0; }
    else               { Ahi=g_H1h;  K=H1D;  Bhi=g_W21h; Nvalid=N1T; G=G1; pS=g_ps1; rowlist=g_idx1; cnt=g_n1; }

    int rbase = bx * 128;
    if (rbase >= cnt) return;

    extern __shared__ __align__(16) char sm[];
    uint32_t sbase = smem_u32(sm);
    int wm = wid >> 2, wn = wid & 3;

    float acc[4][4][4];
#pragma unroll
    for (int mt = 0; mt < 4; mt++)
#pragma unroll
        for (int nt = 0; nt < 4; nt++)
#pragma unroll
            for (int c = 0; c < 4; c++) acc[mt][nt][c] = 0.f;

    int lrow[4]; uint32_t lso[4]; int lu[4];
#pragma unroll
    for (int e = 0; e < 4; e++) {
        int f = e*256 + tid, row = f >> 3, u = f & 7;
        int grow = rbase + row; if (grow >= cnt) grow = cnt - 1;
        lrow[e] = rowlist ? rowlist[grow] : grow;
        lso[e] = (uint32_t)((row*RS + u*8) * 2);
        lu[e] = (by*128 + row);
    }
    int nchunks = K >> 6;

    {
#pragma unroll
        for (int e = 0; e < 4; e++) {
            int u8 = (lso[e]/2) % RS;
            CP_ASYNC16(sbase + lso[e],           Ahi + (size_t)lrow[e]*K + u8);
            CP_ASYNC16(sbase + TILE_B + lso[e],  Bhi + (size_t)lu[e]*K + u8);
        }
        CP_COMMIT();
    }

    uint32_t aoff  = (uint32_t)(((wm*64 + (lane & 15)) * RS + (lane >> 4) * 8) * 2);
    // B x4 addressing: n_off = (lane>>4)*8 + (lane&7); k_off = ((lane>>3)&1)*8
    uint32_t boff4 = (uint32_t)(((wn*32 + (lane & 7) + ((lane >> 4) << 3)) * RS + ((lane >> 3) & 1) * 8) * 2);

    for (int ch = 0; ch < nchunks; ch++) {
        if (ch + 1 < nchunks) {
            int k0 = (ch + 1) << 6;
            uint32_t st = ((ch + 1) & 1) * STAGE_B;
#pragma unroll
            for (int e = 0; e < 4; e++) {
                int u8 = (lso[e]/2) % RS;
                CP_ASYNC16(sbase + st + lso[e],          Ahi + (size_t)lrow[e]*K + k0 + u8);
                CP_ASYNC16(sbase + st + TILE_B + lso[e], Bhi + (size_t)lu[e]*K + k0 + u8);
            }
            CP_COMMIT();
            asm volatile("cp.async.wait_group 1;" ::: "memory");
        } else {
            asm volatile("cp.async.wait_group 0;" ::: "memory");
        }
        __syncthreads();
        uint32_t sb = sbase + (ch & 1) * STAGE_B;
        uint32_t aA = sb + aoff, aB4 = sb + TILE_B + boff4;
#pragma unroll
        for (int ks = 0; ks < 4; ks++) {
            uint32_t ah[4][4];
#pragma unroll
            for (int mt = 0; mt < 4; mt++)
                ldmx4(ah[mt], aA + (uint32_t)(mt*16*RS*2 + ks*32));
#pragma unroll
            for (int ntp = 0; ntp < 2; ntp++) {
                uint32_t bq[4];
                ldmx4(bq, aB4 + (uint32_t)(ntp*16*RS*2 + ks*32));
#pragma unroll
                for (int mt = 0; mt < 4; mt++) {
                    mma16816(acc[mt][ntp*2 + 0], ah[mt], bq);
                    mma16816(acc[mt][ntp*2 + 1], ah[mt], bq + 2);
                }
            }
        }
        __syncthreads();
    }

    // epilogue: sum of 2^t (hybrid MUFU f16x2 + Schraudolph)
    int q = lane >> 2, r4 = lane & 3;
    float* sps = (float*)sm;            // [128][4]
    bool edge = (by == G - 1);
#pragma unroll
    for (int mt = 0; mt < 4; mt++) {
#pragma unroll
        for (int h = 0; h < 2; h++) {
            float v[8];
#pragma unroll
            for (int nt = 0; nt < 4; nt++)
#pragma unroll
                for (int c = 0; c < 2; c++) {
                    float t = acc[mt][nt][h*2 + c];
                    if (edge) {
                        int col = by*128 + wn*32 + nt*8 + r4*2 + c;
                        if (col >= Nvalid) t = -100.f;
                    }
                    v[nt*2 + c] = t;
                }
            uint32_t e0 = ex2_pair(v[0], v[1]);
            uint32_t e1 = ex2_pair(v[2], v[3]);
            uint32_t t2 = hadd2u(e0, e1);
            __half2 hh = *(__half2*)&t2;
            float sm_ = __low2float(hh) + __high2float(hh);
            float y4 = schr_exp2(v[4]);
            float y5 = schr_exp2(v[5]);
            float y6 = schr_exp2(v[6]);
            float y7 = schr_exp2(v[7]);
            float s8 = fmaf(SCHR_CORR, (y4 + y5) + (y6 + y7), sm_);
            s8 += __shfl_xor_sync(0xffffffffu, s8, 1);
            s8 += __shfl_xor_sync(0xffffffffu, s8, 2);
            if (r4 == 0) sps[(wm*64 + mt*16 + q + h*8)*4 + wn] = s8;
        }
    }
    __syncthreads();
    if (tid < 128) {
        float ssum = sps[tid*4 + 0] + sps[tid*4 + 1] + sps[tid*4 + 2] + sps[tid*4 + 3];
        int grow = rbase + tid;
        if (grow < cnt) {
            int orow = rowlist ? rowlist[grow] : grow;
            pS[(size_t)orow*G + by] = ssum;
        }
    }
}

// ---------------- combine + deterministic loss reduction ----------------
__global__ void combine_kernel(float* __restrict__ out) {
    __shared__ float red[256];
    int i = blockIdx.x * 256 + threadIdx.x;

    float s = 0.f;
    for (int g = 0; g < GH; g++) s += g_psH[(size_t)i*GH + g];
    float o = g_zh[i] - log2f(s);

    int cid = g_cid[i];
    if (cid == 1) {
        float s2 = 0.f;
        for (int g = 0; g < G0; g++) s2 += g_ps0[(size_t)i*G0 + g];
        o += g_z0[i] - log2f(s2);
    } else if (cid == 2) {
        float s2 = 0.f;
        for (int g = 0; g < G1; g++) s2 += g_ps1[(size_t)i*G1 + g];
        o += g_z1[i] - log2f(s2);
    }
    o *= LN2;
    out[i] = o;

    red[threadIdx.x] = o;
    __syncthreads();
    for (int st = 128; st > 0; st >>= 1) {
        if (threadIdx.x < st) red[threadIdx.x] += red[threadIdx.x + st];
        __syncthreads();
    }
    if (threadIdx.x == 0) g_blocksum[blockIdx.x] = red[0];
}

__global__ void finalize_kernel(float* __restrict__ out, int out_size) {
    float s = 0.f;
    for (int i = 0; i < 16; i++) s += g_blocksum[i];
    if (out_size > BB) out[BB] = -s / (float)BB;
}

// ---------------- launch ----------------
extern "C" void kernel_launch(void* const* d_in, const int* in_sizes, int n_in,
                              void* d_out, int out_size) {
    const float* X    = (const float*)d_in[0];
    const int*   tgt  = (const int*)d_in[1];
    const float* Wh   = (const float*)d_in[2];
    const float* W1_0 = (const float*)d_in[3];
    const float* W2_0 = (const float*)d_in[4];
    const float* W1_1 = (const float*)d_in[5];
    const float* W2_1 = (const float*)d_in[6];
    float* out = (float*)d_out;

    cudaFuncSetAttribute(hidden_kernel,    cudaFuncAttributeMaxDynamicSharedMemorySize, SMEM_HID);
    cudaFuncSetAttribute(lse_fused_kernel, cudaFuncAttributeMaxDynamicSharedMemorySize, SMEM_LSE);

    init_kernel<<<1, 1>>>();
    fusedprep_kernel<<<FUSEDPREP_BLKS, dim3(32, 8)>>>(X, tgt, Wh, W1_0, W2_0, W1_1, W2_1);
    hidden_kernel<<<dim3(BB/128, 3), 256, SMEM_HID>>>();
    lse_fused_kernel<<<GD_BLKS + 8192, 256, SMEM_LSE>>>(X);
    combine_kernel<<<BB/256, 256>>>(out);
    finalize_kernel<<<1, 1>>>(out, out_size);
}

// round 12
// speedup vs baseline: 4.5345x; 1.0118x over previous
#include <cuda_runtime.h>
#include <cuda_bf16.h>
#include <math.h>
#include <stdint.h>

// ---------------- problem constants ----------------
#define BB    4096
#define NINP  1024
#define C0    2000
#define C1    10000
#define NH    2002
#define N0T   8000
#define N1T   22000
#define H0D   256
#define H1D   64

#define NHP   2048
#define N0P   8064
#define N1P   22016
#define GH    (NHP/128)    // 16
#define G0    (N0P/128)    // 63
#define G1    (N1P/128)    // 172

#define LOG2E 1.4426950408889634f
#define LN2   0.6931471805599453f
#define SCHR_CORR 0.96090830f

#define RS    72
#define TILE_B (128*RS*2)      // 18432
// hidden kernel (3 products)
#define OFF_AH 0
#define OFF_AL TILE_B
#define OFF_BH (2*TILE_B)
#define OFF_BL (3*TILE_B)
#define SMEM_HID (4*TILE_B)    // 73728
// LSE kernel layout:
//  head path: 2 stages of (A+B) ping-pong in [0, 4*TILE_B)
//  tail path: A cache [0, 4*TILE_B) (up to 4 chunks), B ping-pong at B_OFF
#define STAGE_B (2*TILE_B)     // 36864
#define B_OFF   (4*TILE_B)     // 73728
#define SPS_OFF (6*TILE_B)     // 110592
#define SMEM_LSE (6*TILE_B + 2048)  // 112640

#define GD_BLKS 1536           // 512 x 3 gatherdot blocks in front
#define LSE_PERIODS 172
#define LSE_BLKS (LSE_PERIODS*17)   // 2924

// ---------------- device scratch ----------------
__device__ int   g_n0, g_n1;
__device__ int   g_idx0[BB], g_idx1[BB];
__device__ int   g_cid[BB], g_gind[BB], g_t0[BB], g_t1[BB];
__device__ __nv_bfloat16 g_Xhi[BB*NINP],  g_Xlo[BB*NINP];
__device__ __nv_bfloat16 g_Whh[NHP*NINP], g_Whl[NHP*NINP];
__device__ __nv_bfloat16 g_W10h[H0D*NINP], g_W10l[H0D*NINP];
__device__ __nv_bfloat16 g_W11h[128*NINP], g_W11l[128*NINP];
__device__ __nv_bfloat16 g_W20h[N0P*H0D], g_W20l[N0P*H0D];
__device__ __nv_bfloat16 g_W21h[N1P*H1D], g_W21l[N1P*H1D];
__device__ float g_H0[BB*H0D]; __device__ __nv_bfloat16 g_H0h[BB*H0D], g_H0l[BB*H0D];
__device__ float g_H1[BB*H1D]; __device__ __nv_bfloat16 g_H1h[BB*H1D], g_H1l[BB*H1D];
__device__ float g_zh[BB], g_z0[BB], g_z1[BB];   // base-2 units
__device__ float g_psH[BB*GH];
__device__ float g_ps0[(size_t)BB*G0];
__device__ float g_ps1[(size_t)BB*G1];
__device__ float g_blocksum[16];

// ---------------- helpers ----------------
__device__ __forceinline__ uint32_t smem_u32(const void* p) {
    uint32_t a;
    asm("{ .reg .u64 t; cvta.to.shared.u64 t, %1; cvt.u32.u64 %0, t; }" : "=r"(a) : "l"(p));
    return a;
}
__device__ __forceinline__ void ldmx4(uint32_t* r, uint32_t addr) {
    asm volatile("ldmatrix.sync.aligned.m8n8.x4.shared.b16 {%0,%1,%2,%3}, [%4];"
        : "=r"(r[0]), "=r"(r[1]), "=r"(r[2]), "=r"(r[3]) : "r"(addr));
}
__device__ __forceinline__ void ldmx2(uint32_t* r, uint32_t addr) {
    asm volatile("ldmatrix.sync.aligned.m8n8.x2.shared.b16 {%0,%1}, [%2];"
        : "=r"(r[0]), "=r"(r[1]) : "r"(addr));
}
__device__ __forceinline__ void mma16816(float* c, const uint32_t* a, const uint32_t* b) {
    asm volatile("mma.sync.aligned.m16n8k16.row.col.f32.bf16.bf16.f32 "
        "{%0,%1,%2,%3}, {%4,%5,%6,%7}, {%8,%9}, {%0,%1,%2,%3};"
        : "+f"(c[0]), "+f"(c[1]), "+f"(c[2]), "+f"(c[3])
        : "r"(a[0]), "r"(a[1]), "r"(a[2]), "r"(a[3]), "r"(b[0]), "r"(b[1]));
}
__device__ __forceinline__ uint32_t ex2_pair(float a, float b) {
    uint32_t p;
    asm("cvt.rn.f16x2.f32 %0, %1, %2;" : "=r"(p) : "f"(b), "f"(a));
    asm("ex2.approx.f16x2 %0, %0;" : "+r"(p));
    return p;
}
__device__ __forceinline__ uint32_t hadd2u(uint32_t a, uint32_t b) {
    uint32_t d;
    asm("add.f16x2 %0, %1, %2;" : "=r"(d) : "r"(a), "r"(b));
    return d;
}
__device__ __forceinline__ float schr_exp2(float t) {
    float vv = fmaf(t, 32768.0f, 12582912.0f);
    return __uint_as_float((__float_as_uint(vv) << 8) + 0xFF800000u);
}
#define CP_ASYNC16(dst, src) \
    asm volatile("cp.async.cg.shared.global [%0], [%1], 16;" :: "r"(dst), "l"(src) : "memory")
#define CP_COMMIT() asm volatile("cp.async.commit_group;" ::: "memory")

// shared LSE epilogue: sum of 2^acc over 128 cols of tile cy, store partial sums.
__device__ __forceinline__ void lse_epilogue(
    float acc[4][4][4], int cy, int Nvalid, int G, int cnt, int rbase,
    const int* rowlist, float* pS, float* sps,
    int wm, int wn, int lane, int tid)
{
    int q = lane >> 2, r4 = lane & 3;
    bool edge = (cy == G - 1);
#pragma unroll
    for (int mt = 0; mt < 4; mt++) {
#pragma unroll
        for (int h = 0; h < 2; h++) {
            float v[8];
#pragma unroll
            for (int nt = 0; nt < 4; nt++)
#pragma unroll
                for (int c = 0; c < 2; c++) {
                    float t = acc[mt][nt][h*2 + c];
                    if (edge) {
                        int col = cy*128 + wn*32 + nt*8 + r4*2 + c;
                        if (col >= Nvalid) t = -100.f;
                    }
                    v[nt*2 + c] = t;
                }
            uint32_t e0 = ex2_pair(v[0], v[1]);
            uint32_t e1 = ex2_pair(v[2], v[3]);
            uint32_t t2 = hadd2u(e0, e1);
            __half2 hh = *(__half2*)&t2;
            float sm_ = __low2float(hh) + __high2float(hh);
            float y4 = schr_exp2(v[4]);
            float y5 = schr_exp2(v[5]);
            float y6 = schr_exp2(v[6]);
            float y7 = schr_exp2(v[7]);
            float s8 = fmaf(SCHR_CORR, (y4 + y5) + (y6 + y7), sm_);
            s8 += __shfl_xor_sync(0xffffffffu, s8, 1);
            s8 += __shfl_xor_sync(0xffffffffu, s8, 2);
            if (r4 == 0) sps[(wm*64 + mt*16 + q + h*8)*4 + wn] = s8;
        }
    }
    __syncthreads();
    if (tid < 128) {
        float ssum = sps[tid*4 + 0] + sps[tid*4 + 1] + sps[tid*4 + 2] + sps[tid*4 + 3];
        int grow = rbase + tid;
        if (grow < cnt) {
            int orow = rowlist ? rowlist[grow] : grow;
            pS[(size_t)orow*G + cy] = ssum;
        }
    }
    __syncthreads();
}

// ---------------- init ----------------
__global__ void init_kernel() { g_n0 = 0; g_n1 = 0; }

// ---------------- fused prologue: prep + splitx + all tsplits ----------------
__global__ void fusedprep_kernel(const float* __restrict__ X,
                                 const int* __restrict__ target,
                                 const float* __restrict__ Wh,
                                 const float* __restrict__ W10,
                                 const float* __restrict__ W20,
                                 const float* __restrict__ W11,
                                 const float* __restrict__ W21) {
    __shared__ float t[32][33];
    int tid = threadIdx.y * 32 + threadIdx.x;
    int z = blockIdx.x;

    if (z < 16) {                         // prep
        int i = z * 256 + tid;
        int tg = target[i];
        int cid = (tg >= C0) + (tg >= C1);
        g_cid[i]  = cid;
        g_gind[i] = (cid == 0) ? tg : (C0 + cid - 1);
        int a = tg - C0; a = a < 0 ? 0 : a; a = a > N0T-1 ? N0T-1 : a; g_t0[i] = a;
        int b = tg - C1; b = b < 0 ? 0 : b; b = b > N1T-1 ? N1T-1 : b; g_t1[i] = b;
        if (cid == 1)      g_idx0[atomicAdd(&g_n0, 1)] = i;
        else if (cid == 2) g_idx1[atomicAdd(&g_n1, 1)] = i;
        return;
    }
    z -= 16;
    if (z < BB*NINP/256) {                // splitx
        int i = z * 256 + tid;
        float v = X[i];
        __nv_bfloat16 h = __float2bfloat16(v);
        g_Xhi[i] = h;
        g_Xlo[i] = __float2bfloat16(v - __bfloat162float(h));
        return;
    }
    z -= BB*NINP/256;

    const float* src; int R, C, Cpad, Cb; __nv_bfloat16 *dhi, *dlo; float scale;
    if (z < 2048)        { src=Wh;  R=NINP; C=NH;  Cpad=NHP; dhi=g_Whh;  dlo=g_Whl;  scale=LOG2E; Cb=64; }
    else if (z < 2304)   { z-=2048; src=W10; R=NINP; C=H0D; Cpad=H0D; dhi=g_W10h; dlo=g_W10l; scale=1.0f; Cb=8; }
    else if (z < 2432)   { z-=2304; src=W11; R=NINP; C=H1D; Cpad=128; dhi=g_W11h; dlo=g_W11l; scale=1.0f; Cb=4; }
    else if (z < 4448)   { z-=2432; src=W20; R=H0D;  C=N0T; Cpad=N0P; dhi=g_W20h; dlo=g_W20l; scale=LOG2E; Cb=252; }
    else                 { z-=4448; src=W21; R=H1D;  C=N1T; Cpad=N1P; dhi=g_W21h; dlo=g_W21l; scale=LOG2E; Cb=688; }
    int cb = (z % Cb) * 32, rb = (z / Cb) * 32;
#pragma unroll
    for (int e = 0; e < 4; e++) {
        int rr = rb + threadIdx.y + e*8, cc = cb + threadIdx.x;
        t[threadIdx.y + e*8][threadIdx.x] = (rr < R && cc < C) ? src[(size_t)rr*C + cc] : 0.f;
    }
    __syncthreads();
#pragma unroll
    for (int e = 0; e < 4; e++) {
        int n = cb + threadIdx.y + e*8, k = rb + threadIdx.x;
        if (n < Cpad && k < R) {
            float v = t[threadIdx.x][threadIdx.y + e*8] * scale;
            __nv_bfloat16 h = __float2bfloat16(v);
            dhi[(size_t)n*R + k] = h;
            dlo[(size_t)n*R + k] = __float2bfloat16(v - __bfloat162float(h));
        }
    }
}
#define FUSEDPREP_BLKS (16 + BB*NINP/256 + 2048 + 256 + 128 + 2016 + 1376)

// ---------------- hidden projections (both in one launch): 3-product mma ------
__global__ __launch_bounds__(256, 2)
void hidden_kernel() {
    int sel = (blockIdx.y == 2) ? 1 : 0;
    int by  = (blockIdx.y == 2) ? 0 : blockIdx.y;
    const __nv_bfloat16 *Ahi = g_Xhi, *Alo = g_Xlo, *Bhi, *Blo;
    int Nvalid, ldH; float* Hout; __nv_bfloat16 *Hh, *Hl;
    if (sel == 0) { Bhi=g_W10h; Blo=g_W10l; Nvalid=H0D; Hout=g_H0; Hh=g_H0h; Hl=g_H0l; ldH=H0D; }
    else          { Bhi=g_W11h; Blo=g_W11l; Nvalid=H1D; Hout=g_H1; Hh=g_H1h; Hl=g_H1l; ldH=H1D; }
    const int K = NINP;
    int rbase = blockIdx.x * 128;

    extern __shared__ __align__(16) char sm[];
    uint32_t sbase = smem_u32(sm);
    int tid = threadIdx.x, wid = tid >> 5, lane = tid & 31;
    int wm = wid >> 2, wn = wid & 3;

    float acc[4][4][4];
#pragma unroll
    for (int mt = 0; mt < 4; mt++)
#pragma unroll
        for (int nt = 0; nt < 4; nt++)
#pragma unroll
            for (int c = 0; c < 4; c++) acc[mt][nt][c] = 0.f;

    uint32_t aoff = (uint32_t)(((wm*64 + (lane & 15)) * RS + (lane >> 4) * 8) * 2);
    uint32_t boff = (uint32_t)(((wn*32 + (lane & 7)) * RS + ((lane >> 3) & 1) * 8) * 2);
    uint32_t aAH = sbase + OFF_AH + aoff, aAL = sbase + OFF_AL + aoff;
    uint32_t aBH = sbase + OFF_BH + boff, aBL = sbase + OFF_BL + boff;

    for (int ch = 0; ch < K/64; ch++) {
        int k0 = ch << 6;
#pragma unroll
        for (int e = 0; e < 4; e++) {
            int f = e*256 + tid, row = f >> 3, u = f & 7;
            size_t go = (size_t)(rbase + row) * K + k0 + u*8;
            uint32_t so = (uint32_t)((row*RS + u*8) * 2);
            *(uint4*)(sm + OFF_AH + so) = *(const uint4*)(Ahi + go);
            *(uint4*)(sm + OFF_AL + so) = *(const uint4*)(Alo + go);
            size_t gb = (size_t)(by*128 + row) * K + k0 + u*8;
            *(uint4*)(sm + OFF_BH + so) = *(const uint4*)(Bhi + gb);
            *(uint4*)(sm + OFF_BL + so) = *(const uint4*)(Blo + gb);
        }
        __syncthreads();
#pragma unroll
        for (int ks = 0; ks < 4; ks++) {
            uint32_t ah[4][4], al[4][4];
#pragma unroll
            for (int mt = 0; mt < 4; mt++) {
                uint32_t d = (uint32_t)(mt*16*RS*2 + ks*32);
                ldmx4(ah[mt], aAH + d);
                ldmx4(al[mt], aAL + d);
            }
#pragma unroll
            for (int nt = 0; nt < 4; nt++) {
                uint32_t d = (uint32_t)(nt*8*RS*2 + ks*32);
                uint32_t bh[2], bl[2];
                ldmx2(bh, aBH + d);
                ldmx2(bl, aBL + d);
#pragma unroll
                for (int mt = 0; mt < 4; mt++) {
                    mma16816(acc[mt][nt], ah[mt], bh);
                    mma16816(acc[mt][nt], ah[mt], bl);
                    mma16816(acc[mt][nt], al[mt], bh);
                }
            }
        }
        __syncthreads();
    }

    int q = lane >> 2, r4 = lane & 3;
#pragma unroll
    for (int mt = 0; mt < 4; mt++)
#pragma unroll
        for (int nt = 0; nt < 4; nt++)
#pragma unroll
            for (int c = 0; c < 4; c++) {
                int row = rbase + wm*64 + mt*16 + q + (c >> 1)*8;
                int col = by*128 + wn*32 + nt*8 + r4*2 + (c & 1);
                if (col < Nvalid) {
                    float v = acc[mt][nt][c];
                    Hout[(size_t)row*ldH + col] = v;
                    __nv_bfloat16 hh = __float2bfloat16(v);
                    Hh[(size_t)row*ldH + col] = hh;
                    Hl[(size_t)row*ldH + col] = __float2bfloat16(v - __bfloat162float(hh));
                }
            }
}

// ---------------- fused LSE + gatherdot launch -------------------------------
// blocks [0, GD_BLKS): gatherdot.
// blocks [GD_BLKS, +LSE_BLKS): period-17 decode -> 3 head / 6 tail0 / 8 tail1.
// head: K=1024 streamed A+B 2-stage pipeline (T=1 col tile).
// tails: A cached in smem (whole K), B streamed over T col tiles (tail0 T=2, tail1 T=4).
__global__ __launch_bounds__(256, 2)
void lse_fused_kernel(const float* __restrict__ X) {
    int zb = blockIdx.x;
    int tid = threadIdx.x, wid = tid >> 5, lane = tid & 31;

    if (zb < GD_BLKS) {
        int sel = zb / 512, bx = zb % 512;
        const float* A; const __nv_bfloat16 *Whi, *Wlo; const int* colidx; float* out; int K;
        if (sel == 0)      { A = X;    Whi = g_Whh;  Wlo = g_Whl;  colidx = g_gind; out = g_zh; K = NINP; }
        else if (sel == 1) { A = g_H0; Whi = g_W20h; Wlo = g_W20l; colidx = g_t0;   out = g_z0; K = H0D; }
        else               { A = g_H1; Whi = g_W21h; Wlo = g_W21l; colidx = g_t1;   out = g_z1; K = H1D; }
        int w = (bx * 256 + tid) >> 5;
        if (w >= BB) return;
        int c = colidx[w];
        float s = 0.f;
        for (int k = lane*2; k < K; k += 64) {
            float2 a = *(const float2*)&A[(size_t)w*K + k];
            __nv_bfloat162 h = *(const __nv_bfloat162*)&Whi[(size_t)c*K + k];
            __nv_bfloat162 l = *(const __nv_bfloat162*)&Wlo[(size_t)c*K + k];
            s += a.x * (__bfloat162float(h.x) + __bfloat162float(l.x));
            s += a.y * (__bfloat162float(h.y) + __bfloat162float(l.y));
        }
#pragma unroll
        for (int o = 16; o > 0; o >>= 1) s += __shfl_xor_sync(0xffffffffu, s, o);
        if (lane == 0) out[w] = s;
        return;
    }

    // -------- LSE decode --------
    int z = zb - GD_BLKS;
    int p = z / 17, i = z % 17;
    int sel, bx, by0;
    if (i < 3) {
        int idx = p*3 + i; if (idx >= 512) return;
        sel = 0; bx = idx & 31; by0 = idx >> 5;
    } else if (i < 9) {
        int idx = p*6 + (i - 3); if (idx >= 1024) return;
        sel = 1; bx = idx & 31; by0 = (idx >> 5) * 2;
    } else {
        int idx = p*8 + (i - 9); if (idx >= 1376) return;
        sel = 2; bx = idx & 31; by0 = (idx >> 5) * 4;
    }

    const __nv_bfloat16 *Ahi, *Bhi;
    int K, Nvalid, G, cnt;
    const int* rowlist;
    float* pS;
    if (sel == 0)      { Ahi=g_Xhi;  K=NINP; Bhi=g_Whh;  Nvalid=NH;  G=GH; pS=g_psH; rowlist=nullptr; cnt=BB; }
    else if (sel == 1) { Ahi=g_H0h;  K=H0D;  Bhi=g_W20h; Nvalid=N0T; G=G0; pS=g_ps0; rowlist=g_idx0; cnt=g_n0; }
    else               { Ahi=g_H1h;  K=H1D;  Bhi=g_W21h; Nvalid=N1T; G=G1; pS=g_ps1; rowlist=g_idx1; cnt=g_n1; }

    int rbase = bx * 128;
    if (rbase >= cnt) return;

    extern __shared__ __align__(16) char sm[];
    uint32_t sbase = smem_u32(sm);
    int wm = wid >> 2, wn = wid & 3;
    float* sps = (float*)(sm + SPS_OFF);

    float acc[4][4][4];
#pragma unroll
    for (int mt = 0; mt < 4; mt++)
#pragma unroll
        for (int nt = 0; nt < 4; nt++)
#pragma unroll
            for (int c = 0; c < 4; c++) acc[mt][nt][c] = 0.f;

    // per-thread load slots
    int lrow[4], brow[4], u8[4]; uint32_t so[4];
#pragma unroll
    for (int e = 0; e < 4; e++) {
        int f = e*256 + tid, row = f >> 3, u = f & 7;
        int grow = rbase + row; if (grow >= cnt) grow = cnt - 1;
        lrow[e] = rowlist ? rowlist[grow] : grow;
        brow[e] = row;
        u8[e] = u*8;
        so[e] = (uint32_t)((row*RS + u*8) * 2);
    }

    uint32_t aoff  = (uint32_t)(((wm*64 + (lane & 15)) * RS + (lane >> 4) * 8) * 2);
    uint32_t boff4 = (uint32_t)(((wn*32 + (lane & 7) + ((lane >> 4) << 3)) * RS + ((lane >> 3) & 1) * 8) * 2);

    if (sel == 0) {
        // -------- head: streamed A+B 2-stage pipeline --------
        int by = by0;
        int nchunks = K >> 6;
#pragma unroll
        for (int e = 0; e < 4; e++) {
            CP_ASYNC16(sbase + so[e],           Ahi + (size_t)lrow[e]*K + u8[e]);
            CP_ASYNC16(sbase + TILE_B + so[e],  Bhi + ((size_t)(by*128) + brow[e])*K + u8[e]);
        }
        CP_COMMIT();
        for (int ch = 0; ch < nchunks; ch++) {
            if (ch + 1 < nchunks) {
                int k0 = (ch + 1) << 6;
                uint32_t st = ((ch + 1) & 1) * STAGE_B;
#pragma unroll
                for (int e = 0; e < 4; e++) {
                    CP_ASYNC16(sbase + st + so[e],          Ahi + (size_t)lrow[e]*K + k0 + u8[e]);
                    CP_ASYNC16(sbase + st + TILE_B + so[e], Bhi + ((size_t)(by*128) + brow[e])*K + k0 + u8[e]);
                }
                CP_COMMIT();
                asm volatile("cp.async.wait_group 1;" ::: "memory");
            } else {
                asm volatile("cp.async.wait_group 0;" ::: "memory");
            }
            __syncthreads();
            uint32_t sb = sbase + (ch & 1) * STAGE_B;
            uint32_t aA = sb + aoff, aB4 = sb + TILE_B + boff4;
#pragma unroll
            for (int ks = 0; ks < 4; ks++) {
                uint32_t ah[4][4];
#pragma unroll
                for (int mt = 0; mt < 4; mt++)
                    ldmx4(ah[mt], aA + (uint32_t)(mt*16*RS*2 + ks*32));
#pragma unroll
                for (int ntp = 0; ntp < 2; ntp++) {
                    uint32_t bq[4];
                    ldmx4(bq, aB4 + (uint32_t)(ntp*16*RS*2 + ks*32));
#pragma unroll
                    for (int mt = 0; mt < 4; mt++) {
                        mma16816(acc[mt][ntp*2 + 0], ah[mt], bq);
                        mma16816(acc[mt][ntp*2 + 1], ah[mt], bq + 2);
                    }
                }
            }
            __syncthreads();
        }
        lse_epilogue(acc, by, Nvalid, G, cnt, rbase, rowlist, pS, sps, wm, wn, lane, tid);
        return;
    }

    // -------- tails: A cached, B streamed over T col tiles --------
    int nch = K >> 6;                       // 4 (tail0) or 1 (tail1)
    int lognch = (sel == 1) ? 2 : 0;
    int T = (sel == 1) ? 2 : 4;
    int iters = T << lognch;                // 8 or 4

    // load full A (all chunks) + B iter 0 in group 0
    for (int ch = 0; ch < nch; ch++) {
#pragma unroll
        for (int e = 0; e < 4; e++)
            CP_ASYNC16(sbase + ch*TILE_B + so[e], Ahi + (size_t)lrow[e]*K + ch*64 + u8[e]);
    }
    {
        int cy0 = by0; if (cy0 > G - 1) cy0 = G - 1;
#pragma unroll
        for (int e = 0; e < 4; e++)
            CP_ASYNC16(sbase + B_OFF + so[e], Bhi + ((size_t)(cy0*128) + brow[e])*K + u8[e]);
        CP_COMMIT();
    }

    for (int it = 0; it < iters; it++) {
        if (it + 1 < iters) {
            int nt = it + 1;
            int t2 = nt >> lognch, ch2 = nt & (nch - 1);
            int cy2 = by0 + t2; if (cy2 > G - 1) cy2 = G - 1;
            uint32_t bb = B_OFF + ((nt & 1) ? TILE_B : 0u);
#pragma unroll
            for (int e = 0; e < 4; e++)
                CP_ASYNC16(sbase + bb + so[e], Bhi + ((size_t)(cy2*128) + brow[e])*K + ch2*64 + u8[e]);
            CP_COMMIT();
            asm volatile("cp.async.wait_group 1;" ::: "memory");
        } else {
            asm volatile("cp.async.wait_group 0;" ::: "memory");
        }
        __syncthreads();
        int ach = it & (nch - 1);
        uint32_t aA  = sbase + ach*TILE_B + aoff;
        uint32_t aB4 = sbase + B_OFF + ((it & 1) ? TILE_B : 0u) + boff4;
#pragma unroll
        for (int ks = 0; ks < 4; ks++) {
            uint32_t ah[4][4];
#pragma unroll
            for (int mt = 0; mt < 4; mt++)
                ldmx4(ah[mt], aA + (uint32_t)(mt*16*RS*2 + ks*32));
#pragma unroll
            for (int ntp = 0; ntp < 2; ntp++) {
                uint32_t bq[4];
                ldmx4(bq, aB4 + (uint32_t)(ntp*16*RS*2 + ks*32));
#pragma unroll
                for (int mt = 0; mt < 4; mt++) {
                    mma16816(acc[mt][ntp*2 + 0], ah[mt], bq);
                    mma16816(acc[mt][ntp*2 + 1], ah[mt], bq + 2);
                }
            }
        }
        __syncthreads();
        if (ach == nch - 1) {
            int cy = by0 + (it >> lognch);
            if (cy < G)
                lse_epilogue(acc, cy, Nvalid, G, cnt, rbase, rowlist, pS, sps, wm, wn, lane, tid);
#pragma unroll
            for (int mt = 0; mt < 4; mt++)
#pragma unroll
                for (int nt2 = 0; nt2 < 4; nt2++)
#pragma unroll
                    for (int c = 0; c < 4; c++) acc[mt][nt2][c] = 0.f;
        }
    }
}

// ---------------- combine + deterministic loss reduction ----------------
__global__ void combine_kernel(float* __restrict__ out) {
    __shared__ float red[256];
    int i = blockIdx.x * 256 + threadIdx.x;

    float s = 0.f;
    for (int g = 0; g < GH; g++) s += g_psH[(size_t)i*GH + g];
    float o = g_zh[i] - log2f(s);

    int cid = g_cid[i];
    if (cid == 1) {
        float s2 = 0.f;
        for (int g = 0; g < G0; g++) s2 += g_ps0[(size_t)i*G0 + g];
        o += g_z0[i] - log2f(s2);
    } else if (cid == 2) {
        float s2 = 0.f;
        for (int g = 0; g < G1; g++) s2 += g_ps1[(size_t)i*G1 + g];
        o += g_z1[i] - log2f(s2);
    }
    o *= LN2;
    out[i] = o;

    red[threadIdx.x] = o;
    __syncthreads();
    for (int st = 128; st > 0; st >>= 1) {
        if (threadIdx.x < st) red[threadIdx.x] += red[threadIdx.x + st];
        __syncthreads();
    }
    if (threadIdx.x == 0) g_blocksum[blockIdx.x] = red[0];
}

__global__ void finalize_kernel(float* __restrict__ out, int out_size) {
    float s = 0.f;
    for (int i = 0; i < 16; i++) s += g_blocksum[i];
    if (out_size > BB) out[BB] = -s / (float)BB;
}

// ---------------- launch ----------------
extern "C" void kernel_launch(void* const* d_in, const int* in_sizes, int n_in,
                              void* d_out, int out_size) {
    const float* X    = (const float*)d_in[0];
    const int*   tgt  = (const int*)d_in[1];
    const float* Wh   = (const float*)d_in[2];
    const float* W1_0 = (const float*)d_in[3];
    const float* W2_0 = (const float*)d_in[4];
    const float* W1_1 = (const float*)d_in[5];
    const float* W2_1 = (const float*)d_in[6];
    float* out = (float*)d_out;

    cudaFuncSetAttribute(hidden_kernel,    cudaFuncAttributeMaxDynamicSharedMemorySize, SMEM_HID);
    cudaFuncSetAttribute(lse_fused_kernel, cudaFuncAttributeMaxDynamicSharedMemorySize, SMEM_LSE);

    init_kernel<<<1, 1>>>();
    fusedprep_kernel<<<FUSEDPREP_BLKS, dim3(32, 8)>>>(X, tgt, Wh, W1_0, W2_0, W1_1, W2_1);
    hidden_kernel<<<dim3(BB/128, 3), 256, SMEM_HID>>>();
    lse_fused_kernel<<<GD_BLKS + LSE_BLKS, 256, SMEM_LSE>>>(X);
    combine_kernel<<<BB/256, 256>>>(out);
    finalize_kernel<<<1, 1>>>(out, out_size);
}

// round 14
// speedup vs baseline: 4.7719x; 1.0523x over previous
#include <cuda_runtime.h>
#include <cuda_fp16.h>
#include <math.h>
#include <stdint.h>

// ---------------- problem constants ----------------
#define BB    4096
#define NINP  1024
#define C0    2000
#define C1    10000
#define NH    2002
#define N0T   8000
#define N1T   22000
#define H0D   256
#define H1D   64

#define NHP   2048
#define N0P   8064
#define N1P   22016
#define GH    (NHP/128)    // 16
#define G0    (N0P/128)    // 63
#define G1    (N1P/128)    // 172

#define LOG2E 1.4426950408889634f
#define LN2   0.6931471805599453f

#define RS    72
#define TILE_B (128*RS*2)      // 18432
// hidden kernel (3 products)
#define OFF_AH 0
#define OFF_AL TILE_B
#define OFF_BH (2*TILE_B)
#define OFF_BL (3*TILE_B)
#define SMEM_HID (4*TILE_B)    // 73728
// LSE: 2 stages x (A tile + B tile)
#define STAGE_B (2*TILE_B)     // 36864
#define SMEM_LSE (2*STAGE_B)   // 73728

#define GD_BLKS 1536
#define LSE_PERIODS 172
#define LSE_BLKS (LSE_PERIODS*17)

// ---------------- device scratch ----------------
__device__ int   g_n0, g_n1;
__device__ int   g_idx0[BB], g_idx1[BB];
__device__ int   g_cid[BB], g_gind[BB], g_t0[BB], g_t1[BB];
__device__ __half g_Xhi[BB*NINP],  g_Xlo[BB*NINP];
__device__ __half g_Whh[NHP*NINP], g_Whl[NHP*NINP];
__device__ __half g_W10h[H0D*NINP], g_W10l[H0D*NINP];
__device__ __half g_W11h[128*NINP], g_W11l[128*NINP];
__device__ __half g_W20h[N0P*H0D], g_W20l[N0P*H0D];
__device__ __half g_W21h[N1P*H1D], g_W21l[N1P*H1D];
__device__ float g_H0[BB*H0D]; __device__ __half g_H0h[BB*H0D], g_H0l[BB*H0D];
__device__ float g_H1[BB*H1D]; __device__ __half g_H1h[BB*H1D], g_H1l[BB*H1D];
__device__ float g_zh[BB], g_z0[BB], g_z1[BB];   // base-2 units
__device__ float g_psH[BB*GH];
__device__ float g_ps0[(size_t)BB*G0];
__device__ float g_ps1[(size_t)BB*G1];
__device__ float g_blocksum[16];

// ---------------- helpers ----------------
__device__ __forceinline__ uint32_t smem_u32(const void* p) {
    uint32_t a;
    asm("{ .reg .u64 t; cvta.to.shared.u64 t, %1; cvt.u32.u64 %0, t; }" : "=r"(a) : "l"(p));
    return a;
}
__device__ __forceinline__ void ldmx4(uint32_t* r, uint32_t addr) {
    asm volatile("ldmatrix.sync.aligned.m8n8.x4.shared.b16 {%0,%1,%2,%3}, [%4];"
        : "=r"(r[0]), "=r"(r[1]), "=r"(r[2]), "=r"(r[3]) : "r"(addr));
}
__device__ __forceinline__ void ldmx2(uint32_t* r, uint32_t addr) {
    asm volatile("ldmatrix.sync.aligned.m8n8.x2.shared.b16 {%0,%1}, [%2];"
        : "=r"(r[0]), "=r"(r[1]) : "r"(addr));
}
// f32-accum f16-input mma (hidden projections)
__device__ __forceinline__ void mma16816_f32(float* c, const uint32_t* a, const uint32_t* b) {
    asm volatile("mma.sync.aligned.m16n8k16.row.col.f32.f16.f16.f32 "
        "{%0,%1,%2,%3}, {%4,%5,%6,%7}, {%8,%9}, {%0,%1,%2,%3};"
        : "+f"(c[0]), "+f"(c[1]), "+f"(c[2]), "+f"(c[3])
        : "r"(a[0]), "r"(a[1]), "r"(a[2]), "r"(a[3]), "r"(b[0]), "r"(b[1]));
}
// f16-accum mma (LSE): C = 2 packed f16x2 regs
__device__ __forceinline__ void mma16816_f16(uint32_t* c, const uint32_t* a, const uint32_t* b) {
    asm volatile("mma.sync.aligned.m16n8k16.row.col.f16.f16.f16.f16 "
        "{%0,%1}, {%2,%3,%4,%5}, {%6,%7}, {%0,%1};"
        : "+r"(c[0]), "+r"(c[1])
        : "r"(a[0]), "r"(a[1]), "r"(a[2]), "r"(a[3]), "r"(b[0]), "r"(b[1]));
}
__device__ __forceinline__ uint32_t ex2u(uint32_t t) {
    asm("ex2.approx.f16x2 %0, %0;" : "+r"(t));
    return t;
}
__device__ __forceinline__ uint32_t hadd2u(uint32_t a, uint32_t b) {
    uint32_t d;
    asm("add.f16x2 %0, %1, %2;" : "=r"(d) : "r"(a), "r"(b));
    return d;
}
#define CP_ASYNC16(dst, src) \
    asm volatile("cp.async.cg.shared.global [%0], [%1], 16;" :: "r"(dst), "l"(src) : "memory")
#define CP_COMMIT() asm volatile("cp.async.commit_group;" ::: "memory")

// ---------------- init ----------------
__global__ void init_kernel() { g_n0 = 0; g_n1 = 0; }

// ---------------- fused prologue: prep + splitx + all tsplits ----------------
__global__ void fusedprep_kernel(const float* __restrict__ X,
                                 const int* __restrict__ target,
                                 const float* __restrict__ Wh,
                                 const float* __restrict__ W10,
                                 const float* __restrict__ W20,
                                 const float* __restrict__ W11,
                                 const float* __restrict__ W21) {
    __shared__ float t[32][33];
    int tid = threadIdx.y * 32 + threadIdx.x;
    int z = blockIdx.x;

    if (z < 16) {                         // prep
        int i = z * 256 + tid;
        int tg = target[i];
        int cid = (tg >= C0) + (tg >= C1);
        g_cid[i]  = cid;
        g_gind[i] = (cid == 0) ? tg : (C0 + cid - 1);
        int a = tg - C0; a = a < 0 ? 0 : a; a = a > N0T-1 ? N0T-1 : a; g_t0[i] = a;
        int b = tg - C1; b = b < 0 ? 0 : b; b = b > N1T-1 ? N1T-1 : b; g_t1[i] = b;
        if (cid == 1)      g_idx0[atomicAdd(&g_n0, 1)] = i;
        else if (cid == 2) g_idx1[atomicAdd(&g_n1, 1)] = i;
        return;
    }
    z -= 16;
    if (z < BB*NINP/256) {                // splitx
        int i = z * 256 + tid;
        float v = X[i];
        __half h = __float2half(v);
        g_Xhi[i] = h;
        g_Xlo[i] = __float2half(v - __half2float(h));
        return;
    }
    z -= BB*NINP/256;

    const float* src; int R, C, Cpad, Cb; __half *dhi, *dlo; float scale;
    if (z < 2048)        { src=Wh;  R=NINP; C=NH;  Cpad=NHP; dhi=g_Whh;  dlo=g_Whl;  scale=LOG2E; Cb=64; }
    else if (z < 2304)   { z-=2048; src=W10; R=NINP; C=H0D; Cpad=H0D; dhi=g_W10h; dlo=g_W10l; scale=1.0f; Cb=8; }
    else if (z < 2432)   { z-=2304; src=W11; R=NINP; C=H1D; Cpad=128; dhi=g_W11h; dlo=g_W11l; scale=1.0f; Cb=4; }
    else if (z < 4448)   { z-=2432; src=W20; R=H0D;  C=N0T; Cpad=N0P; dhi=g_W20h; dlo=g_W20l; scale=LOG2E; Cb=252; }
    else                 { z-=4448; src=W21; R=H1D;  C=N1T; Cpad=N1P; dhi=g_W21h; dlo=g_W21l; scale=LOG2E; Cb=688; }
    int cb = (z % Cb) * 32, rb = (z / Cb) * 32;
#pragma unroll
    for (int e = 0; e < 4; e++) {
        int rr = rb + threadIdx.y + e*8, cc = cb + threadIdx.x;
        t[threadIdx.y + e*8][threadIdx.x] = (rr < R && cc < C) ? src[(size_t)rr*C + cc] : 0.f;
    }
    __syncthreads();
#pragma unroll
    for (int e = 0; e < 4; e++) {
        int n = cb + threadIdx.y + e*8, k = rb + threadIdx.x;
        if (n < Cpad && k < R) {
            float v = t[threadIdx.x][threadIdx.y + e*8] * scale;
            __half h = __float2half(v);
            dhi[(size_t)n*R + k] = h;
            dlo[(size_t)n*R + k] = __float2half(v - __half2float(h));
        }
    }
}
#define FUSEDPREP_BLKS (16 + BB*NINP/256 + 2048 + 256 + 128 + 2016 + 1376)

// ---------------- hidden projections: 3-product split-fp16 mma ----------------
__global__ __launch_bounds__(256, 2)
void hidden_kernel() {
    int sel = (blockIdx.y == 2) ? 1 : 0;
    int by  = (blockIdx.y == 2) ? 0 : blockIdx.y;
    const __half *Ahi = g_Xhi, *Alo = g_Xlo, *Bhi, *Blo;
    int Nvalid, ldH; float* Hout; __half *Hh, *Hl;
    if (sel == 0) { Bhi=g_W10h; Blo=g_W10l; Nvalid=H0D; Hout=g_H0; Hh=g_H0h; Hl=g_H0l; ldH=H0D; }
    else          { Bhi=g_W11h; Blo=g_W11l; Nvalid=H1D; Hout=g_H1; Hh=g_H1h; Hl=g_H1l; ldH=H1D; }
    const int K = NINP;
    int rbase = blockIdx.x * 128;

    extern __shared__ __align__(16) char sm[];
    uint32_t sbase = smem_u32(sm);
    int tid = threadIdx.x, wid = tid >> 5, lane = tid & 31;
    int wm = wid >> 2, wn = wid & 3;

    float acc[4][4][4];
#pragma unroll
    for (int mt = 0; mt < 4; mt++)
#pragma unroll
        for (int nt = 0; nt < 4; nt++)
#pragma unroll
            for (int c = 0; c < 4; c++) acc[mt][nt][c] = 0.f;

    uint32_t aoff = (uint32_t)(((wm*64 + (lane & 15)) * RS + (lane >> 4) * 8) * 2);
    uint32_t boff = (uint32_t)(((wn*32 + (lane & 7)) * RS + ((lane >> 3) & 1) * 8) * 2);
    uint32_t aAH = sbase + OFF_AH + aoff, aAL = sbase + OFF_AL + aoff;
    uint32_t aBH = sbase + OFF_BH + boff, aBL = sbase + OFF_BL + boff;

    for (int ch = 0; ch < K/64; ch++) {
        int k0 = ch << 6;
#pragma unroll
        for (int e = 0; e < 4; e++) {
            int f = e*256 + tid, row = f >> 3, u = f & 7;
            size_t go = (size_t)(rbase + row) * K + k0 + u*8;
            uint32_t so = (uint32_t)((row*RS + u*8) * 2);
            *(uint4*)(sm + OFF_AH + so) = *(const uint4*)(Ahi + go);
            *(uint4*)(sm + OFF_AL + so) = *(const uint4*)(Alo + go);
            size_t gb = (size_t)(by*128 + row) * K + k0 + u*8;
            *(uint4*)(sm + OFF_BH + so) = *(const uint4*)(Bhi + gb);
            *(uint4*)(sm + OFF_BL + so) = *(const uint4*)(Blo + gb);
        }
        __syncthreads();
#pragma unroll
        for (int ks = 0; ks < 4; ks++) {
            uint32_t ah[4][4], al[4][4];
#pragma unroll
            for (int mt = 0; mt < 4; mt++) {
                uint32_t d = (uint32_t)(mt*16*RS*2 + ks*32);
                ldmx4(ah[mt], aAH + d);
                ldmx4(al[mt], aAL + d);
            }
#pragma unroll
            for (int nt = 0; nt < 4; nt++) {
                uint32_t d = (uint32_t)(nt*8*RS*2 + ks*32);
                uint32_t bh[2], bl[2];
                ldmx2(bh, aBH + d);
                ldmx2(bl, aBL + d);
#pragma unroll
                for (int mt = 0; mt < 4; mt++) {
                    mma16816_f32(acc[mt][nt], ah[mt], bh);
                    mma16816_f32(acc[mt][nt], ah[mt], bl);
                    mma16816_f32(acc[mt][nt], al[mt], bh);
                }
            }
        }
        __syncthreads();
    }

    int q = lane >> 2, r4 = lane & 3;
#pragma unroll
    for (int mt = 0; mt < 4; mt++)
#pragma unroll
        for (int nt = 0; nt < 4; nt++)
#pragma unroll
            for (int c = 0; c < 4; c++) {
                int row = rbase + wm*64 + mt*16 + q + (c >> 1)*8;
                int col = by*128 + wn*32 + nt*8 + r4*2 + (c & 1);
                if (col < Nvalid) {
                    float v = acc[mt][nt][c];
                    Hout[(size_t)row*ldH + col] = v;
                    __half hh = __float2half(v);
                    Hh[(size_t)row*ldH + col] = hh;
                    Hl[(size_t)row*ldH + col] = __float2half(v - __half2float(hh));
                }
            }
}

// ---------------- fused LSE + gatherdot launch -------------------------------
// blocks [0, GD_BLKS): gatherdot. Then period-17 decode: 3 head / 6 tail0 / 8 tail1.
// Unified pipeline: per iteration stream (A chunk, B tile); single __syncthreads.
// Warp tile m16 x n128, f16 accumulators; epilogue fully warp-local.
__global__ __launch_bounds__(256, 3)
void lse_fused_kernel(const float* __restrict__ X) {
    int zb = blockIdx.x;
    int tid = threadIdx.x, wid = tid >> 5, lane = tid & 31;

    if (zb < GD_BLKS) {
        int sel = zb / 512, bx = zb % 512;
        const float* A; const __half *Whi, *Wlo; const int* colidx; float* out; int K;
        if (sel == 0)      { A = X;    Whi = g_Whh;  Wlo = g_Whl;  colidx = g_gind; out = g_zh; K = NINP; }
        else if (sel == 1) { A = g_H0; Whi = g_W20h; Wlo = g_W20l; colidx = g_t0;   out = g_z0; K = H0D; }
        else               { A = g_H1; Whi = g_W21h; Wlo = g_W21l; colidx = g_t1;   out = g_z1; K = H1D; }
        int w = (bx * 256 + tid) >> 5;
        if (w >= BB) return;
        int c = colidx[w];
        float s = 0.f;
        for (int k = lane*2; k < K; k += 64) {
            float2 a = *(const float2*)&A[(size_t)w*K + k];
            float2 h = __half22float2(*(const __half2*)&Whi[(size_t)c*K + k]);
            float2 l = __half22float2(*(const __half2*)&Wlo[(size_t)c*K + k]);
            s += a.x * (h.x + l.x);
            s += a.y * (h.y + l.y);
        }
#pragma unroll
        for (int o = 16; o > 0; o >>= 1) s += __shfl_xor_sync(0xffffffffu, s, o);
        if (lane == 0) out[w] = s;
        return;
    }

    // -------- LSE decode --------
    int z = zb - GD_BLKS;
    int p = z / 17, i = z % 17;
    int sel, bx, by0;
    if (i < 3) {
        int idx = p*3 + i; if (idx >= 512) return;
        sel = 0; bx = idx & 31; by0 = idx >> 5;
    } else if (i < 9) {
        int idx = p*6 + (i - 3); if (idx >= 1024) return;
        sel = 1; bx = idx & 31; by0 = (idx >> 5) * 2;
    } else {
        int idx = p*8 + (i - 9); if (idx >= 1376) return;
        sel = 2; bx = idx & 31; by0 = (idx >> 5) * 4;
    }

    const __half *Ahi, *Bhi;
    int K, Nvalid, G, cnt, T;
    const int* rowlist;
    float* pS;
    if (sel == 0)      { Ahi=g_Xhi;  K=NINP; Bhi=g_Whh;  Nvalid=NH;  G=GH; pS=g_psH; rowlist=nullptr; cnt=BB;   T=1; }
    else if (sel == 1) { Ahi=g_H0h;  K=H0D;  Bhi=g_W20h; Nvalid=N0T; G=G0; pS=g_ps0; rowlist=g_idx0; cnt=g_n0; T=2; }
    else               { Ahi=g_H1h;  K=H1D;  Bhi=g_W21h; Nvalid=N1T; G=G1; pS=g_ps1; rowlist=g_idx1; cnt=g_n1; T=4; }

    int rbase = bx * 128;
    if (rbase >= cnt) return;

    extern __shared__ __align__(16) char sm[];
    uint32_t sbase = smem_u32(sm);

    // f16 accumulators: 16 n8-tiles x 2 regs
    uint32_t facc[16][2];
#pragma unroll
    for (int nt = 0; nt < 16; nt++) { facc[nt][0] = 0; facc[nt][1] = 0; }

    // per-thread load slots
    int lrow[4], brow[4], u8[4]; uint32_t so[4];
#pragma unroll
    for (int e = 0; e < 4; e++) {
        int f = e*256 + tid, row = f >> 3, u = f & 7;
        int grow = rbase + row; if (grow >= cnt) grow = cnt - 1;
        lrow[e] = rowlist ? rowlist[grow] : grow;
        brow[e] = row;
        u8[e] = u*8;
        so[e] = (uint32_t)((row*RS + u*8) * 2);
    }

    int nch = K >> 6;
    int iters = nch * T;

    // prologue: load iter 0 (A chunk 0, B tile by0 chunk 0) into stage 0
    {
        int cy0 = by0 < G ? by0 : G - 1;
#pragma unroll
        for (int e = 0; e < 4; e++) {
            CP_ASYNC16(sbase + so[e],          Ahi + (size_t)lrow[e]*K + u8[e]);
            CP_ASYNC16(sbase + TILE_B + so[e], Bhi + ((size_t)(cy0*128) + brow[e])*K + u8[e]);
        }
        CP_COMMIT();
    }

    uint32_t aoff  = (uint32_t)(((wid*16 + (lane & 15)) * RS + (lane >> 4) * 8) * 2);
    uint32_t boff4 = (uint32_t)((((lane & 7) + ((lane >> 4) << 3)) * RS + ((lane >> 3) & 1) * 8) * 2);

    int q = lane >> 2, r4 = lane & 3;
    int ch = 0, cyi = 0;   // chunk index, col-tile index

    for (int it = 0; it < iters; it++) {
        asm volatile("cp.async.wait_group 0;" ::: "memory");
        __syncthreads();
        // issue loads for it+1 (post-sync: target stage was fully consumed at it-1)
        if (it + 1 < iters) {
            int ch2 = ch + 1, cy2i = cyi;
            if (ch2 == nch) { ch2 = 0; cy2i++; }
            int cy2 = by0 + cy2i; if (cy2 > G - 1) cy2 = G - 1;
            int k0 = ch2 << 6;
            uint32_t st = ((it + 1) & 1) * STAGE_B;
#pragma unroll
            for (int e = 0; e < 4; e++) {
                CP_ASYNC16(sbase + st + so[e],          Ahi + (size_t)lrow[e]*K + k0 + u8[e]);
                CP_ASYNC16(sbase + st + TILE_B + so[e], Bhi + ((size_t)(cy2*128) + brow[e])*K + k0 + u8[e]);
            }
            CP_COMMIT();
        }
        uint32_t sb = sbase + (it & 1) * STAGE_B;
        uint32_t aA = sb + aoff, aB4 = sb + TILE_B + boff4;
#pragma unroll
        for (int ks = 0; ks < 4; ks++) {
            uint32_t a4[4];
            ldmx4(a4, aA + (uint32_t)(ks*32));
#pragma unroll
            for (int ntp = 0; ntp < 8; ntp++) {
                uint32_t bq[4];
                ldmx4(bq, aB4 + (uint32_t)(ntp*16*RS*2 + ks*32));
                mma16816_f16(facc[ntp*2 + 0], a4, bq);
                mma16816_f16(facc[ntp*2 + 1], a4, bq + 2);
            }
        }

        // epilogue at last chunk of this col tile (warp-local; no syncs)
        if (ch == nch - 1) {
            int cy = by0 + cyi;
            if (cy < G) {
                bool edge = (cy == G - 1);
#pragma unroll
                for (int h = 0; h < 2; h++) {
                    uint32_t e16[16];
#pragma unroll
                    for (int nt = 0; nt < 16; nt++) {
                        uint32_t t = facc[nt][h];
                        if (edge) {
                            int col0 = cy*128 + nt*8 + r4*2;
                            if (col0 >= Nvalid) t = 0xFC00FC00u;   // -inf,-inf
                        }
                        e16[nt] = ex2u(t);
                    }
#pragma unroll
                    for (int j = 0; j < 8; j++) e16[j] = hadd2u(e16[j], e16[j + 8]);
#pragma unroll
                    for (int j = 0; j < 4; j++) e16[j] = hadd2u(e16[j], e16[j + 4]);
                    float s = 0.f;
#pragma unroll
                    for (int j = 0; j < 4; j++) {
                        float2 f2 = __half22float2(*(__half2*)&e16[j]);
                        s += f2.x + f2.y;
                    }
                    s += __shfl_xor_sync(0xffffffffu, s, 1);
                    s += __shfl_xor_sync(0xffffffffu, s, 2);
                    if (r4 == 0) {
                        int row = wid*16 + q + h*8;
                        int grow = rbase + row;
                        if (grow < cnt) {
                            int orow = rowlist ? rowlist[grow] : grow;
                            pS[(size_t)orow*G + cy] = s;
                        }
                    }
                }
            }
#pragma unroll
            for (int nt = 0; nt < 16; nt++) { facc[nt][0] = 0; facc[nt][1] = 0; }
            ch = 0; cyi++;
        } else {
            ch++;
        }
    }
}

// ---------------- combine + deterministic loss reduction ----------------
__global__ void combine_kernel(float* __restrict__ out) {
    __shared__ float red[256];
    int i = blockIdx.x * 256 + threadIdx.x;

    float s = 0.f;
    for (int g = 0; g < GH; g++) s += g_psH[(size_t)i*GH + g];
    float o = g_zh[i] - log2f(s);

    int cid = g_cid[i];
    if (cid == 1) {
        float s2 = 0.f;
        for (int g = 0; g < G0; g++) s2 += g_ps0[(size_t)i*G0 + g];
        o += g_z0[i] - log2f(s2);
    } else if (cid == 2) {
        float s2 = 0.f;
        for (int g = 0; g < G1; g++) s2 += g_ps1[(size_t)i*G1 + g];
        o += g_z1[i] - log2f(s2);
    }
    o *= LN2;
    out[i] = o;

    red[threadIdx.x] = o;
    __syncthreads();
    for (int st = 128; st > 0; st >>= 1) {
        if (threadIdx.x < st) red[threadIdx.x] += red[threadIdx.x + st];
        __syncthreads();
    }
    if (threadIdx.x == 0) g_blocksum[blockIdx.x] = red[0];
}

__global__ void finalize_kernel(float* __restrict__ out, int out_size) {
    float s = 0.f;
    for (int i = 0; i < 16; i++) s += g_blocksum[i];
    if (out_size > BB) out[BB] = -s / (float)BB;
}

// ---------------- launch ----------------
extern "C" void kernel_launch(void* const* d_in, const int* in_sizes, int n_in,
                              void* d_out, int out_size) {
    const float* X    = (const float*)d_in[0];
    const int*   tgt  = (const int*)d_in[1];
    const float* Wh   = (const float*)d_in[2];
    const float* W1_0 = (const float*)d_in[3];
    const float* W2_0 = (const float*)d_in[4];
    const float* W1_1 = (const float*)d_in[5];
    const float* W2_1 = (const float*)d_in[6];
    float* out = (float*)d_out;

    cudaFuncSetAttribute(hidden_kernel,    cudaFuncAttributeMaxDynamicSharedMemorySize, SMEM_HID);
    cudaFuncSetAttribute(lse_fused_kernel, cudaFuncAttributeMaxDynamicSharedMemorySize, SMEM_LSE);

    init_kernel<<<1, 1>>>();
    fusedprep_kernel<<<FUSEDPREP_BLKS, dim3(32, 8)>>>(X, tgt, Wh, W1_0, W2_0, W1_1, W2_1);
    hidden_kernel<<<dim3(BB/128, 3), 256, SMEM_HID>>>();
    lse_fused_kernel<<<GD_BLKS + LSE_BLKS, 256, SMEM_LSE>>>(X);
    combine_kernel<<<BB/256, 256>>>(out);
    finalize_kernel<<<1, 1>>>(out, out_size);
}

// round 15
// speedup vs baseline: 4.7771x; 1.0011x over previous
#include <cuda_runtime.h>
#include <cuda_fp16.h>
#include <math.h>
#include <stdint.h>

// ---------------- problem constants ----------------
#define BB    4096
#define NINP  1024
#define C0    2000
#define C1    10000
#define NH    2002
#define N0T   8000
#define N1T   22000
#define H0D   256
#define H1D   64

#define NHP   2048
#define N0P   8064
#define N1P   22016
#define GH    (NHP/128)    // 16
#define G0    (N0P/128)    // 63
#define G1    (N1P/128)    // 172

#define LOG2E 1.4426950408889634f
#define LN2   0.6931471805599453f

#define RS    72
#define TILE_B (128*RS*2)      // 18432
// hidden kernel (3 products)
#define OFF_AH 0
#define OFF_AL TILE_B
#define OFF_BH (2*TILE_B)
#define OFF_BL (3*TILE_B)
#define SMEM_HID (4*TILE_B)    // 73728
// LSE: 2 stages x (A tile + B tile)
#define STAGE_B (2*TILE_B)     // 36864
#define SMEM_LSE (2*STAGE_B)   // 73728

#define GD_BLKS 3072           // 1024 x 3 (128-thread blocks)
#define LSE_PERIODS 172
#define LSE_BLKS (LSE_PERIODS*17)

// ---------------- device scratch ----------------
__device__ int   g_n0, g_n1;
__device__ int   g_idx0[BB], g_idx1[BB];
__device__ int   g_cid[BB], g_gind[BB], g_t0[BB], g_t1[BB];
__device__ __half g_Xhi[BB*NINP],  g_Xlo[BB*NINP];
__device__ __half g_Whh[NHP*NINP], g_Whl[NHP*NINP];
__device__ __half g_W10h[H0D*NINP], g_W10l[H0D*NINP];
__device__ __half g_W11h[128*NINP], g_W11l[128*NINP];
__device__ __half g_W20h[N0P*H0D], g_W20l[N0P*H0D];
__device__ __half g_W21h[N1P*H1D], g_W21l[N1P*H1D];
__device__ float g_H0[BB*H0D]; __device__ __half g_H0h[BB*H0D], g_H0l[BB*H0D];
__device__ float g_H1[BB*H1D]; __device__ __half g_H1h[BB*H1D], g_H1l[BB*H1D];
__device__ float g_zh[BB], g_z0[BB], g_z1[BB];   // base-2 units
__device__ float g_psH[BB*GH];
__device__ float g_ps0[(size_t)BB*G0];
__device__ float g_ps1[(size_t)BB*G1];
__device__ float g_blocksum[16];

// ---------------- helpers ----------------
__device__ __forceinline__ uint32_t smem_u32(const void* p) {
    uint32_t a;
    asm("{ .reg .u64 t; cvta.to.shared.u64 t, %1; cvt.u32.u64 %0, t; }" : "=r"(a) : "l"(p));
    return a;
}
__device__ __forceinline__ void ldmx4(uint32_t* r, uint32_t addr) {
    asm volatile("ldmatrix.sync.aligned.m8n8.x4.shared.b16 {%0,%1,%2,%3}, [%4];"
        : "=r"(r[0]), "=r"(r[1]), "=r"(r[2]), "=r"(r[3]) : "r"(addr));
}
__device__ __forceinline__ void ldmx2(uint32_t* r, uint32_t addr) {
    asm volatile("ldmatrix.sync.aligned.m8n8.x2.shared.b16 {%0,%1}, [%2];"
        : "=r"(r[0]), "=r"(r[1]) : "r"(addr));
}
// f32-accum f16-input mma (hidden projections)
__device__ __forceinline__ void mma16816_f32(float* c, const uint32_t* a, const uint32_t* b) {
    asm volatile("mma.sync.aligned.m16n8k16.row.col.f32.f16.f16.f32 "
        "{%0,%1,%2,%3}, {%4,%5,%6,%7}, {%8,%9}, {%0,%1,%2,%3};"
        : "+f"(c[0]), "+f"(c[1]), "+f"(c[2]), "+f"(c[3])
        : "r"(a[0]), "r"(a[1]), "r"(a[2]), "r"(a[3]), "r"(b[0]), "r"(b[1]));
}
// f16-accum mma (LSE)
__device__ __forceinline__ void mma16816_f16(uint32_t* c, const uint32_t* a, const uint32_t* b) {
    asm volatile("mma.sync.aligned.m16n8k16.row.col.f16.f16.f16.f16 "
        "{%0,%1}, {%2,%3,%4,%5}, {%6,%7}, {%0,%1};"
        : "+r"(c[0]), "+r"(c[1])
        : "r"(a[0]), "r"(a[1]), "r"(a[2]), "r"(a[3]), "r"(b[0]), "r"(b[1]));
}
__device__ __forceinline__ uint32_t ex2u(uint32_t t) {
    asm("ex2.approx.f16x2 %0, %0;" : "+r"(t));
    return t;
}
__device__ __forceinline__ uint32_t hadd2u(uint32_t a, uint32_t b) {
    uint32_t d;
    asm("add.f16x2 %0, %1, %2;" : "=r"(d) : "r"(a), "r"(b));
    return d;
}
#define CP_ASYNC16(dst, src) \
    asm volatile("cp.async.cg.shared.global [%0], [%1], 16;" :: "r"(dst), "l"(src) : "memory")
#define CP_COMMIT() asm volatile("cp.async.commit_group;" ::: "memory")

// ---------------- init ----------------
__global__ void init_kernel() { g_n0 = 0; g_n1 = 0; }

// ---------------- fused prologue: prep + splitx + all tsplits ----------------
__global__ void fusedprep_kernel(const float* __restrict__ X,
                                 const int* __restrict__ target,
                                 const float* __restrict__ Wh,
                                 const float* __restrict__ W10,
                                 const float* __restrict__ W20,
                                 const float* __restrict__ W11,
                                 const float* __restrict__ W21) {
    __shared__ float t[32][33];
    int tid = threadIdx.y * 32 + threadIdx.x;
    int z = blockIdx.x;

    if (z < 16) {                         // prep
        int i = z * 256 + tid;
        int tg = target[i];
        int cid = (tg >= C0) + (tg >= C1);
        g_cid[i]  = cid;
        g_gind[i] = (cid == 0) ? tg : (C0 + cid - 1);
        int a = tg - C0; a = a < 0 ? 0 : a; a = a > N0T-1 ? N0T-1 : a; g_t0[i] = a;
        int b = tg - C1; b = b < 0 ? 0 : b; b = b > N1T-1 ? N1T-1 : b; g_t1[i] = b;
        if (cid == 1)      g_idx0[atomicAdd(&g_n0, 1)] = i;
        else if (cid == 2) g_idx1[atomicAdd(&g_n1, 1)] = i;
        return;
    }
    z -= 16;
    if (z < BB*NINP/256) {                // splitx
        int i = z * 256 + tid;
        float v = X[i];
        __half h = __float2half(v);
        g_Xhi[i] = h;
        g_Xlo[i] = __float2half(v - __half2float(h));
        return;
    }
    z -= BB*NINP/256;

    const float* src; int R, C, Cpad, Cb; __half *dhi, *dlo; float scale;
    if (z < 2048)        { src=Wh;  R=NINP; C=NH;  Cpad=NHP; dhi=g_Whh;  dlo=g_Whl;  scale=LOG2E; Cb=64; }
    else if (z < 2304)   { z-=2048; src=W10; R=NINP; C=H0D; Cpad=H0D; dhi=g_W10h; dlo=g_W10l; scale=1.0f; Cb=8; }
    else if (z < 2432)   { z-=2304; src=W11; R=NINP; C=H1D; Cpad=128; dhi=g_W11h; dlo=g_W11l; scale=1.0f; Cb=4; }
    else if (z < 4448)   { z-=2432; src=W20; R=H0D;  C=N0T; Cpad=N0P; dhi=g_W20h; dlo=g_W20l; scale=LOG2E; Cb=252; }
    else                 { z-=4448; src=W21; R=H1D;  C=N1T; Cpad=N1P; dhi=g_W21h; dlo=g_W21l; scale=LOG2E; Cb=688; }
    int cb = (z % Cb) * 32, rb = (z / Cb) * 32;
#pragma unroll
    for (int e = 0; e < 4; e++) {
        int rr = rb + threadIdx.y + e*8, cc = cb + threadIdx.x;
        t[threadIdx.y + e*8][threadIdx.x] = (rr < R && cc < C) ? src[(size_t)rr*C + cc] : 0.f;
    }
    __syncthreads();
#pragma unroll
    for (int e = 0; e < 4; e++) {
        int n = cb + threadIdx.y + e*8, k = rb + threadIdx.x;
        if (n < Cpad && k < R) {
            float v = t[threadIdx.x][threadIdx.y + e*8] * scale;
            __half h = __float2half(v);
            dhi[(size_t)n*R + k] = h;
            dlo[(size_t)n*R + k] = __float2half(v - __half2float(h));
        }
    }
}
#define FUSEDPREP_BLKS (16 + BB*NINP/256 + 2048 + 256 + 128 + 2016 + 1376)

// ---------------- hidden projections: 3-product split-fp16 mma ----------------
__global__ __launch_bounds__(256, 2)
void hidden_kernel() {
    int sel = (blockIdx.y == 2) ? 1 : 0;
    int by  = (blockIdx.y == 2) ? 0 : blockIdx.y;
    const __half *Ahi = g_Xhi, *Alo = g_Xlo, *Bhi, *Blo;
    int Nvalid, ldH; float* Hout; __half *Hh, *Hl;
    if (sel == 0) { Bhi=g_W10h; Blo=g_W10l; Nvalid=H0D; Hout=g_H0; Hh=g_H0h; Hl=g_H0l; ldH=H0D; }
    else          { Bhi=g_W11h; Blo=g_W11l; Nvalid=H1D; Hout=g_H1; Hh=g_H1h; Hl=g_H1l; ldH=H1D; }
    const int K = NINP;
    int rbase = blockIdx.x * 128;

    extern __shared__ __align__(16) char sm[];
    uint32_t sbase = smem_u32(sm);
    int tid = threadIdx.x, wid = tid >> 5, lane = tid & 31;
    int wm = wid >> 2, wn = wid & 3;

    float acc[4][4][4];
#pragma unroll
    for (int mt = 0; mt < 4; mt++)
#pragma unroll
        for (int nt = 0; nt < 4; nt++)
#pragma unroll
            for (int c = 0; c < 4; c++) acc[mt][nt][c] = 0.f;

    uint32_t aoff = (uint32_t)(((wm*64 + (lane & 15)) * RS + (lane >> 4) * 8) * 2);
    uint32_t boff = (uint32_t)(((wn*32 + (lane & 7)) * RS + ((lane >> 3) & 1) * 8) * 2);
    uint32_t aAH = sbase + OFF_AH + aoff, aAL = sbase + OFF_AL + aoff;
    uint32_t aBH = sbase + OFF_BH + boff, aBL = sbase + OFF_BL + boff;

    for (int ch = 0; ch < K/64; ch++) {
        int k0 = ch << 6;
#pragma unroll
        for (int e = 0; e < 4; e++) {
            int f = e*256 + tid, row = f >> 3, u = f & 7;
            size_t go = (size_t)(rbase + row) * K + k0 + u*8;
            uint32_t so = (uint32_t)((row*RS + u*8) * 2);
            *(uint4*)(sm + OFF_AH + so) = *(const uint4*)(Ahi + go);
            *(uint4*)(sm + OFF_AL + so) = *(const uint4*)(Alo + go);
            size_t gb = (size_t)(by*128 + row) * K + k0 + u*8;
            *(uint4*)(sm + OFF_BH + so) = *(const uint4*)(Bhi + gb);
            *(uint4*)(sm + OFF_BL + so) = *(const uint4*)(Blo + gb);
        }
        __syncthreads();
#pragma unroll
        for (int ks = 0; ks < 4; ks++) {
            uint32_t ah[4][4], al[4][4];
#pragma unroll
            for (int mt = 0; mt < 4; mt++) {
                uint32_t d = (uint32_t)(mt*16*RS*2 + ks*32);
                ldmx4(ah[mt], aAH + d);
                ldmx4(al[mt], aAL + d);
            }
#pragma unroll
            for (int nt = 0; nt < 4; nt++) {
                uint32_t d = (uint32_t)(nt*8*RS*2 + ks*32);
                uint32_t bh[2], bl[2];
                ldmx2(bh, aBH + d);
                ldmx2(bl, aBL + d);
#pragma unroll
                for (int mt = 0; mt < 4; mt++) {
                    mma16816_f32(acc[mt][nt], ah[mt], bh);
                    mma16816_f32(acc[mt][nt], ah[mt], bl);
                    mma16816_f32(acc[mt][nt], al[mt], bh);
                }
            }
        }
        __syncthreads();
    }

    int q = lane >> 2, r4 = lane & 3;
#pragma unroll
    for (int mt = 0; mt < 4; mt++)
#pragma unroll
        for (int nt = 0; nt < 4; nt++)
#pragma unroll
            for (int c = 0; c < 4; c++) {
                int row = rbase + wm*64 + mt*16 + q + (c >> 1)*8;
                int col = by*128 + wn*32 + nt*8 + r4*2 + (c & 1);
                if (col < Nvalid) {
                    float v = acc[mt][nt][c];
                    Hout[(size_t)row*ldH + col] = v;
                    __half hh = __float2half(v);
                    Hh[(size_t)row*ldH + col] = hh;
                    Hl[(size_t)row*ldH + col] = __float2half(v - __half2float(hh));
                }
            }
}

// ---------------- fused LSE + gatherdot launch (128-thread CTAs) -------------
// blocks [0, GD_BLKS): gatherdot. Then period-17 decode: 3 head / 6 tail0 / 8 tail1.
// 4 warps x m32n128 tile, f16 accumulators, warp-local epilogue, 1 sync/iter.
__global__ __launch_bounds__(128, 3)
void lse_fused_kernel(const float* __restrict__ X) {
    int zb = blockIdx.x;
    int tid = threadIdx.x, wid = tid >> 5, lane = tid & 31;

    if (zb < GD_BLKS) {
        int sel = zb / 1024, bx = zb % 1024;
        const float* A; const __half *Whi, *Wlo; const int* colidx; float* out; int K;
        if (sel == 0)      { A = X;    Whi = g_Whh;  Wlo = g_Whl;  colidx = g_gind; out = g_zh; K = NINP; }
        else if (sel == 1) { A = g_H0; Whi = g_W20h; Wlo = g_W20l; colidx = g_t0;   out = g_z0; K = H0D; }
        else               { A = g_H1; Whi = g_W21h; Wlo = g_W21l; colidx = g_t1;   out = g_z1; K = H1D; }
        int w = (bx * 128 + tid) >> 5;
        if (w >= BB) return;
        int c = colidx[w];
        float s = 0.f;
        for (int k = lane*2; k < K; k += 64) {
            float2 a = *(const float2*)&A[(size_t)w*K + k];
            float2 h = __half22float2(*(const __half2*)&Whi[(size_t)c*K + k]);
            float2 l = __half22float2(*(const __half2*)&Wlo[(size_t)c*K + k]);
            s += a.x * (h.x + l.x);
            s += a.y * (h.y + l.y);
        }
#pragma unroll
        for (int o = 16; o > 0; o >>= 1) s += __shfl_xor_sync(0xffffffffu, s, o);
        if (lane == 0) out[w] = s;
        return;
    }

    // -------- LSE decode --------
    int z = zb - GD_BLKS;
    int p = z / 17, i = z % 17;
    int sel, bx, by0;
    if (i < 3) {
        int idx = p*3 + i; if (idx >= 512) return;
        sel = 0; bx = idx & 31; by0 = idx >> 5;
    } else if (i < 9) {
        int idx = p*6 + (i - 3); if (idx >= 1024) return;
        sel = 1; bx = idx & 31; by0 = (idx >> 5) * 2;
    } else {
        int idx = p*8 + (i - 9); if (idx >= 1376) return;
        sel = 2; bx = idx & 31; by0 = (idx >> 5) * 4;
    }

    const __half *Ahi, *Bhi;
    int K, Nvalid, G, cnt, T;
    const int* rowlist;
    float* pS;
    if (sel == 0)      { Ahi=g_Xhi;  K=NINP; Bhi=g_Whh;  Nvalid=NH;  G=GH; pS=g_psH; rowlist=nullptr; cnt=BB;   T=1; }
    else if (sel == 1) { Ahi=g_H0h;  K=H0D;  Bhi=g_W20h; Nvalid=N0T; G=G0; pS=g_ps0; rowlist=g_idx0; cnt=g_n0; T=2; }
    else               { Ahi=g_H1h;  K=H1D;  Bhi=g_W21h; Nvalid=N1T; G=G1; pS=g_ps1; rowlist=g_idx1; cnt=g_n1; T=4; }

    int rbase = bx * 128;
    if (rbase >= cnt) return;

    extern __shared__ __align__(16) char sm[];
    uint32_t sbase = smem_u32(sm);

    // f16 accumulators: 2 m-tiles x 16 n8-tiles x 2 regs
    uint32_t facc[2][16][2];
#pragma unroll
    for (int mt = 0; mt < 2; mt++)
#pragma unroll
        for (int nt = 0; nt < 16; nt++) { facc[mt][nt][0] = 0; facc[mt][nt][1] = 0; }

    // load slots: 8 x 16B per matrix per chunk; row(e) = e*16 + (tid>>3), u8 const
    int rlocal = tid >> 3;
    int u8 = (tid & 7) * 8;
    uint32_t so0 = (uint32_t)((rlocal*RS + u8) * 2);
    int lrowK[8];
#pragma unroll
    for (int e = 0; e < 8; e++) {
        int row = e*16 + rlocal;
        int grow = rbase + row; if (grow >= cnt) grow = cnt - 1;
        lrowK[e] = (rowlist ? rowlist[grow] : grow) * K;
    }

    int nch = K >> 6;
    int iters = nch * T;

    // prologue: iter 0 into stage 0
    {
        int cy0 = by0 < G ? by0 : G - 1;
        int bbase = cy0 * 128;
#pragma unroll
        for (int e = 0; e < 8; e++) {
            uint32_t so = so0 + (uint32_t)(e*16*RS*2);
            CP_ASYNC16(sbase + so,          Ahi + (size_t)lrowK[e] + u8);
            CP_ASYNC16(sbase + TILE_B + so, Bhi + (size_t)(bbase + e*16 + rlocal)*K + u8);
        }
        CP_COMMIT();
    }

    uint32_t aoff  = (uint32_t)(((wid*32 + (lane & 15)) * RS + (lane >> 4) * 8) * 2);
    uint32_t boff4 = (uint32_t)((((lane & 7) + ((lane >> 4) << 3)) * RS + ((lane >> 3) & 1) * 8) * 2);

    int q = lane >> 2, r4 = lane & 3;
    int ch = 0, cyi = 0;

    for (int it = 0; it < iters; it++) {
        asm volatile("cp.async.wait_group 0;" ::: "memory");
        __syncthreads();
        if (it + 1 < iters) {
            int ch2 = ch + 1, cy2i = cyi;
            if (ch2 == nch) { ch2 = 0; cy2i++; }
            int cy2 = by0 + cy2i; if (cy2 > G - 1) cy2 = G - 1;
            int k0 = ch2 << 6;
            int bbase = cy2 * 128;
            uint32_t st = ((it + 1) & 1) * STAGE_B;
#pragma unroll
            for (int e = 0; e < 8; e++) {
                uint32_t so = so0 + (uint32_t)(e*16*RS*2);
                CP_ASYNC16(sbase + st + so,          Ahi + (size_t)lrowK[e] + k0 + u8);
                CP_ASYNC16(sbase + st + TILE_B + so, Bhi + (size_t)(bbase + e*16 + rlocal)*K + k0 + u8);
            }
            CP_COMMIT();
        }
        uint32_t sb = sbase + (it & 1) * STAGE_B;
        uint32_t aA = sb + aoff, aB4 = sb + TILE_B + boff4;
#pragma unroll
        for (int ks = 0; ks < 4; ks++) {
            uint32_t a4[2][4];
            ldmx4(a4[0], aA + (uint32_t)(ks*32));
            ldmx4(a4[1], aA + (uint32_t)(16*RS*2 + ks*32));
#pragma unroll
            for (int ntp = 0; ntp < 8; ntp++) {
                uint32_t bq[4];
                ldmx4(bq, aB4 + (uint32_t)(ntp*16*RS*2 + ks*32));
#pragma unroll
                for (int mt = 0; mt < 2; mt++) {
                    mma16816_f16(facc[mt][ntp*2 + 0], a4[mt], bq);
                    mma16816_f16(facc[mt][ntp*2 + 1], a4[mt], bq + 2);
                }
            }
        }

        // epilogue at last chunk of this col tile (warp-local, sync-free)
        if (ch == nch - 1) {
            int cy = by0 + cyi;
            if (cy < G) {
                bool edge = (cy == G - 1);
#pragma unroll
                for (int mt = 0; mt < 2; mt++) {
#pragma unroll
                    for (int h = 0; h < 2; h++) {
                        uint32_t e16[16];
#pragma unroll
                        for (int nt = 0; nt < 16; nt++) {
                            uint32_t t = facc[mt][nt][h];
                            if (edge) {
                                int col0 = cy*128 + nt*8 + r4*2;
                                if (col0 >= Nvalid) t = 0xFC00FC00u;   // -inf,-inf
                            }
                            e16[nt] = ex2u(t);
                        }
#pragma unroll
                        for (int j = 0; j < 8; j++) e16[j] = hadd2u(e16[j], e16[j + 8]);
#pragma unroll
                        for (int j = 0; j < 4; j++) e16[j] = hadd2u(e16[j], e16[j + 4]);
                        float s = 0.f;
#pragma unroll
                        for (int j = 0; j < 4; j++) {
                            float2 f2 = __half22float2(*(__half2*)&e16[j]);
                            s += f2.x + f2.y;
                        }
                        s += __shfl_xor_sync(0xffffffffu, s, 1);
                        s += __shfl_xor_sync(0xffffffffu, s, 2);
                        if (r4 == 0) {
                            int row = wid*32 + mt*16 + q + h*8;
                            int grow = rbase + row;
                            if (grow < cnt) {
                                int orow = rowlist ? rowlist[grow] : grow;
                                pS[(size_t)orow*G + cy] = s;
                            }
                        }
                    }
                }
            }
#pragma unroll
            for (int mt = 0; mt < 2; mt++)
#pragma unroll
                for (int nt = 0; nt < 16; nt++) { facc[mt][nt][0] = 0; facc[mt][nt][1] = 0; }
            ch = 0; cyi++;
        } else {
            ch++;
        }
    }
}

// ---------------- combine + deterministic loss reduction ----------------
__global__ void combine_kernel(float* __restrict__ out) {
    __shared__ float red[256];
    int i = blockIdx.x * 256 + threadIdx.x;

    float s = 0.f;
    for (int g = 0; g < GH; g++) s += g_psH[(size_t)i*GH + g];
    float o = g_zh[i] - log2f(s);

    int cid = g_cid[i];
    if (cid == 1) {
        float s2 = 0.f;
        for (int g = 0; g < G0; g++) s2 += g_ps0[(size_t)i*G0 + g];
        o += g_z0[i] - log2f(s2);
    } else if (cid == 2) {
        float s2 = 0.f;
        for (int g = 0; g < G1; g++) s2 += g_ps1[(size_t)i*G1 + g];
        o += g_z1[i] - log2f(s2);
    }
    o *= LN2;
    out[i] = o;

    red[threadIdx.x] = o;
    __syncthreads();
    for (int st = 128; st > 0; st >>= 1) {
        if (threadIdx.x < st) red[threadIdx.x] += red[threadIdx.x + st];
        __syncthreads();
    }
    if (threadIdx.x == 0) g_blocksum[blockIdx.x] = red[0];
}

__global__ void finalize_kernel(float* __restrict__ out, int out_size) {
    float s = 0.f;
    for (int i = 0; i < 16; i++) s += g_blocksum[i];
    if (out_size > BB) out[BB] = -s / (float)BB;
}

// ---------------- launch ----------------
extern "C" void kernel_launch(void* const* d_in, const int* in_sizes, int n_in,
                              void* d_out, int out_size) {
    const float* X    = (const float*)d_in[0];
    const int*   tgt  = (const int*)d_in[1];
    const float* Wh   = (const float*)d_in[2];
    const float* W1_0 = (const float*)d_in[3];
    const float* W2_0 = (const float*)d_in[4];
    const float* W1_1 = (const float*)d_in[5];
    const float* W2_1 = (const float*)d_in[6];
    float* out = (float*)d_out;

    cudaFuncSetAttribute(hidden_kernel,    cudaFuncAttributeMaxDynamicSharedMemorySize, SMEM_HID);
    cudaFuncSetAttribute(lse_fused_kernel, cudaFuncAttributeMaxDynamicSharedMemorySize, SMEM_LSE);

    init_kernel<<<1, 1>>>();
    fusedprep_kernel<<<FUSEDPREP_BLKS, dim3(32, 8)>>>(X, tgt, Wh, W1_0, W2_0, W1_1, W2_1);
    hidden_kernel<<<dim3(BB/128, 3), 256, SMEM_HID>>>();
    lse_fused_kernel<<<GD_BLKS + LSE_BLKS, 128, SMEM_LSE>>>(X);
    combine_kernel<<<BB/256, 256>>>(out);
    finalize_kernel<<<1, 1>>>(out, out_size);
}